// round 3
// baseline (speedup 1.0000x reference)
#include <cuda_runtime.h>
#include <cuda_bf16.h>
#include <math.h>

// Problem constants
#define BB 2
#define SS 2048
#define DD 1024
#define D3 (3*DD)
#define BS (BB*SS)            // 4096
#define BSD ((size_t)BS*DD)   // 4,194,304
#define BSS ((size_t)BB*SS*SS) // 8,388,608

// GEMM tiling
#define TBM 64
#define TBN 64
#define TBK 16

// ----------------- scratch buffers (static device globals; no allocs) ------
__device__ float g_qkv_s[(size_t)BS*D3];
__device__ float g_qkv_m[(size_t)BS*D3];
__device__ float g_qkv_l[(size_t)BS*D3];
__device__ float g_scores[(size_t)BB*16*SS*SS];   // reused per branch (sized for long)
__device__ float g_ctx[(size_t)BS*DD];            // reused per branch
__device__ float g_combined[(size_t)BS*D3];
__device__ float g_comb_out[(size_t)BS*DD];

// ----------------- generic C = A @ W^T + bias ------------------------------
// A: [M,K] row-major lda ; W: [N,K] row-major ldb ; C: [M,N] ldc
__global__ void gemm_nt_bias(const float* __restrict__ A, int lda,
                             const float* __restrict__ W, int ldb,
                             const float* __restrict__ bias,
                             float* __restrict__ C, int ldc,
                             int K) {
    __shared__ float As[TBK][TBM+4];
    __shared__ float Bs[TBK][TBN+4];
    const int tx = threadIdx.x & 15;
    const int ty = threadIdx.x >> 4;
    const int m0 = blockIdx.y * TBM;
    const int n0 = blockIdx.x * TBN;
    float acc[4][4] = {};
    for (int k0 = 0; k0 < K; k0 += TBK) {
#pragma unroll
        for (int i = 0; i < 4; i++) {
            int idx = threadIdx.x + i*256;
            int m = idx >> 4, k = idx & 15;
            As[k][m] = A[(size_t)(m0+m)*lda + k0 + k];
        }
#pragma unroll
        for (int i = 0; i < 4; i++) {
            int idx = threadIdx.x + i*256;
            int n = idx >> 4, k = idx & 15;
            Bs[k][n] = W[(size_t)(n0+n)*ldb + k0 + k];
        }
        __syncthreads();
#pragma unroll
        for (int k = 0; k < TBK; k++) {
            float a[4], b[4];
#pragma unroll
            for (int i = 0; i < 4; i++) a[i] = As[k][ty*4+i];
#pragma unroll
            for (int j = 0; j < 4; j++) b[j] = Bs[k][tx*4+j];
#pragma unroll
            for (int i = 0; i < 4; i++)
#pragma unroll
                for (int j = 0; j < 4; j++)
                    acc[i][j] += a[i] * b[j];
        }
        __syncthreads();
    }
#pragma unroll
    for (int i = 0; i < 4; i++)
#pragma unroll
        for (int j = 0; j < 4; j++) {
            int m = m0 + ty*4 + i, n = n0 + tx*4 + j;
            C[(size_t)m*ldc + n] = acc[i][j] + bias[n];
        }
}

// ----------------- batched scores = Q @ K^T (per b,h) -----------------------
// qkv layout [B,S,3D]; Q col offset h*dk, K at D + h*dk. scores [BH,S,S].
__global__ void gemm_qk(const float* __restrict__ qkv, float* __restrict__ scores,
                        int H, int dk, int band) {
    const int z = blockIdx.z;
    const int b = z / H, h = z % H;
    const int m0 = blockIdx.y * TBM;
    const int n0 = blockIdx.x * TBN;
    if (band >= 0 && (n0 + TBN - 1) < m0 - band) return;   // fully masked tile
    const float* A  = qkv + (size_t)b*SS*D3 + h*dk;        // Q rows, lda=3D
    const float* Bp = qkv + (size_t)b*SS*D3 + DD + h*dk;   // K rows, ldb=3D
    float* C = scores + (size_t)z*SS*SS;
    __shared__ float As[TBK][TBM+4];
    __shared__ float Bs[TBK][TBN+4];
    const int tx = threadIdx.x & 15;
    const int ty = threadIdx.x >> 4;
    float acc[4][4] = {};
    for (int k0 = 0; k0 < dk; k0 += TBK) {
#pragma unroll
        for (int i = 0; i < 4; i++) {
            int idx = threadIdx.x + i*256;
            int m = idx >> 4, k = idx & 15;
            As[k][m] = A[(size_t)(m0+m)*D3 + k0 + k];
        }
#pragma unroll
        for (int i = 0; i < 4; i++) {
            int idx = threadIdx.x + i*256;
            int n = idx >> 4, k = idx & 15;
            Bs[k][n] = Bp[(size_t)(n0+n)*D3 + k0 + k];
        }
        __syncthreads();
#pragma unroll
        for (int k = 0; k < TBK; k++) {
            float a[4], bb[4];
#pragma unroll
            for (int i = 0; i < 4; i++) a[i] = As[k][ty*4+i];
#pragma unroll
            for (int j = 0; j < 4; j++) bb[j] = Bs[k][tx*4+j];
#pragma unroll
            for (int i = 0; i < 4; i++)
#pragma unroll
                for (int j = 0; j < 4; j++)
                    acc[i][j] += a[i] * bb[j];
        }
        __syncthreads();
    }
#pragma unroll
    for (int i = 0; i < 4; i++)
#pragma unroll
        for (int j = 0; j < 4; j++)
            C[(size_t)(m0+ty*4+i)*SS + n0 + tx*4 + j] = acc[i][j];
}

// ----------------- row softmax (in-place), scale + band mask ----------------
__global__ void softmax_rows(float* __restrict__ scores, int band, float scale) {
    __shared__ float srow[SS];
    __shared__ float red[256];
    const size_t rid = blockIdx.x;
    const int i = (int)(rid % SS);
    float* row = scores + rid * (size_t)SS;
    const int jstart = (band >= 0) ? max(0, i - band) : 0;
    const int t = threadIdx.x;
    float lmax = -1e30f;
    for (int j = t; j < SS; j += 256) {
        float v = (j >= jstart) ? row[j] * scale : -1e30f;
        srow[j] = v;
        lmax = fmaxf(lmax, v);
    }
    red[t] = lmax; __syncthreads();
    for (int s = 128; s > 0; s >>= 1) {
        if (t < s) red[t] = fmaxf(red[t], red[t+s]);
        __syncthreads();
    }
    const float m = red[0];
    __syncthreads();
    float lsum = 0.f;
    for (int j = t; j < SS; j += 256) {
        float e = (j >= jstart) ? __expf(srow[j] - m) : 0.f;
        srow[j] = e;
        lsum += e;
    }
    red[t] = lsum; __syncthreads();
    for (int s = 128; s > 0; s >>= 1) {
        if (t < s) red[t] += red[t+s];
        __syncthreads();
    }
    const float inv = 1.f / red[0];
    for (int j = t; j < SS; j += 256) row[j] = srow[j] * inv;
}

// ----------------- ctx = P @ V (per b,h), k-tile skip below band -----------
__global__ void gemm_pv(const float* __restrict__ probs, const float* __restrict__ qkv,
                        float* __restrict__ ctx, int H, int dk, int band) {
    const int z = blockIdx.z;
    const int b = z / H, h = z % H;
    const int m0 = blockIdx.y * TBM;
    const int n0 = blockIdx.x * TBN;   // within dk
    const float* A  = probs + (size_t)z*SS*SS;                        // lda=S
    const float* Bp = qkv + (size_t)b*SS*D3 + 2*DD + h*dk + n0;       // ldb=3D
    float* C = ctx + (size_t)b*SS*DD + h*dk + n0;                     // ldc=D
    __shared__ float As[TBK][TBM+4];
    __shared__ float Bs[TBK][TBN+4];
    const int tx = threadIdx.x & 15;
    const int ty = threadIdx.x >> 4;
    float acc[4][4] = {};
    for (int k0 = 0; k0 < SS; k0 += TBK) {
        if (band >= 0 && (k0 + TBK - 1) < m0 - band) continue;  // P tile all-zero
#pragma unroll
        for (int i = 0; i < 4; i++) {
            int idx = threadIdx.x + i*256;
            int m = idx >> 4, k = idx & 15;
            As[k][m] = A[(size_t)(m0+m)*SS + k0 + k];
        }
        // Stage B tile: 16 k-slices x 64 n-cols = 1024 elems = 4 passes of 256.
        // idx in [0,1024): k = idx>>6 in [0,16), n = idx&63.
#pragma unroll
        for (int i = 0; i < 4; i++) {
            int idx = threadIdx.x + i*256;
            int k = idx >> 6, n = idx & 63;
            Bs[k][n] = Bp[(size_t)(k0+k)*D3 + n];
        }
        __syncthreads();
#pragma unroll
        for (int k = 0; k < TBK; k++) {
            float a[4], bb[4];
#pragma unroll
            for (int i = 0; i < 4; i++) a[i] = As[k][ty*4+i];
#pragma unroll
            for (int j = 0; j < 4; j++) bb[j] = Bs[k][tx*4+j];
#pragma unroll
            for (int i = 0; i < 4; i++)
#pragma unroll
                for (int j = 0; j < 4; j++)
                    acc[i][j] += a[i] * bb[j];
        }
        __syncthreads();
    }
#pragma unroll
    for (int i = 0; i < 4; i++)
#pragma unroll
        for (int j = 0; j < 4; j++)
            C[(size_t)(m0+ty*4+i)*DD + tx*4 + j] = acc[i][j];
}

// ----------------- long-branch attn mean over heads -------------------------
__global__ void attn_mean(const float* __restrict__ probs, float* __restrict__ out) {
    const int b = blockIdx.x / SS, i = blockIdx.x % SS;
    for (int j = threadIdx.x; j < SS; j += blockDim.x) {
        float s = 0.f;
#pragma unroll
        for (int h = 0; h < 16; h++)
            s += probs[(((size_t)(b*16 + h)*SS) + i)*SS + j];
        out[(size_t)blockIdx.x*SS + j] = s * (1.f/16.f);
    }
}

// ----------------- residual + layernorm -------------------------------------
__global__ void ln_kernel(const float* __restrict__ y, const float* __restrict__ x,
                          const float* __restrict__ gamma, const float* __restrict__ beta,
                          float* __restrict__ out) {
    const int row = blockIdx.x;
    __shared__ float r1[256];
    __shared__ float r2[256];
    const float* yr = y + (size_t)row*DD;
    const float* xr = x + (size_t)row*DD;
    float s = 0.f, s2 = 0.f;
    float v[4];
    int c = 0;
    for (int d = threadIdx.x; d < DD; d += 256, c++) {
        float t = yr[d] + xr[d];
        v[c] = t; s += t; s2 += t*t;
    }
    r1[threadIdx.x] = s; r2[threadIdx.x] = s2; __syncthreads();
    for (int k = 128; k > 0; k >>= 1) {
        if (threadIdx.x < k) { r1[threadIdx.x] += r1[threadIdx.x+k]; r2[threadIdx.x] += r2[threadIdx.x+k]; }
        __syncthreads();
    }
    const float mu = r1[0] * (1.f/DD);
    const float var = r2[0] * (1.f/DD) - mu*mu;
    const float rs = rsqrtf(var + 1e-5f);
    c = 0;
    for (int d = threadIdx.x; d < DD; d += 256, c++)
        out[(size_t)row*DD + d] = (v[c] - mu) * rs * gamma[d] + beta[d];
}

// ----------------- orchestration --------------------------------------------
static void run_branch(const float* qkv, float* scores, float* ctx,
                       float* combined_col, const float* wo, const float* bo,
                       int H, int dk, int band) {
    const float inv_sqrt = 1.f / sqrtf((float)dk);
    dim3 gqk(SS/TBN, SS/TBM, BB*H);
    gemm_qk<<<gqk, 256>>>(qkv, scores, H, dk, band);
    softmax_rows<<<BB*H*SS, 256>>>(scores, band, inv_sqrt);
    dim3 gpv(dk/TBN, SS/TBM, BB*H);
    gemm_pv<<<gpv, 256>>>(scores, qkv, ctx, H, dk, band);
    dim3 gop(DD/TBN, BS/TBM);
    gemm_nt_bias<<<gop, 256>>>(ctx, DD, wo, DD, bo, combined_col, D3, DD);
}

extern "C" void kernel_launch(void* const* d_in, const int* in_sizes, int n_in,
                              void* d_out, int out_size) {
    const float* x      = (const float*)d_in[0];
    const float* w_in_s = (const float*)d_in[1];
    const float* b_in_s = (const float*)d_in[2];
    const float* wo_s   = (const float*)d_in[3];
    const float* bo_s   = (const float*)d_in[4];
    const float* w_in_m = (const float*)d_in[5];
    const float* b_in_m = (const float*)d_in[6];
    const float* wo_m   = (const float*)d_in[7];
    const float* bo_m   = (const float*)d_in[8];
    const float* w_in_l = (const float*)d_in[9];
    const float* b_in_l = (const float*)d_in[10];
    const float* wo_l   = (const float*)d_in[11];
    const float* bo_l   = (const float*)d_in[12];
    const float* w_comb = (const float*)d_in[13];
    const float* b_comb = (const float*)d_in[14];
    const float* gamma  = (const float*)d_in[15];
    const float* beta   = (const float*)d_in[16];
    float* out = (float*)d_out;

    float *qkv_s, *qkv_m, *qkv_l, *scores, *ctx, *combined, *comb_out;
    cudaGetSymbolAddress((void**)&qkv_s,    g_qkv_s);
    cudaGetSymbolAddress((void**)&qkv_m,    g_qkv_m);
    cudaGetSymbolAddress((void**)&qkv_l,    g_qkv_l);
    cudaGetSymbolAddress((void**)&scores,   g_scores);
    cudaGetSymbolAddress((void**)&ctx,      g_ctx);
    cudaGetSymbolAddress((void**)&combined, g_combined);
    cudaGetSymbolAddress((void**)&comb_out, g_comb_out);

    // QKV projections: [BS,1024] @ [3072,1024]^T
    dim3 gqkv(D3/TBN, BS/TBM);
    gemm_nt_bias<<<gqkv, 256>>>(x, DD, w_in_s, DD, b_in_s, qkv_s, D3, DD);
    gemm_nt_bias<<<gqkv, 256>>>(x, DD, w_in_m, DD, b_in_m, qkv_m, D3, DD);
    gemm_nt_bias<<<gqkv, 256>>>(x, DD, w_in_l, DD, b_in_l, qkv_l, D3, DD);

    // short: H=8, dk=128, band=10
    run_branch(qkv_s, scores, ctx, combined + 0,    wo_s, bo_s, 8, 128, 10);
    // medium: H=8, dk=128, band=30
    run_branch(qkv_m, scores, ctx, combined + DD,   wo_m, bo_m, 8, 128, 30);

    // long: H=16, dk=64, no band; need probs mean before reusing anything
    {
        const float inv_sqrt = 1.f / sqrtf(64.f);
        dim3 gqk(SS/TBN, SS/TBM, BB*16);
        gemm_qk<<<gqk, 256>>>(qkv_l, scores, 16, 64, -1);
        softmax_rows<<<BB*16*SS, 256>>>(scores, -1, inv_sqrt);
        if ((size_t)out_size >= BSD + BSS)
            attn_mean<<<BB*SS, 256>>>(scores, out + BSD);
        dim3 gpv(64/TBN, SS/TBM, BB*16);
        gemm_pv<<<gpv, 256>>>(scores, qkv_l, ctx, 16, 64, -1);
        dim3 gop(DD/TBN, BS/TBM);
        gemm_nt_bias<<<gop, 256>>>(ctx, DD, wo_l, DD, bo_l, combined + 2*DD, D3, DD);
    }

    // combine: [BS,3072] @ [1024,3072]^T
    dim3 gc(DD/TBN, BS/TBM);
    gemm_nt_bias<<<gc, 256>>>(combined, D3, w_comb, D3, b_comb, comb_out, DD, D3);

    // residual + LN -> first BSD floats of out
    ln_kernel<<<BS, 256>>>(comb_out, x, gamma, beta, out);
}

// round 6
// speedup vs baseline: 1.5498x; 1.5498x over previous
#include <cuda_runtime.h>
#include <cuda_bf16.h>
#include <math.h>

// Problem constants
#define BB 2
#define SS 2048
#define DD 1024
#define D3 (3*DD)
#define BS (BB*SS)             // 4096
#define BSD ((size_t)BS*DD)    // 4,194,304
#define BSS ((size_t)BB*SS*SS) // 8,388,608

// GEMM tiling: 128x128 C-tile, BK=16, 256 threads, 8x8 per thread
#define BM 128
#define BN 128
#define BK 16
#define SMS (BM + 4)   // 132: padded smem stride

// ----------------- scratch buffers (static device globals; no allocs) ------
__device__ float g_qkv_s[(size_t)BS*D3];
__device__ float g_qkv_m[(size_t)BS*D3];
__device__ float g_qkv_l[(size_t)BS*D3];
__device__ float g_scores[(size_t)BB*16*SS*SS];   // sized for long branch
__device__ float g_ctx[(size_t)BS*D3];            // concatenated ctx (s|m|l)
__device__ float g_Mall[(size_t)DD*D3];           // fused wo∘w_comb weights
__device__ float g_bias[DD];
__device__ float g_comb_out[(size_t)BS*DD];

// ===================== C = A @ W^T + bias (NT) ==============================
// A: [M,K] row-major lda ; W: [N,K] row-major ldb ; C: [M,N] ldc
__global__ __launch_bounds__(256) void gemm_nt_f4(
        const float* __restrict__ A, int lda,
        const float* __restrict__ W, int ldb,
        const float* __restrict__ bias,
        float* __restrict__ C, int ldc, int K) {
    __shared__ float As[BK][SMS];
    __shared__ float Bs[BK][SMS];
    const int tid = threadIdx.x;
    const int tx = tid & 15, ty = tid >> 4;
    const int m0 = blockIdx.y * BM, n0 = blockIdx.x * BN;
    float acc[8][8] = {};
    for (int k0 = 0; k0 < K; k0 += BK) {
#pragma unroll
        for (int i = 0; i < 2; i++) {
            int idx = tid + i*256;
            int r = idx >> 2, kq = (idx & 3) * 4;
            float4 va = *(const float4*)(A + (size_t)(m0 + r)*lda + k0 + kq);
            As[kq+0][r] = va.x; As[kq+1][r] = va.y; As[kq+2][r] = va.z; As[kq+3][r] = va.w;
            float4 vb = *(const float4*)(W + (size_t)(n0 + r)*ldb + k0 + kq);
            Bs[kq+0][r] = vb.x; Bs[kq+1][r] = vb.y; Bs[kq+2][r] = vb.z; Bs[kq+3][r] = vb.w;
        }
        __syncthreads();
#pragma unroll
        for (int k = 0; k < BK; k++) {
            float a[8], b[8];
            *(float4*)&a[0] = *(const float4*)&As[k][ty*8];
            *(float4*)&a[4] = *(const float4*)&As[k][ty*8+4];
            *(float4*)&b[0] = *(const float4*)&Bs[k][tx*8];
            *(float4*)&b[4] = *(const float4*)&Bs[k][tx*8+4];
#pragma unroll
            for (int i = 0; i < 8; i++)
#pragma unroll
                for (int j = 0; j < 8; j++)
                    acc[i][j] = fmaf(a[i], b[j], acc[i][j]);
        }
        __syncthreads();
    }
#pragma unroll
    for (int i = 0; i < 8; i++) {
        int m = m0 + ty*8 + i;
#pragma unroll
        for (int jq = 0; jq < 2; jq++) {
            int n = n0 + tx*8 + jq*4;
            float4 bv = *(const float4*)(bias + n);
            float4 o = make_float4(acc[i][jq*4+0]+bv.x, acc[i][jq*4+1]+bv.y,
                                   acc[i][jq*4+2]+bv.z, acc[i][jq*4+3]+bv.w);
            *(float4*)(C + (size_t)m*ldc + n) = o;
        }
    }
}

// ===================== C = A @ B (NN), no bias ==============================
// A: [M,K] lda ; B: [K,N] ldb ; C: [M,N] ldc. (used for M_b = w_comb_b @ wo_b)
__global__ __launch_bounds__(256) void gemm_nn_f4(
        const float* __restrict__ A, int lda,
        const float* __restrict__ B, int ldb,
        float* __restrict__ C, int ldc, int K) {
    __shared__ float As[BK][SMS];
    __shared__ float Bs[BK][SMS];
    const int tid = threadIdx.x;
    const int tx = tid & 15, ty = tid >> 4;
    const int m0 = blockIdx.y * BM, n0 = blockIdx.x * BN;
    float acc[8][8] = {};
    for (int k0 = 0; k0 < K; k0 += BK) {
#pragma unroll
        for (int i = 0; i < 2; i++) {
            int idx = tid + i*256;
            int r = idx >> 2, kq = (idx & 3) * 4;
            float4 va = *(const float4*)(A + (size_t)(m0 + r)*lda + k0 + kq);
            As[kq+0][r] = va.x; As[kq+1][r] = va.y; As[kq+2][r] = va.z; As[kq+3][r] = va.w;
            int k = idx >> 5, nq = (idx & 31) * 4;
            *(float4*)&Bs[k][nq] = *(const float4*)(B + (size_t)(k0 + k)*ldb + n0 + nq);
        }
        __syncthreads();
#pragma unroll
        for (int k = 0; k < BK; k++) {
            float a[8], b[8];
            *(float4*)&a[0] = *(const float4*)&As[k][ty*8];
            *(float4*)&a[4] = *(const float4*)&As[k][ty*8+4];
            *(float4*)&b[0] = *(const float4*)&Bs[k][tx*8];
            *(float4*)&b[4] = *(const float4*)&Bs[k][tx*8+4];
#pragma unroll
            for (int i = 0; i < 8; i++)
#pragma unroll
                for (int j = 0; j < 8; j++)
                    acc[i][j] = fmaf(a[i], b[j], acc[i][j]);
        }
        __syncthreads();
    }
#pragma unroll
    for (int i = 0; i < 8; i++) {
        int m = m0 + ty*8 + i;
#pragma unroll
        for (int jq = 0; jq < 2; jq++) {
            int n = n0 + tx*8 + jq*4;
            *(float4*)(C + (size_t)m*ldc + n) =
                make_float4(acc[i][jq*4+0], acc[i][jq*4+1], acc[i][jq*4+2], acc[i][jq*4+3]);
        }
    }
}

// ===================== scores = scale * Q @ K^T (batched, band skip) ========
__global__ __launch_bounds__(256) void gemm_qk_f4(
        const float* __restrict__ qkv, float* __restrict__ scores,
        int H, int dk, int band, float scale) {
    const int z = blockIdx.z;
    const int b = z / H, h = z % H;
    const int m0 = blockIdx.y * BM, n0 = blockIdx.x * BN;
    if (band >= 0 && (n0 + BN - 1) < m0 - band) return;   // fully masked tile
    const float* Aq = qkv + (size_t)b*SS*D3 + h*dk;        // Q, lda=3D
    const float* Bk = qkv + (size_t)b*SS*D3 + DD + h*dk;   // K, ldb=3D
    float* C = scores + (size_t)z*SS*SS;
    __shared__ float As[BK][SMS];
    __shared__ float Bs[BK][SMS];
    const int tid = threadIdx.x;
    const int tx = tid & 15, ty = tid >> 4;
    float acc[8][8] = {};
    for (int k0 = 0; k0 < dk; k0 += BK) {
#pragma unroll
        for (int i = 0; i < 2; i++) {
            int idx = tid + i*256;
            int r = idx >> 2, kq = (idx & 3) * 4;
            float4 va = *(const float4*)(Aq + (size_t)(m0 + r)*D3 + k0 + kq);
            As[kq+0][r] = va.x; As[kq+1][r] = va.y; As[kq+2][r] = va.z; As[kq+3][r] = va.w;
            float4 vb = *(const float4*)(Bk + (size_t)(n0 + r)*D3 + k0 + kq);
            Bs[kq+0][r] = vb.x; Bs[kq+1][r] = vb.y; Bs[kq+2][r] = vb.z; Bs[kq+3][r] = vb.w;
        }
        __syncthreads();
#pragma unroll
        for (int k = 0; k < BK; k++) {
            float a[8], b2[8];
            *(float4*)&a[0]  = *(const float4*)&As[k][ty*8];
            *(float4*)&a[4]  = *(const float4*)&As[k][ty*8+4];
            *(float4*)&b2[0] = *(const float4*)&Bs[k][tx*8];
            *(float4*)&b2[4] = *(const float4*)&Bs[k][tx*8+4];
#pragma unroll
            for (int i = 0; i < 8; i++)
#pragma unroll
                for (int j = 0; j < 8; j++)
                    acc[i][j] = fmaf(a[i], b2[j], acc[i][j]);
        }
        __syncthreads();
    }
#pragma unroll
    for (int i = 0; i < 8; i++) {
        int m = m0 + ty*8 + i;
#pragma unroll
        for (int jq = 0; jq < 2; jq++) {
            int n = n0 + tx*8 + jq*4;
            *(float4*)(C + (size_t)m*SS + n) =
                make_float4(acc[i][jq*4+0]*scale, acc[i][jq*4+1]*scale,
                            acc[i][jq*4+2]*scale, acc[i][jq*4+3]*scale);
        }
    }
}

// ===================== ctx = P @ V (BN=128, dk=128 heads) ===================
// writes into ctx_all (ld=3D) at column colbase + h*dk
__global__ __launch_bounds__(256) void gemm_pv_f4(
        const float* __restrict__ probs, const float* __restrict__ qkv,
        float* __restrict__ ctx_all, int H, int band, int colbase) {
    const int z = blockIdx.z;
    const int b = z / H, h = z % H;
    const int m0 = blockIdx.y * BM;
    const float* A  = probs + (size_t)z*SS*SS;                  // lda=SS
    const float* Bv = qkv + (size_t)b*SS*D3 + 2*DD + h*128;     // ldb=3D
    float* C = ctx_all + (size_t)b*SS*D3 + colbase + h*128;     // ldc=3D
    __shared__ float As[BK][SMS];
    __shared__ float Bs[BK][SMS];
    const int tid = threadIdx.x;
    const int tx = tid & 15, ty = tid >> 4;
    float acc[8][8] = {};
    for (int k0 = 0; k0 < SS; k0 += BK) {
        if (band >= 0 && (k0 + BK - 1) < m0 - band) continue;   // P-tile all zero
#pragma unroll
        for (int i = 0; i < 2; i++) {
            int idx = tid + i*256;
            int r = idx >> 2, kq = (idx & 3) * 4;
            float4 va = *(const float4*)(A + (size_t)(m0 + r)*SS + k0 + kq);
            As[kq+0][r] = va.x; As[kq+1][r] = va.y; As[kq+2][r] = va.z; As[kq+3][r] = va.w;
            int k = idx >> 5, nq = (idx & 31) * 4;
            *(float4*)&Bs[k][nq] = *(const float4*)(Bv + (size_t)(k0 + k)*D3 + nq);
        }
        __syncthreads();
#pragma unroll
        for (int k = 0; k < BK; k++) {
            float a[8], b2[8];
            *(float4*)&a[0]  = *(const float4*)&As[k][ty*8];
            *(float4*)&a[4]  = *(const float4*)&As[k][ty*8+4];
            *(float4*)&b2[0] = *(const float4*)&Bs[k][tx*8];
            *(float4*)&b2[4] = *(const float4*)&Bs[k][tx*8+4];
#pragma unroll
            for (int i = 0; i < 8; i++)
#pragma unroll
                for (int j = 0; j < 8; j++)
                    acc[i][j] = fmaf(a[i], b2[j], acc[i][j]);
        }
        __syncthreads();
    }
#pragma unroll
    for (int i = 0; i < 8; i++) {
        int m = m0 + ty*8 + i;
#pragma unroll
        for (int jq = 0; jq < 2; jq++) {
            int n = tx*8 + jq*4;
            *(float4*)(C + (size_t)m*D3 + n) =
                make_float4(acc[i][jq*4+0], acc[i][jq*4+1], acc[i][jq*4+2], acc[i][jq*4+3]);
        }
    }
}

// ===================== ctx = P @ V (BN=64, dk=64 long branch) ===============
__global__ __launch_bounds__(256) void gemm_pv64_f4(
        const float* __restrict__ probs, const float* __restrict__ qkv,
        float* __restrict__ ctx_all, int colbase) {
    const int z = blockIdx.z;           // B*16
    const int b = z >> 4, h = z & 15;
    const int m0 = blockIdx.y * BM;
    const float* A  = probs + (size_t)z*SS*SS;
    const float* Bv = qkv + (size_t)b*SS*D3 + 2*DD + h*64;
    float* C = ctx_all + (size_t)b*SS*D3 + colbase + h*64;
    __shared__ float As[BK][SMS];
    __shared__ float Bs[BK][64+4];
    const int tid = threadIdx.x;
    const int tx = tid & 15, ty = tid >> 4;
    float acc[8][4] = {};
    for (int k0 = 0; k0 < SS; k0 += BK) {
#pragma unroll
        for (int i = 0; i < 2; i++) {
            int idx = tid + i*256;
            int r = idx >> 2, kq = (idx & 3) * 4;
            float4 va = *(const float4*)(A + (size_t)(m0 + r)*SS + k0 + kq);
            As[kq+0][r] = va.x; As[kq+1][r] = va.y; As[kq+2][r] = va.z; As[kq+3][r] = va.w;
        }
        {
            int k = tid >> 4, nq = (tid & 15) * 4;   // 16*16 float4 = 1024 floats
            *(float4*)&Bs[k][nq] = *(const float4*)(Bv + (size_t)(k0 + k)*D3 + nq);
        }
        __syncthreads();
#pragma unroll
        for (int k = 0; k < BK; k++) {
            float a[8], b2[4];
            *(float4*)&a[0]  = *(const float4*)&As[k][ty*8];
            *(float4*)&a[4]  = *(const float4*)&As[k][ty*8+4];
            *(float4*)&b2[0] = *(const float4*)&Bs[k][tx*4];
#pragma unroll
            for (int i = 0; i < 8; i++)
#pragma unroll
                for (int j = 0; j < 4; j++)
                    acc[i][j] = fmaf(a[i], b2[j], acc[i][j]);
        }
        __syncthreads();
    }
#pragma unroll
    for (int i = 0; i < 8; i++) {
        int m = m0 + ty*8 + i;
        int n = tx*4;
        *(float4*)(C + (size_t)m*D3 + n) =
            make_float4(acc[i][0], acc[i][1], acc[i][2], acc[i][3]);
    }
}

// ===================== row softmax (in-place, scale pre-applied) ============
__global__ __launch_bounds__(256) void softmax_rows(float* __restrict__ scores, int band) {
    __shared__ float srow[SS];
    __shared__ float redA[8];
    __shared__ float redB[8];
    const int rid = blockIdx.x;
    const int i = rid % SS;
    float* row = scores + (size_t)rid * SS;
    const int jstart = (band >= 0) ? max(0, i - band) : 0;
    const int t = threadIdx.x;
    float lmax = -1e30f;
    for (int g = t; g < SS/4; g += 256) {
        float4 v = ((const float4*)row)[g];
        int j = g*4;
        float v0 = (j+0 >= jstart) ? v.x : -1e30f;
        float v1 = (j+1 >= jstart) ? v.y : -1e30f;
        float v2 = (j+2 >= jstart) ? v.z : -1e30f;
        float v3 = (j+3 >= jstart) ? v.w : -1e30f;
        ((float4*)srow)[g] = make_float4(v0, v1, v2, v3);
        lmax = fmaxf(fmaxf(fmaxf(v0, v1), v2), fmaxf(v3, lmax));
    }
#pragma unroll
    for (int o = 16; o; o >>= 1) lmax = fmaxf(lmax, __shfl_xor_sync(0xffffffffu, lmax, o));
    if ((t & 31) == 0) redA[t >> 5] = lmax;
    __syncthreads();
    float m = redA[0];
#pragma unroll
    for (int w = 1; w < 8; w++) m = fmaxf(m, redA[w]);
    float lsum = 0.f;
    for (int g = t; g < SS/4; g += 256) {
        float4 v = ((const float4*)srow)[g];
        float e0 = (v.x > -1e29f) ? __expf(v.x - m) : 0.f;
        float e1 = (v.y > -1e29f) ? __expf(v.y - m) : 0.f;
        float e2 = (v.z > -1e29f) ? __expf(v.z - m) : 0.f;
        float e3 = (v.w > -1e29f) ? __expf(v.w - m) : 0.f;
        ((float4*)srow)[g] = make_float4(e0, e1, e2, e3);
        lsum += e0 + e1 + e2 + e3;
    }
#pragma unroll
    for (int o = 16; o; o >>= 1) lsum += __shfl_xor_sync(0xffffffffu, lsum, o);
    if ((t & 31) == 0) redB[t >> 5] = lsum;
    __syncthreads();
    float s = 0.f;
#pragma unroll
    for (int w = 0; w < 8; w++) s += redB[w];
    const float inv = 1.f / s;
    for (int g = t; g < SS/4; g += 256) {
        float4 v = ((const float4*)srow)[g];
        ((float4*)row)[g] = make_float4(v.x*inv, v.y*inv, v.z*inv, v.w*inv);
    }
}

// ===================== long-branch attn mean over 16 heads ==================
__global__ __launch_bounds__(256) void attn_mean(const float* __restrict__ probs,
                                                 float* __restrict__ out) {
    const int b = blockIdx.x / SS, i = blockIdx.x % SS;
    const size_t rowlen4 = SS/4;
    for (int g = threadIdx.x; g < SS/4; g += 256) {
        float4 s = make_float4(0.f, 0.f, 0.f, 0.f);
#pragma unroll
        for (int h = 0; h < 16; h++) {
            float4 v = ((const float4*)probs)[((size_t)(b*16 + h)*SS + i)*rowlen4 + g];
            s.x += v.x; s.y += v.y; s.z += v.z; s.w += v.w;
        }
        ((float4*)out)[(size_t)blockIdx.x*rowlen4 + g] =
            make_float4(s.x*(1.f/16.f), s.y*(1.f/16.f), s.z*(1.f/16.f), s.w*(1.f/16.f));
    }
}

// ===================== fused bias: b_comb + w_comb @ [bo_s;bo_m;bo_l] =======
__global__ void bias_comb(const float* __restrict__ w_comb,
                          const float* __restrict__ b_comb,
                          const float* __restrict__ bo_s,
                          const float* __restrict__ bo_m,
                          const float* __restrict__ bo_l,
                          float* __restrict__ bias_total) {
    const int p = blockIdx.x;
    __shared__ float red[256];
    float s = 0.f;
    for (int q = threadIdx.x; q < D3; q += 256) {
        float bo = (q < DD) ? bo_s[q] : (q < 2*DD) ? bo_m[q - DD] : bo_l[q - 2*DD];
        s += w_comb[(size_t)p*D3 + q] * bo;
    }
    red[threadIdx.x] = s; __syncthreads();
    for (int k = 128; k > 0; k >>= 1) {
        if (threadIdx.x < k) red[threadIdx.x] += red[threadIdx.x + k];
        __syncthreads();
    }
    if (threadIdx.x == 0) bias_total[p] = red[0] + b_comb[p];
}

// ===================== residual + layernorm (vectorized) ====================
__global__ __launch_bounds__(256) void ln_kernel(
        const float* __restrict__ y, const float* __restrict__ x,
        const float* __restrict__ gamma, const float* __restrict__ beta,
        float* __restrict__ out) {
    const int row = blockIdx.x;
    __shared__ float redA[8];
    __shared__ float redB[8];
    const int t = threadIdx.x;
    const float4* yr = (const float4*)(y + (size_t)row*DD);
    const float4* xr = (const float4*)(x + (size_t)row*DD);
    float4 yv = yr[t], xv = xr[t];
    float4 v = make_float4(yv.x+xv.x, yv.y+xv.y, yv.z+xv.z, yv.w+xv.w);
    float s  = v.x + v.y + v.z + v.w;
    float s2 = v.x*v.x + v.y*v.y + v.z*v.z + v.w*v.w;
#pragma unroll
    for (int o = 16; o; o >>= 1) {
        s  += __shfl_xor_sync(0xffffffffu, s,  o);
        s2 += __shfl_xor_sync(0xffffffffu, s2, o);
    }
    if ((t & 31) == 0) { redA[t >> 5] = s; redB[t >> 5] = s2; }
    __syncthreads();
    float ts = 0.f, ts2 = 0.f;
#pragma unroll
    for (int w = 0; w < 8; w++) { ts += redA[w]; ts2 += redB[w]; }
    const float mu  = ts * (1.f/DD);
    const float var = ts2 * (1.f/DD) - mu*mu;
    const float rs  = rsqrtf(var + 1e-5f);
    const float4 g4 = ((const float4*)gamma)[t];
    const float4 b4 = ((const float4*)beta)[t];
    ((float4*)(out + (size_t)row*DD))[t] = make_float4(
        (v.x - mu)*rs*g4.x + b4.x, (v.y - mu)*rs*g4.y + b4.y,
        (v.z - mu)*rs*g4.z + b4.z, (v.w - mu)*rs*g4.w + b4.w);
}

// ===================== orchestration ========================================
extern "C" void kernel_launch(void* const* d_in, const int* in_sizes, int n_in,
                              void* d_out, int out_size) {
    const float* x      = (const float*)d_in[0];
    const float* w_in_s = (const float*)d_in[1];
    const float* b_in_s = (const float*)d_in[2];
    const float* wo_s   = (const float*)d_in[3];
    const float* bo_s   = (const float*)d_in[4];
    const float* w_in_m = (const float*)d_in[5];
    const float* b_in_m = (const float*)d_in[6];
    const float* wo_m   = (const float*)d_in[7];
    const float* bo_m   = (const float*)d_in[8];
    const float* w_in_l = (const float*)d_in[9];
    const float* b_in_l = (const float*)d_in[10];
    const float* wo_l   = (const float*)d_in[11];
    const float* bo_l   = (const float*)d_in[12];
    const float* w_comb = (const float*)d_in[13];
    const float* b_comb = (const float*)d_in[14];
    const float* gamma  = (const float*)d_in[15];
    const float* beta   = (const float*)d_in[16];
    float* out = (float*)d_out;

    float *qkv_s, *qkv_m, *qkv_l, *scores, *ctx, *Mall, *biasT, *comb_out;
    cudaGetSymbolAddress((void**)&qkv_s,    g_qkv_s);
    cudaGetSymbolAddress((void**)&qkv_m,    g_qkv_m);
    cudaGetSymbolAddress((void**)&qkv_l,    g_qkv_l);
    cudaGetSymbolAddress((void**)&scores,   g_scores);
    cudaGetSymbolAddress((void**)&ctx,      g_ctx);
    cudaGetSymbolAddress((void**)&Mall,     g_Mall);
    cudaGetSymbolAddress((void**)&biasT,    g_bias);
    cudaGetSymbolAddress((void**)&comb_out, g_comb_out);

    // ---- fused weights: M_b = w_comb[:, bD:(b+1)D] @ wo_b  (stored in Mall cols bD..) ----
    {
        dim3 g(DD/BN, DD/BM);
        gemm_nn_f4<<<g, 256>>>(w_comb + 0*DD, D3, wo_s, DD, Mall + 0*DD, D3, DD);
        gemm_nn_f4<<<g, 256>>>(w_comb + 1*DD, D3, wo_m, DD, Mall + 1*DD, D3, DD);
        gemm_nn_f4<<<g, 256>>>(w_comb + 2*DD, D3, wo_l, DD, Mall + 2*DD, D3, DD);
        bias_comb<<<DD, 256>>>(w_comb, b_comb, bo_s, bo_m, bo_l, biasT);
    }

    // ---- QKV projections ----
    dim3 gqkv(D3/BN, BS/BM);
    gemm_nt_f4<<<gqkv, 256>>>(x, DD, w_in_s, DD, b_in_s, qkv_s, D3, DD);
    gemm_nt_f4<<<gqkv, 256>>>(x, DD, w_in_m, DD, b_in_m, qkv_m, D3, DD);
    gemm_nt_f4<<<gqkv, 256>>>(x, DD, w_in_l, DD, b_in_l, qkv_l, D3, DD);

    const float sc128 = 1.f / sqrtf(128.f);
    const float sc64  = 1.f / sqrtf(64.f);

    // ---- short branch: H=8, dk=128, band=10 ----
    {
        dim3 gqk(SS/BN, SS/BM, BB*8);
        gemm_qk_f4<<<gqk, 256>>>(qkv_s, scores, 8, 128, 10, sc128);
        softmax_rows<<<BB*8*SS, 256>>>(scores, 10);
        dim3 gpv(1, SS/BM, BB*8);
        gemm_pv_f4<<<gpv, 256>>>(scores, qkv_s, ctx, 8, 10, 0);
    }
    // ---- medium branch: H=8, dk=128, band=30 ----
    {
        dim3 gqk(SS/BN, SS/BM, BB*8);
        gemm_qk_f4<<<gqk, 256>>>(qkv_m, scores, 8, 128, 30, sc128);
        softmax_rows<<<BB*8*SS, 256>>>(scores, 30);
        dim3 gpv(1, SS/BM, BB*8);
        gemm_pv_f4<<<gpv, 256>>>(scores, qkv_m, ctx, 8, 30, DD);
    }
    // ---- long branch: H=16, dk=64, no band ----
    {
        dim3 gqk(SS/BN, SS/BM, BB*16);
        gemm_qk_f4<<<gqk, 256>>>(qkv_l, scores, 16, 64, -1, sc64);
        softmax_rows<<<BB*16*SS, 256>>>(scores, -1);
        if ((size_t)out_size >= BSD + BSS)
            attn_mean<<<BB*SS, 256>>>(scores, out + BSD);
        dim3 gpv(1, SS/BM, BB*16);
        gemm_pv64_f4<<<gpv, 256>>>(scores, qkv_l, ctx, 2*DD);
    }

    // ---- fused output: comb_out = ctx_all @ Mall^T + biasT ----
    dim3 gc(DD/BN, BS/BM);
    gemm_nt_f4<<<gc, 256>>>(ctx, D3, Mall, D3, biasT, comb_out, DD, D3);

    // ---- residual + LN ----
    ln_kernel<<<BS, 256>>>(comb_out, x, gamma, beta, out);
}

// round 7
// speedup vs baseline: 3.2183x; 2.0766x over previous
#include <cuda_runtime.h>
#include <cuda_bf16.h>
#include <math.h>

// Problem constants
#define BB 2
#define SS 2048
#define DD 1024
#define D3 (3*DD)
#define BS (BB*SS)             // 4096
#define BSD ((size_t)BS*DD)    // 4,194,304
#define BSS ((size_t)BB*SS*SS) // 8,388,608

// ----------------- scratch buffers (static device globals; no allocs) ------
__device__ float g_qkv_s[(size_t)BS*D3];
__device__ float g_qkv_m[(size_t)BS*D3];
__device__ float g_qkv_l[(size_t)BS*D3];
__device__ float g_scores[(size_t)BB*16*SS*SS];   // sized for long branch
__device__ float g_ctx[(size_t)BS*D3];            // concatenated ctx (s|m|l)
__device__ float g_Mall[(size_t)DD*D3];           // fused wo∘w_comb weights
__device__ float g_bias[DD];
__device__ float g_comb_out[(size_t)BS*DD];

// ===================== TF32 mma helpers =====================================
__device__ __forceinline__ float tfF(float f) {
    unsigned u;
    asm("cvt.rna.tf32.f32 %0, %1;" : "=r"(u) : "f"(f));
    return __uint_as_float(u);
}
__device__ __forceinline__ float4 tf4(float4 v) {
    return make_float4(tfF(v.x), tfF(v.y), tfF(v.z), tfF(v.w));
}
__device__ __forceinline__ void mma8(float c[4], const unsigned a[4], const unsigned b[2]) {
    asm volatile(
        "mma.sync.aligned.m16n8k8.row.col.f32.tf32.tf32.f32 "
        "{%0,%1,%2,%3}, {%4,%5,%6,%7}, {%8,%9}, {%0,%1,%2,%3};"
        : "+f"(c[0]), "+f"(c[1]), "+f"(c[2]), "+f"(c[3])
        : "r"(a[0]), "r"(a[1]), "r"(a[2]), "r"(a[3]), "r"(b[0]), "r"(b[1]));
}

// ===================== core: 128x128 block, 8 warps (2m x 4n), warp 64x32 ===
// A: block-local rows [0,128), k-contiguous (lda given). BKC=true: B is [N,K]
// k-contig (NT); BKC=false: B is [K,N] n-contig (NN). K-loop starts at k0start
// (band skip), contiguous to K. acc[mf][nf][4].
template<bool BKC>
__device__ __forceinline__ void core128(
        const float* __restrict__ A, int lda,
        const float* __restrict__ B, int ldb,
        int K, int k0start,
        float (&acc)[4][4][4])
{
    __shared__ float As[128][20];
    __shared__ float Bs[16][136];
    const int tid  = threadIdx.x;
    const int lane = tid & 31, w = tid >> 5;
    const int wm = w & 1, wn = w >> 1;
    const int g = lane >> 2, tg = lane & 3;

    // staging indices
    const int r0  = tid >> 2;          // 0..63 ; second pass uses r0+64
    const int kq0 = (tid & 3) * 4;     // 0,4,8,12
    const int kb  = tid >> 5;          // NN: 0..7 ; second pass kb+8
    const int nqb = (tid & 31) * 4;    // NN: 0..124

    float4 pa0, pa1, pb0, pb1;
    auto ldt = [&](int k0) {
        pa0 = *(const float4*)(A + (size_t)r0       *lda + k0 + kq0);
        pa1 = *(const float4*)(A + (size_t)(r0 + 64)*lda + k0 + kq0);
        if (BKC) {
            pb0 = *(const float4*)(B + (size_t)r0       *ldb + k0 + kq0);
            pb1 = *(const float4*)(B + (size_t)(r0 + 64)*ldb + k0 + kq0);
        } else {
            pb0 = *(const float4*)(B + (size_t)(k0 + kb    )*ldb + nqb);
            pb1 = *(const float4*)(B + (size_t)(k0 + kb + 8)*ldb + nqb);
        }
    };
    auto sts = [&]() {
        As[r0][kq0+0] = tfF(pa0.x); As[r0][kq0+1] = tfF(pa0.y);
        As[r0][kq0+2] = tfF(pa0.z); As[r0][kq0+3] = tfF(pa0.w);
        As[r0+64][kq0+0] = tfF(pa1.x); As[r0+64][kq0+1] = tfF(pa1.y);
        As[r0+64][kq0+2] = tfF(pa1.z); As[r0+64][kq0+3] = tfF(pa1.w);
        if (BKC) {
            Bs[kq0+0][r0] = tfF(pb0.x); Bs[kq0+1][r0] = tfF(pb0.y);
            Bs[kq0+2][r0] = tfF(pb0.z); Bs[kq0+3][r0] = tfF(pb0.w);
            Bs[kq0+0][r0+64] = tfF(pb1.x); Bs[kq0+1][r0+64] = tfF(pb1.y);
            Bs[kq0+2][r0+64] = tfF(pb1.z); Bs[kq0+3][r0+64] = tfF(pb1.w);
        } else {
            *(float4*)&Bs[kb][nqb]     = tf4(pb0);
            *(float4*)&Bs[kb + 8][nqb] = tf4(pb1);
        }
    };

    int k0 = k0start;
    ldt(k0);
    sts();
    __syncthreads();

    for (;;) {
        const int kn = k0 + 16;
        const bool more = kn < K;
        if (more) ldt(kn);

#pragma unroll
        for (int kk = 0; kk < 16; kk += 8) {
            unsigned a[4][4];
#pragma unroll
            for (int mf = 0; mf < 4; mf++) {
                int m = wm*64 + mf*16 + g;
                a[mf][0] = __float_as_uint(As[m    ][kk + tg    ]);
                a[mf][1] = __float_as_uint(As[m + 8][kk + tg    ]);
                a[mf][2] = __float_as_uint(As[m    ][kk + tg + 4]);
                a[mf][3] = __float_as_uint(As[m + 8][kk + tg + 4]);
            }
            unsigned b[4][2];
#pragma unroll
            for (int nf = 0; nf < 4; nf++) {
                int n = wn*32 + nf*8 + g;
                b[nf][0] = __float_as_uint(Bs[kk + tg    ][n]);
                b[nf][1] = __float_as_uint(Bs[kk + tg + 4][n]);
            }
#pragma unroll
            for (int mf = 0; mf < 4; mf++)
#pragma unroll
                for (int nf = 0; nf < 4; nf++)
                    mma8(acc[mf][nf], a[mf], b[nf]);
        }

        if (!more) break;
        __syncthreads();
        sts();
        __syncthreads();
        k0 = kn;
    }
}

// ===================== core: 128x64 block, 8 warps (4m x 2n), warp 32x32 ====
// NN only (used by long-branch PV). acc[mf(2)][nf(4)][4].
__device__ __forceinline__ void core64nn(
        const float* __restrict__ A, int lda,
        const float* __restrict__ B, int ldb,
        int K, int k0start,
        float (&acc)[2][4][4])
{
    __shared__ float As[128][20];
    __shared__ float Bs[16][72];
    const int tid  = threadIdx.x;
    const int lane = tid & 31, w = tid >> 5;
    const int wm = w & 3, wn = w >> 2;
    const int g = lane >> 2, tg = lane & 3;

    const int r0  = tid >> 2;
    const int kq0 = (tid & 3) * 4;
    const int kb  = tid >> 4;          // 0..15
    const int nqb = (tid & 15) * 4;    // 0..60

    float4 pa0, pa1, pb0;
    auto ldt = [&](int k0) {
        pa0 = *(const float4*)(A + (size_t)r0       *lda + k0 + kq0);
        pa1 = *(const float4*)(A + (size_t)(r0 + 64)*lda + k0 + kq0);
        pb0 = *(const float4*)(B + (size_t)(k0 + kb)*ldb + nqb);
    };
    auto sts = [&]() {
        As[r0][kq0+0] = tfF(pa0.x); As[r0][kq0+1] = tfF(pa0.y);
        As[r0][kq0+2] = tfF(pa0.z); As[r0][kq0+3] = tfF(pa0.w);
        As[r0+64][kq0+0] = tfF(pa1.x); As[r0+64][kq0+1] = tfF(pa1.y);
        As[r0+64][kq0+2] = tfF(pa1.z); As[r0+64][kq0+3] = tfF(pa1.w);
        *(float4*)&Bs[kb][nqb] = tf4(pb0);
    };

    int k0 = k0start;
    ldt(k0);
    sts();
    __syncthreads();

    for (;;) {
        const int kn = k0 + 16;
        const bool more = kn < K;
        if (more) ldt(kn);

#pragma unroll
        for (int kk = 0; kk < 16; kk += 8) {
            unsigned a[2][4];
#pragma unroll
            for (int mf = 0; mf < 2; mf++) {
                int m = wm*32 + mf*16 + g;
                a[mf][0] = __float_as_uint(As[m    ][kk + tg    ]);
                a[mf][1] = __float_as_uint(As[m + 8][kk + tg    ]);
                a[mf][2] = __float_as_uint(As[m    ][kk + tg + 4]);
                a[mf][3] = __float_as_uint(As[m + 8][kk + tg + 4]);
            }
            unsigned b[4][2];
#pragma unroll
            for (int nf = 0; nf < 4; nf++) {
                int n = wn*32 + nf*8 + g;
                b[nf][0] = __float_as_uint(Bs[kk + tg    ][n]);
                b[nf][1] = __float_as_uint(Bs[kk + tg + 4][n]);
            }
#pragma unroll
            for (int mf = 0; mf < 2; mf++)
#pragma unroll
                for (int nf = 0; nf < 4; nf++)
                    mma8(acc[mf][nf], a[mf], b[nf]);
        }

        if (!more) break;
        __syncthreads();
        sts();
        __syncthreads();
        k0 = kn;
    }
}

// ===================== C = A @ W^T + bias (NT) ==============================
__global__ __launch_bounds__(256) void k_mma_nt_bias(
        const float* __restrict__ A, int lda,
        const float* __restrict__ W, int ldb,
        const float* __restrict__ bias,
        float* __restrict__ C, int ldc, int K)
{
    const int m0 = blockIdx.y * 128, n0 = blockIdx.x * 128;
    float acc[4][4][4] = {};
    core128<true>(A + (size_t)m0*lda, lda, W + (size_t)n0*ldb, ldb, K, 0, acc);
    const int lane = threadIdx.x & 31, w = threadIdx.x >> 5;
    const int wm = w & 1, wn = w >> 1, g = lane >> 2, tg = lane & 3;
#pragma unroll
    for (int mf = 0; mf < 4; mf++) {
        int row = m0 + wm*64 + mf*16 + g;
#pragma unroll
        for (int nf = 0; nf < 4; nf++) {
            int col = n0 + wn*32 + nf*8 + tg*2;
            float2 bv = *(const float2*)(bias + col);
            *(float2*)(C + (size_t)row*ldc + col) =
                make_float2(acc[mf][nf][0] + bv.x, acc[mf][nf][1] + bv.y);
            *(float2*)(C + (size_t)(row+8)*ldc + col) =
                make_float2(acc[mf][nf][2] + bv.x, acc[mf][nf][3] + bv.y);
        }
    }
}

// ===================== C = A @ B (NN), no bias ==============================
__global__ __launch_bounds__(256) void k_mma_nn(
        const float* __restrict__ A, int lda,
        const float* __restrict__ B, int ldb,
        float* __restrict__ C, int ldc, int K)
{
    const int m0 = blockIdx.y * 128, n0 = blockIdx.x * 128;
    float acc[4][4][4] = {};
    core128<false>(A + (size_t)m0*lda, lda, B + n0, ldb, K, 0, acc);
    const int lane = threadIdx.x & 31, w = threadIdx.x >> 5;
    const int wm = w & 1, wn = w >> 1, g = lane >> 2, tg = lane & 3;
#pragma unroll
    for (int mf = 0; mf < 4; mf++) {
        int row = m0 + wm*64 + mf*16 + g;
#pragma unroll
        for (int nf = 0; nf < 4; nf++) {
            int col = n0 + wn*32 + nf*8 + tg*2;
            *(float2*)(C + (size_t)row*ldc + col) =
                make_float2(acc[mf][nf][0], acc[mf][nf][1]);
            *(float2*)(C + (size_t)(row+8)*ldc + col) =
                make_float2(acc[mf][nf][2], acc[mf][nf][3]);
        }
    }
}

// ===================== scores = scale * Q @ K^T (batched, band skip) ========
__global__ __launch_bounds__(256) void k_mma_qk(
        const float* __restrict__ qkv, float* __restrict__ scores,
        int H, int dk, int band, float scale)
{
    const int z = blockIdx.z;
    const int b = z / H, h = z % H;
    const int m0 = blockIdx.y * 128, n0 = blockIdx.x * 128;
    if (band >= 0 && (n0 + 127) < m0 - band) return;   // fully masked tile
    const float* Aq = qkv + (size_t)b*SS*D3 + h*dk + (size_t)m0*D3;
    const float* Bk = qkv + (size_t)b*SS*D3 + DD + h*dk + (size_t)n0*D3;
    float* C = scores + (size_t)z*SS*SS;
    float acc[4][4][4] = {};
    core128<true>(Aq, D3, Bk, D3, dk, 0, acc);
    const int lane = threadIdx.x & 31, w = threadIdx.x >> 5;
    const int wm = w & 1, wn = w >> 1, g = lane >> 2, tg = lane & 3;
#pragma unroll
    for (int mf = 0; mf < 4; mf++) {
        int row = m0 + wm*64 + mf*16 + g;
#pragma unroll
        for (int nf = 0; nf < 4; nf++) {
            int col = n0 + wn*32 + nf*8 + tg*2;
            *(float2*)(C + (size_t)row*SS + col) =
                make_float2(acc[mf][nf][0]*scale, acc[mf][nf][1]*scale);
            *(float2*)(C + (size_t)(row+8)*SS + col) =
                make_float2(acc[mf][nf][2]*scale, acc[mf][nf][3]*scale);
        }
    }
}

// ===================== ctx = P @ V (dk=128 heads, NN, band k-skip) ==========
__global__ __launch_bounds__(256) void k_mma_pv(
        const float* __restrict__ probs, const float* __restrict__ qkv,
        float* __restrict__ ctx_all, int H, int band, int colbase)
{
    const int z = blockIdx.z;
    const int b = z / H, h = z % H;
    const int m0 = blockIdx.y * 128;
    const float* A  = probs + (size_t)z*SS*SS + (size_t)m0*SS;
    const float* Bv = qkv + (size_t)b*SS*D3 + 2*DD + h*128;
    float* C = ctx_all + (size_t)b*SS*D3 + colbase + h*128;
    const int k0start = (band >= 0) ? ((max(0, m0 - band) >> 4) << 4) : 0;
    float acc[4][4][4] = {};
    core128<false>(A, SS, Bv, D3, SS, k0start, acc);
    const int lane = threadIdx.x & 31, w = threadIdx.x >> 5;
    const int wm = w & 1, wn = w >> 1, g = lane >> 2, tg = lane & 3;
#pragma unroll
    for (int mf = 0; mf < 4; mf++) {
        int row = m0 + wm*64 + mf*16 + g;
#pragma unroll
        for (int nf = 0; nf < 4; nf++) {
            int col = wn*32 + nf*8 + tg*2;
            *(float2*)(C + (size_t)row*D3 + col) =
                make_float2(acc[mf][nf][0], acc[mf][nf][1]);
            *(float2*)(C + (size_t)(row+8)*D3 + col) =
                make_float2(acc[mf][nf][2], acc[mf][nf][3]);
        }
    }
}

// ===================== ctx = P @ V (dk=64 long branch, NN) ==================
__global__ __launch_bounds__(256) void k_mma_pv64(
        const float* __restrict__ probs, const float* __restrict__ qkv,
        float* __restrict__ ctx_all, int colbase)
{
    const int z = blockIdx.z;            // BB*16
    const int b = z >> 4, h = z & 15;
    const int m0 = blockIdx.y * 128;
    const float* A  = probs + (size_t)z*SS*SS + (size_t)m0*SS;
    const float* Bv = qkv + (size_t)b*SS*D3 + 2*DD + h*64;
    float* C = ctx_all + (size_t)b*SS*D3 + colbase + h*64;
    float acc[2][4][4] = {};
    core64nn(A, SS, Bv, D3, SS, 0, acc);
    const int lane = threadIdx.x & 31, w = threadIdx.x >> 5;
    const int wm = w & 3, wn = w >> 2, g = lane >> 2, tg = lane & 3;
#pragma unroll
    for (int mf = 0; mf < 2; mf++) {
        int row = m0 + wm*32 + mf*16 + g;
#pragma unroll
        for (int nf = 0; nf < 4; nf++) {
            int col = wn*32 + nf*8 + tg*2;
            *(float2*)(C + (size_t)row*D3 + col) =
                make_float2(acc[mf][nf][0], acc[mf][nf][1]);
            *(float2*)(C + (size_t)(row+8)*D3 + col) =
                make_float2(acc[mf][nf][2], acc[mf][nf][3]);
        }
    }
}

// ===================== row softmax (in-place, scale pre-applied) ============
__global__ __launch_bounds__(256) void softmax_rows(float* __restrict__ scores, int band) {
    __shared__ float srow[SS];
    __shared__ float redA[8];
    __shared__ float redB[8];
    const int rid = blockIdx.x;
    const int i = rid % SS;
    float* row = scores + (size_t)rid * SS;
    const int jstart = (band >= 0) ? max(0, i - band) : 0;
    const int t = threadIdx.x;
    float lmax = -1e30f;
    for (int g = t; g < SS/4; g += 256) {
        float4 v = ((const float4*)row)[g];
        int j = g*4;
        float v0 = (j+0 >= jstart) ? v.x : -1e30f;
        float v1 = (j+1 >= jstart) ? v.y : -1e30f;
        float v2 = (j+2 >= jstart) ? v.z : -1e30f;
        float v3 = (j+3 >= jstart) ? v.w : -1e30f;
        ((float4*)srow)[g] = make_float4(v0, v1, v2, v3);
        lmax = fmaxf(fmaxf(fmaxf(v0, v1), v2), fmaxf(v3, lmax));
    }
#pragma unroll
    for (int o = 16; o; o >>= 1) lmax = fmaxf(lmax, __shfl_xor_sync(0xffffffffu, lmax, o));
    if ((t & 31) == 0) redA[t >> 5] = lmax;
    __syncthreads();
    float m = redA[0];
#pragma unroll
    for (int w = 1; w < 8; w++) m = fmaxf(m, redA[w]);
    float lsum = 0.f;
    for (int g = t; g < SS/4; g += 256) {
        float4 v = ((const float4*)srow)[g];
        float e0 = (v.x > -1e29f) ? __expf(v.x - m) : 0.f;
        float e1 = (v.y > -1e29f) ? __expf(v.y - m) : 0.f;
        float e2 = (v.z > -1e29f) ? __expf(v.z - m) : 0.f;
        float e3 = (v.w > -1e29f) ? __expf(v.w - m) : 0.f;
        ((float4*)srow)[g] = make_float4(e0, e1, e2, e3);
        lsum += e0 + e1 + e2 + e3;
    }
#pragma unroll
    for (int o = 16; o; o >>= 1) lsum += __shfl_xor_sync(0xffffffffu, lsum, o);
    if ((t & 31) == 0) redB[t >> 5] = lsum;
    __syncthreads();
    float s = 0.f;
#pragma unroll
    for (int w = 0; w < 8; w++) s += redB[w];
    const float inv = 1.f / s;
    for (int g = t; g < SS/4; g += 256) {
        float4 v = ((const float4*)srow)[g];
        ((float4*)row)[g] = make_float4(v.x*inv, v.y*inv, v.z*inv, v.w*inv);
    }
}

// ===================== long-branch attn mean over 16 heads ==================
__global__ __launch_bounds__(256) void attn_mean(const float* __restrict__ probs,
                                                 float* __restrict__ out) {
    const int b = blockIdx.x / SS, i = blockIdx.x % SS;
    const size_t rowlen4 = SS/4;
    for (int g = threadIdx.x; g < SS/4; g += 256) {
        float4 s = make_float4(0.f, 0.f, 0.f, 0.f);
#pragma unroll
        for (int h = 0; h < 16; h++) {
            float4 v = ((const float4*)probs)[((size_t)(b*16 + h)*SS + i)*rowlen4 + g];
            s.x += v.x; s.y += v.y; s.z += v.z; s.w += v.w;
        }
        ((float4*)out)[(size_t)blockIdx.x*rowlen4 + g] =
            make_float4(s.x*(1.f/16.f), s.y*(1.f/16.f), s.z*(1.f/16.f), s.w*(1.f/16.f));
    }
}

// ===================== fused bias: b_comb + w_comb @ [bo_s;bo_m;bo_l] =======
__global__ void bias_comb(const float* __restrict__ w_comb,
                          const float* __restrict__ b_comb,
                          const float* __restrict__ bo_s,
                          const float* __restrict__ bo_m,
                          const float* __restrict__ bo_l,
                          float* __restrict__ bias_total) {
    const int p = blockIdx.x;
    __shared__ float red[256];
    float s = 0.f;
    for (int q = threadIdx.x; q < D3; q += 256) {
        float bo = (q < DD) ? bo_s[q] : (q < 2*DD) ? bo_m[q - DD] : bo_l[q - 2*DD];
        s += w_comb[(size_t)p*D3 + q] * bo;
    }
    red[threadIdx.x] = s; __syncthreads();
    for (int k = 128; k > 0; k >>= 1) {
        if (threadIdx.x < k) red[threadIdx.x] += red[threadIdx.x + k];
        __syncthreads();
    }
    if (threadIdx.x == 0) bias_total[p] = red[0] + b_comb[p];
}

// ===================== residual + layernorm (vectorized) ====================
__global__ __launch_bounds__(256) void ln_kernel(
        const float* __restrict__ y, const float* __restrict__ x,
        const float* __restrict__ gamma, const float* __restrict__ beta,
        float* __restrict__ out) {
    const int row = blockIdx.x;
    __shared__ float redA[8];
    __shared__ float redB[8];
    const int t = threadIdx.x;
    const float4* yr = (const float4*)(y + (size_t)row*DD);
    const float4* xr = (const float4*)(x + (size_t)row*DD);
    float4 yv = yr[t], xv = xr[t];
    float4 v = make_float4(yv.x+xv.x, yv.y+xv.y, yv.z+xv.z, yv.w+xv.w);
    float s  = v.x + v.y + v.z + v.w;
    float s2 = v.x*v.x + v.y*v.y + v.z*v.z + v.w*v.w;
#pragma unroll
    for (int o = 16; o; o >>= 1) {
        s  += __shfl_xor_sync(0xffffffffu, s,  o);
        s2 += __shfl_xor_sync(0xffffffffu, s2, o);
    }
    if ((t & 31) == 0) { redA[t >> 5] = s; redB[t >> 5] = s2; }
    __syncthreads();
    float ts = 0.f, ts2 = 0.f;
#pragma unroll
    for (int w = 0; w < 8; w++) { ts += redA[w]; ts2 += redB[w]; }
    const float mu  = ts * (1.f/DD);
    const float var = ts2 * (1.f/DD) - mu*mu;
    const float rs  = rsqrtf(var + 1e-5f);
    const float4 g4 = ((const float4*)gamma)[t];
    const float4 b4 = ((const float4*)beta)[t];
    ((float4*)(out + (size_t)row*DD))[t] = make_float4(
        (v.x - mu)*rs*g4.x + b4.x, (v.y - mu)*rs*g4.y + b4.y,
        (v.z - mu)*rs*g4.z + b4.z, (v.w - mu)*rs*g4.w + b4.w);
}

// ===================== orchestration ========================================
extern "C" void kernel_launch(void* const* d_in, const int* in_sizes, int n_in,
                              void* d_out, int out_size) {
    const float* x      = (const float*)d_in[0];
    const float* w_in_s = (const float*)d_in[1];
    const float* b_in_s = (const float*)d_in[2];
    const float* wo_s   = (const float*)d_in[3];
    const float* bo_s   = (const float*)d_in[4];
    const float* w_in_m = (const float*)d_in[5];
    const float* b_in_m = (const float*)d_in[6];
    const float* wo_m   = (const float*)d_in[7];
    const float* bo_m   = (const float*)d_in[8];
    const float* w_in_l = (const float*)d_in[9];
    const float* b_in_l = (const float*)d_in[10];
    const float* wo_l   = (const float*)d_in[11];
    const float* bo_l   = (const float*)d_in[12];
    const float* w_comb = (const float*)d_in[13];
    const float* b_comb = (const float*)d_in[14];
    const float* gamma  = (const float*)d_in[15];
    const float* beta   = (const float*)d_in[16];
    float* out = (float*)d_out;

    float *qkv_s, *qkv_m, *qkv_l, *scores, *ctx, *Mall, *biasT, *comb_out;
    cudaGetSymbolAddress((void**)&qkv_s,    g_qkv_s);
    cudaGetSymbolAddress((void**)&qkv_m,    g_qkv_m);
    cudaGetSymbolAddress((void**)&qkv_l,    g_qkv_l);
    cudaGetSymbolAddress((void**)&scores,   g_scores);
    cudaGetSymbolAddress((void**)&ctx,      g_ctx);
    cudaGetSymbolAddress((void**)&Mall,     g_Mall);
    cudaGetSymbolAddress((void**)&biasT,    g_bias);
    cudaGetSymbolAddress((void**)&comb_out, g_comb_out);

    // ---- fused weights: M_b = w_comb[:, bD:(b+1)D] @ wo_b ----
    {
        dim3 g(DD/128, DD/128);
        k_mma_nn<<<g, 256>>>(w_comb + 0*DD, D3, wo_s, DD, Mall + 0*DD, D3, DD);
        k_mma_nn<<<g, 256>>>(w_comb + 1*DD, D3, wo_m, DD, Mall + 1*DD, D3, DD);
        k_mma_nn<<<g, 256>>>(w_comb + 2*DD, D3, wo_l, DD, Mall + 2*DD, D3, DD);
        bias_comb<<<DD, 256>>>(w_comb, b_comb, bo_s, bo_m, bo_l, biasT);
    }

    // ---- QKV projections ----
    dim3 gqkv(D3/128, BS/128);
    k_mma_nt_bias<<<gqkv, 256>>>(x, DD, w_in_s, DD, b_in_s, qkv_s, D3, DD);
    k_mma_nt_bias<<<gqkv, 256>>>(x, DD, w_in_m, DD, b_in_m, qkv_m, D3, DD);
    k_mma_nt_bias<<<gqkv, 256>>>(x, DD, w_in_l, DD, b_in_l, qkv_l, D3, DD);

    const float sc128 = 1.f / sqrtf(128.f);
    const float sc64  = 1.f / sqrtf(64.f);

    // ---- short branch: H=8, dk=128, band=10 ----
    {
        dim3 gqk(SS/128, SS/128, BB*8);
        k_mma_qk<<<gqk, 256>>>(qkv_s, scores, 8, 128, 10, sc128);
        softmax_rows<<<BB*8*SS, 256>>>(scores, 10);
        dim3 gpv(1, SS/128, BB*8);
        k_mma_pv<<<gpv, 256>>>(scores, qkv_s, ctx, 8, 10, 0);
    }
    // ---- medium branch: H=8, dk=128, band=30 ----
    {
        dim3 gqk(SS/128, SS/128, BB*8);
        k_mma_qk<<<gqk, 256>>>(qkv_m, scores, 8, 128, 30, sc128);
        softmax_rows<<<BB*8*SS, 256>>>(scores, 30);
        dim3 gpv(1, SS/128, BB*8);
        k_mma_pv<<<gpv, 256>>>(scores, qkv_m, ctx, 8, 30, DD);
    }
    // ---- long branch: H=16, dk=64, no band ----
    {
        dim3 gqk(SS/128, SS/128, BB*16);
        k_mma_qk<<<gqk, 256>>>(qkv_l, scores, 16, 64, -1, sc64);
        softmax_rows<<<BB*16*SS, 256>>>(scores, -1);
        if ((size_t)out_size >= BSD + BSS)
            attn_mean<<<BB*SS, 256>>>(scores, out + BSD);
        dim3 gpv(1, SS/128, BB*16);
        k_mma_pv64<<<gpv, 256>>>(scores, qkv_l, ctx, 2*DD);
    }

    // ---- fused output: comb_out = ctx_all @ Mall^T + biasT ----
    dim3 gc(DD/128, BS/128);
    k_mma_nt_bias<<<gc, 256>>>(ctx, D3, Mall, D3, biasT, comb_out, DD, D3);

    // ---- residual + LN ----
    ln_kernel<<<BS, 256>>>(comb_out, x, gamma, beta, out);
}

// round 8
// speedup vs baseline: 4.9373x; 1.5341x over previous
#include <cuda_runtime.h>
#include <cuda_bf16.h>
#include <math.h>

// Problem constants
#define BB 2
#define SS 2048
#define DD 1024
#define D3 (3*DD)
#define BS (BB*SS)             // 4096
#define BSD ((size_t)BS*DD)    // 4,194,304
#define BSS ((size_t)BB*SS*SS) // 8,388,608

typedef unsigned u32;
typedef __nv_bfloat16 bf16;

// ----------------- scratch buffers (static device globals; no allocs) ------
__device__ bf16  g_qkv_s[(size_t)BS*D3];
__device__ bf16  g_qkv_m[(size_t)BS*D3];
__device__ bf16  g_qkv_l[(size_t)BS*D3];
__device__ float g_scores[(size_t)BB*16*SS*SS];   // f32 scores (long-branch sized)
__device__ bf16  g_probs [(size_t)BB*16*SS*SS];   // bf16 probs
__device__ bf16  g_ctx[(size_t)BS*D3];            // concatenated ctx (s|m|l), bf16
__device__ bf16  g_Mall[(size_t)DD*D3];           // fused wo∘w_comb weights, bf16
__device__ float g_bias[DD];
__device__ float g_comb_out[(size_t)BS*DD];

// ===================== bf16 helpers =========================================
__device__ __forceinline__ u32 pk(float lo, float hi) {
    __nv_bfloat162 h = __floats2bfloat162_rn(lo, hi);
    return *reinterpret_cast<u32*>(&h);
}
__device__ __forceinline__ void mma16(float c[4], const u32 a[4], const u32 b[2]) {
    asm volatile(
        "mma.sync.aligned.m16n8k16.row.col.f32.bf16.bf16.f32 "
        "{%0,%1,%2,%3}, {%4,%5,%6,%7}, {%8,%9}, {%0,%1,%2,%3};"
        : "+f"(c[0]), "+f"(c[1]), "+f"(c[2]), "+f"(c[3])
        : "r"(a[0]), "r"(a[1]), "r"(a[2]), "r"(a[3]), "r"(b[0]), "r"(b[1]));
}

// Fragment compute, 128x128 block (8 warps 2m x 4n, warp 64x32).
// As: u32[128][12], k-pairs (kp = k/2 in [0,8)). Bs: u32[8][136], [kp][n].
__device__ __forceinline__ void comp128(
        const u32 (*As)[12], const u32 (*Bs)[136],
        int wm, int wn, int g, int tg, float (&acc)[4][4][4]) {
    u32 a[4][4], b[4][2];
#pragma unroll
    for (int mf = 0; mf < 4; mf++) {
        int m = wm*64 + mf*16 + g;
        a[mf][0] = As[m    ][tg];     a[mf][1] = As[m + 8][tg];
        a[mf][2] = As[m    ][tg + 4]; a[mf][3] = As[m + 8][tg + 4];
    }
#pragma unroll
    for (int nf = 0; nf < 4; nf++) {
        int n = wn*32 + nf*8 + g;
        b[nf][0] = Bs[tg][n]; b[nf][1] = Bs[tg + 4][n];
    }
#pragma unroll
    for (int mf = 0; mf < 4; mf++)
#pragma unroll
        for (int nf = 0; nf < 4; nf++)
            mma16(acc[mf][nf], a[mf], b[nf]);
}

// Fragment compute, 128x64 block (8 warps 4m x 2n, warp 32x32). Bs u32[8][72].
__device__ __forceinline__ void comp64(
        const u32 (*As)[12], const u32 (*Bs)[72],
        int wm, int wn, int g, int tg, float (&acc)[2][4][4]) {
    u32 a[2][4], b[4][2];
#pragma unroll
    for (int mf = 0; mf < 2; mf++) {
        int m = wm*32 + mf*16 + g;
        a[mf][0] = As[m    ][tg];     a[mf][1] = As[m + 8][tg];
        a[mf][2] = As[m    ][tg + 4]; a[mf][3] = As[m + 8][tg + 4];
    }
#pragma unroll
    for (int nf = 0; nf < 4; nf++) {
        int n = wn*32 + nf*8 + g;
        b[nf][0] = Bs[tg][n]; b[nf][1] = Bs[tg + 4][n];
    }
#pragma unroll
    for (int mf = 0; mf < 2; mf++)
#pragma unroll
        for (int nf = 0; nf < 4; nf++)
            mma16(acc[mf][nf], a[mf], b[nf]);
}

// ===================== k_proj: C(bf16) = A(f32) @ W(f32)^T + bias ===========
__global__ __launch_bounds__(256) void k_proj(
        const float* __restrict__ A, int lda,
        const float* __restrict__ W, int ldb,
        const float* __restrict__ bias,
        bf16* __restrict__ C, int ldc, int K)
{
    __shared__ u32 As[2][128][12];
    __shared__ u32 Bs[2][8][136];
    const int tid = threadIdx.x, lane = tid & 31, w = tid >> 5;
    const int wm = w & 1, wn = w >> 1, g = lane >> 2, tg = lane & 3;
    const int m0 = blockIdx.y * 128, n0 = blockIdx.x * 128;
    const int r  = tid >> 2, kq = (tid & 3) * 4, kp0 = (tid & 3) * 2;
    const float* A0 = A + (size_t)(m0 + r     )*lda + kq;
    const float* A1 = A + (size_t)(m0 + r + 64)*lda + kq;
    const float* W0 = W + (size_t)(n0 + r     )*ldb + kq;
    const float* W1 = W + (size_t)(n0 + r + 64)*ldb + kq;
    float acc[4][4][4] = {};
    float4 pa0, pa1, pb0, pb1;
    pa0 = *(const float4*)A0; pa1 = *(const float4*)A1;
    pb0 = *(const float4*)W0; pb1 = *(const float4*)W1;
    int s = 0;
    {
        *(uint2*)&As[0][r     ][kp0] = make_uint2(pk(pa0.x,pa0.y), pk(pa0.z,pa0.w));
        *(uint2*)&As[0][r + 64][kp0] = make_uint2(pk(pa1.x,pa1.y), pk(pa1.z,pa1.w));
        Bs[0][kp0  ][r     ] = pk(pb0.x,pb0.y);  Bs[0][kp0+1][r     ] = pk(pb0.z,pb0.w);
        Bs[0][kp0  ][r + 64] = pk(pb1.x,pb1.y);  Bs[0][kp0+1][r + 64] = pk(pb1.z,pb1.w);
    }
    __syncthreads();
    for (int k0 = 0;;) {
        const int kn = k0 + 16;
        const bool more = kn < K;
        if (more) {
            pa0 = *(const float4*)(A0 + kn); pa1 = *(const float4*)(A1 + kn);
            pb0 = *(const float4*)(W0 + kn); pb1 = *(const float4*)(W1 + kn);
        }
        comp128(As[s], Bs[s], wm, wn, g, tg, acc);
        if (!more) break;
        const int t = s ^ 1;
        *(uint2*)&As[t][r     ][kp0] = make_uint2(pk(pa0.x,pa0.y), pk(pa0.z,pa0.w));
        *(uint2*)&As[t][r + 64][kp0] = make_uint2(pk(pa1.x,pa1.y), pk(pa1.z,pa1.w));
        Bs[t][kp0  ][r     ] = pk(pb0.x,pb0.y);  Bs[t][kp0+1][r     ] = pk(pb0.z,pb0.w);
        Bs[t][kp0  ][r + 64] = pk(pb1.x,pb1.y);  Bs[t][kp0+1][r + 64] = pk(pb1.z,pb1.w);
        __syncthreads();
        s = t; k0 = kn;
    }
#pragma unroll
    for (int mf = 0; mf < 4; mf++) {
        int row = m0 + wm*64 + mf*16 + g;
#pragma unroll
        for (int nf = 0; nf < 4; nf++) {
            int col = n0 + wn*32 + nf*8 + tg*2;
            float2 bv = *(const float2*)(bias + col);
            *(u32*)(C + (size_t)row*ldc + col) =
                pk(acc[mf][nf][0] + bv.x, acc[mf][nf][1] + bv.y);
            *(u32*)(C + (size_t)(row+8)*ldc + col) =
                pk(acc[mf][nf][2] + bv.x, acc[mf][nf][3] + bv.y);
        }
    }
}

// ===================== k_nn_w: C(bf16) = A(f32)[M,K] @ B(f32)[K,N] ==========
__global__ __launch_bounds__(256) void k_nn_w(
        const float* __restrict__ A, int lda,
        const float* __restrict__ B, int ldb,
        bf16* __restrict__ C, int ldc, int K)
{
    __shared__ u32 As[2][128][12];
    __shared__ u32 Bs[2][8][136];
    const int tid = threadIdx.x, lane = tid & 31, w = tid >> 5;
    const int wm = w & 1, wn = w >> 1, g = lane >> 2, tg = lane & 3;
    const int m0 = blockIdx.y * 128, n0 = blockIdx.x * 128;
    const int r  = tid >> 2, kq = (tid & 3) * 4, kp0 = (tid & 3) * 2;
    const int kb = tid >> 5, nq = (tid & 31) * 4;
    const float* A0 = A + (size_t)(m0 + r     )*lda + kq;
    const float* A1 = A + (size_t)(m0 + r + 64)*lda + kq;
    const float* Bp = B + n0 + nq;
    float acc[4][4][4] = {};
    float4 pa0, pa1, pb0, pb1;
    pa0 = *(const float4*)A0; pa1 = *(const float4*)A1;
    pb0 = *(const float4*)(Bp + (size_t)(2*kb    )*ldb);
    pb1 = *(const float4*)(Bp + (size_t)(2*kb + 1)*ldb);
    int s = 0;
    {
        *(uint2*)&As[0][r     ][kp0] = make_uint2(pk(pa0.x,pa0.y), pk(pa0.z,pa0.w));
        *(uint2*)&As[0][r + 64][kp0] = make_uint2(pk(pa1.x,pa1.y), pk(pa1.z,pa1.w));
        *(uint4*)&Bs[0][kb][nq] = make_uint4(pk(pb0.x,pb1.x), pk(pb0.y,pb1.y),
                                             pk(pb0.z,pb1.z), pk(pb0.w,pb1.w));
    }
    __syncthreads();
    for (int k0 = 0;;) {
        const int kn = k0 + 16;
        const bool more = kn < K;
        if (more) {
            pa0 = *(const float4*)(A0 + kn); pa1 = *(const float4*)(A1 + kn);
            pb0 = *(const float4*)(Bp + (size_t)(kn + 2*kb    )*ldb);
            pb1 = *(const float4*)(Bp + (size_t)(kn + 2*kb + 1)*ldb);
        }
        comp128(As[s], Bs[s], wm, wn, g, tg, acc);
        if (!more) break;
        const int t = s ^ 1;
        *(uint2*)&As[t][r     ][kp0] = make_uint2(pk(pa0.x,pa0.y), pk(pa0.z,pa0.w));
        *(uint2*)&As[t][r + 64][kp0] = make_uint2(pk(pa1.x,pa1.y), pk(pa1.z,pa1.w));
        *(uint4*)&Bs[t][kb][nq] = make_uint4(pk(pb0.x,pb1.x), pk(pb0.y,pb1.y),
                                             pk(pb0.z,pb1.z), pk(pb0.w,pb1.w));
        __syncthreads();
        s = t; k0 = kn;
    }
#pragma unroll
    for (int mf = 0; mf < 4; mf++) {
        int row = m0 + wm*64 + mf*16 + g;
#pragma unroll
        for (int nf = 0; nf < 4; nf++) {
            int col = n0 + wn*32 + nf*8 + tg*2;
            *(u32*)(C + (size_t)row*ldc + col)     = pk(acc[mf][nf][0], acc[mf][nf][1]);
            *(u32*)(C + (size_t)(row+8)*ldc + col) = pk(acc[mf][nf][2], acc[mf][nf][3]);
        }
    }
}

// ===================== k_qk: scores(f32) = scale * Q(bf16) @ K(bf16)^T ======
__global__ __launch_bounds__(256) void k_qk(
        const bf16* __restrict__ qkv, float* __restrict__ scores,
        int H, int dk, int band, float scale)
{
    const int z = blockIdx.z;
    const int b = z / H, h = z % H;
    const int m0 = blockIdx.y * 128, n0 = blockIdx.x * 128;
    if (band >= 0 && (n0 + 127) < m0 - band) return;
    const bf16* Aq = qkv + (size_t)b*SS*D3 + h*dk + (size_t)m0*D3;
    const bf16* Bk = qkv + (size_t)b*SS*D3 + DD + h*dk + (size_t)n0*D3;
    float* C = scores + (size_t)z*SS*SS;
    __shared__ u32 As[2][128][12];
    __shared__ u32 Bs[2][8][136];
    const int tid = threadIdx.x, lane = tid & 31, w = tid >> 5;
    const int wm = w & 1, wn = w >> 1, g = lane >> 2, tg = lane & 3;
    const int r2 = tid >> 1, hf = tid & 1;
    const bf16* pA = Aq + (size_t)r2*D3 + hf*8;
    const bf16* pB = Bk + (size_t)r2*D3 + hf*8;
    float acc[4][4][4] = {};
    uint4 va = *(const uint4*)pA;
    uint4 vb = *(const uint4*)pB;
    int s = 0;
    {
        *(uint4*)&As[0][r2][hf*4] = va;
        Bs[0][hf*4+0][r2] = vb.x; Bs[0][hf*4+1][r2] = vb.y;
        Bs[0][hf*4+2][r2] = vb.z; Bs[0][hf*4+3][r2] = vb.w;
    }
    __syncthreads();
    for (int k0 = 0;;) {
        const int kn = k0 + 16;
        const bool more = kn < dk;
        if (more) {
            va = *(const uint4*)(pA + kn);
            vb = *(const uint4*)(pB + kn);
        }
        comp128(As[s], Bs[s], wm, wn, g, tg, acc);
        if (!more) break;
        const int t = s ^ 1;
        *(uint4*)&As[t][r2][hf*4] = va;
        Bs[t][hf*4+0][r2] = vb.x; Bs[t][hf*4+1][r2] = vb.y;
        Bs[t][hf*4+2][r2] = vb.z; Bs[t][hf*4+3][r2] = vb.w;
        __syncthreads();
        s = t; k0 = kn;
    }
#pragma unroll
    for (int mf = 0; mf < 4; mf++) {
        int row = m0 + wm*64 + mf*16 + g;
#pragma unroll
        for (int nf = 0; nf < 4; nf++) {
            int col = n0 + wn*32 + nf*8 + tg*2;
            *(float2*)(C + (size_t)row*SS + col) =
                make_float2(acc[mf][nf][0]*scale, acc[mf][nf][1]*scale);
            *(float2*)(C + (size_t)(row+8)*SS + col) =
                make_float2(acc[mf][nf][2]*scale, acc[mf][nf][3]*scale);
        }
    }
}

// ===================== k_pv: ctx(bf16) = P(bf16) @ V(bf16), dk=128 ==========
__global__ __launch_bounds__(256) void k_pv(
        const bf16* __restrict__ probs, const bf16* __restrict__ qkv,
        bf16* __restrict__ ctx_all, int H, int band, int colbase)
{
    const int z = blockIdx.z;
    const int b = z / H, h = z % H;
    const int m0 = blockIdx.y * 128;
    const bf16* A  = probs + (size_t)z*SS*SS + (size_t)m0*SS;
    const bf16* Bv = qkv + (size_t)b*SS*D3 + 2*DD + h*128;
    bf16* C = ctx_all + (size_t)b*SS*D3 + colbase + h*128;
    const int k0start = (band >= 0) ? ((max(0, m0 - band) >> 4) << 4) : 0;
    __shared__ u32 As[2][128][12];
    __shared__ u32 Bs[2][8][136];
    const int tid = threadIdx.x, lane = tid & 31, w = tid >> 5;
    const int wm = w & 1, wn = w >> 1, g = lane >> 2, tg = lane & 3;
    const int r2 = tid >> 1, hf = tid & 1;
    const int kb = tid >> 5, nq = (tid & 31) * 4;
    const bf16* pA = A + (size_t)r2*SS + hf*8;
    float acc[4][4][4] = {};
    uint4 va; uint2 ra, rb;
    va = *(const uint4*)(pA + k0start);
    ra = *(const uint2*)(Bv + (size_t)(k0start + 2*kb    )*D3 + nq);
    rb = *(const uint2*)(Bv + (size_t)(k0start + 2*kb + 1)*D3 + nq);
    int s = 0;
    {
        *(uint4*)&As[0][r2][hf*4] = va;
        *(uint4*)&Bs[0][kb][nq] = make_uint4(
            __byte_perm(ra.x, rb.x, 0x5410), __byte_perm(ra.x, rb.x, 0x7632),
            __byte_perm(ra.y, rb.y, 0x5410), __byte_perm(ra.y, rb.y, 0x7632));
    }
    __syncthreads();
    for (int k0 = k0start;;) {
        const int kn = k0 + 16;
        const bool more = kn < SS;
        if (more) {
            va = *(const uint4*)(pA + kn);
            ra = *(const uint2*)(Bv + (size_t)(kn + 2*kb    )*D3 + nq);
            rb = *(const uint2*)(Bv + (size_t)(kn + 2*kb + 1)*D3 + nq);
        }
        comp128(As[s], Bs[s], wm, wn, g, tg, acc);
        if (!more) break;
        const int t = s ^ 1;
        *(uint4*)&As[t][r2][hf*4] = va;
        *(uint4*)&Bs[t][kb][nq] = make_uint4(
            __byte_perm(ra.x, rb.x, 0x5410), __byte_perm(ra.x, rb.x, 0x7632),
            __byte_perm(ra.y, rb.y, 0x5410), __byte_perm(ra.y, rb.y, 0x7632));
        __syncthreads();
        s = t; k0 = kn;
    }
#pragma unroll
    for (int mf = 0; mf < 4; mf++) {
        int row = m0 + wm*64 + mf*16 + g;
#pragma unroll
        for (int nf = 0; nf < 4; nf++) {
            int col = wn*32 + nf*8 + tg*2;
            *(u32*)(C + (size_t)row*D3 + col)     = pk(acc[mf][nf][0], acc[mf][nf][1]);
            *(u32*)(C + (size_t)(row+8)*D3 + col) = pk(acc[mf][nf][2], acc[mf][nf][3]);
        }
    }
}

// ===================== k_pv64: ctx(bf16) = P @ V, dk=64 (long branch) =======
__global__ __launch_bounds__(256) void k_pv64(
        const bf16* __restrict__ probs, const bf16* __restrict__ qkv,
        bf16* __restrict__ ctx_all, int colbase)
{
    const int z = blockIdx.z;            // BB*16
    const int b = z >> 4, h = z & 15;
    const int m0 = blockIdx.y * 128;
    const bf16* A  = probs + (size_t)z*SS*SS + (size_t)m0*SS;
    const bf16* Bv = qkv + (size_t)b*SS*D3 + 2*DD + h*64;
    bf16* C = ctx_all + (size_t)b*SS*D3 + colbase + h*64;
    __shared__ u32 As[2][128][12];
    __shared__ u32 Bs[2][8][72];
    const int tid = threadIdx.x, lane = tid & 31, w = tid >> 5;
    const int wm = w & 3, wn = w >> 2, g = lane >> 2, tg = lane & 3;
    const int r2 = tid >> 1, hf = tid & 1;
    const int kb = tid >> 5, nq = (tid & 31) * 2;
    const bf16* pA = A + (size_t)r2*SS + hf*8;
    float acc[2][4][4] = {};
    uint4 va; u32 ra, rb;
    va = *(const uint4*)pA;
    ra = *(const u32*)(Bv + (size_t)(2*kb    )*D3 + nq);
    rb = *(const u32*)(Bv + (size_t)(2*kb + 1)*D3 + nq);
    int s = 0;
    {
        *(uint4*)&As[0][r2][hf*4] = va;
        *(uint2*)&Bs[0][kb][nq] = make_uint2(__byte_perm(ra, rb, 0x5410),
                                             __byte_perm(ra, rb, 0x7632));
    }
    __syncthreads();
    for (int k0 = 0;;) {
        const int kn = k0 + 16;
        const bool more = kn < SS;
        if (more) {
            va = *(const uint4*)(pA + kn);
            ra = *(const u32*)(Bv + (size_t)(kn + 2*kb    )*D3 + nq);
            rb = *(const u32*)(Bv + (size_t)(kn + 2*kb + 1)*D3 + nq);
        }
        comp64(As[s], Bs[s], wm, wn, g, tg, acc);
        if (!more) break;
        const int t = s ^ 1;
        *(uint4*)&As[t][r2][hf*4] = va;
        *(uint2*)&Bs[t][kb][nq] = make_uint2(__byte_perm(ra, rb, 0x5410),
                                             __byte_perm(ra, rb, 0x7632));
        __syncthreads();
        s = t; k0 = kn;
    }
#pragma unroll
    for (int mf = 0; mf < 2; mf++) {
        int row = m0 + wm*32 + mf*16 + g;
#pragma unroll
        for (int nf = 0; nf < 4; nf++) {
            int col = wn*32 + nf*8 + tg*2;
            *(u32*)(C + (size_t)row*D3 + col)     = pk(acc[mf][nf][0], acc[mf][nf][1]);
            *(u32*)(C + (size_t)(row+8)*D3 + col) = pk(acc[mf][nf][2], acc[mf][nf][3]);
        }
    }
}

// ===================== k_comb: C(f32) = ctx(bf16) @ Mall(bf16)^T + bias =====
__global__ __launch_bounds__(256) void k_comb(
        const bf16* __restrict__ A, int lda,
        const bf16* __restrict__ W, int ldb,
        const float* __restrict__ bias,
        float* __restrict__ C, int ldc, int K)
{
    __shared__ u32 As[2][128][12];
    __shared__ u32 Bs[2][8][136];
    const int tid = threadIdx.x, lane = tid & 31, w = tid >> 5;
    const int wm = w & 1, wn = w >> 1, g = lane >> 2, tg = lane & 3;
    const int m0 = blockIdx.y * 128, n0 = blockIdx.x * 128;
    const int r2 = tid >> 1, hf = tid & 1;
    const bf16* pA = A + (size_t)(m0 + r2)*lda + hf*8;
    const bf16* pB = W + (size_t)(n0 + r2)*ldb + hf*8;
    float acc[4][4][4] = {};
    uint4 va = *(const uint4*)pA;
    uint4 vb = *(const uint4*)pB;
    int s = 0;
    {
        *(uint4*)&As[0][r2][hf*4] = va;
        Bs[0][hf*4+0][r2] = vb.x; Bs[0][hf*4+1][r2] = vb.y;
        Bs[0][hf*4+2][r2] = vb.z; Bs[0][hf*4+3][r2] = vb.w;
    }
    __syncthreads();
    for (int k0 = 0;;) {
        const int kn = k0 + 16;
        const bool more = kn < K;
        if (more) {
            va = *(const uint4*)(pA + kn);
            vb = *(const uint4*)(pB + kn);
        }
        comp128(As[s], Bs[s], wm, wn, g, tg, acc);
        if (!more) break;
        const int t = s ^ 1;
        *(uint4*)&As[t][r2][hf*4] = va;
        Bs[t][hf*4+0][r2] = vb.x; Bs[t][hf*4+1][r2] = vb.y;
        Bs[t][hf*4+2][r2] = vb.z; Bs[t][hf*4+3][r2] = vb.w;
        __syncthreads();
        s = t; k0 = kn;
    }
#pragma unroll
    for (int mf = 0; mf < 4; mf++) {
        int row = m0 + wm*64 + mf*16 + g;
#pragma unroll
        for (int nf = 0; nf < 4; nf++) {
            int col = n0 + wn*32 + nf*8 + tg*2;
            float2 bv = *(const float2*)(bias + col);
            *(float2*)(C + (size_t)row*ldc + col) =
                make_float2(acc[mf][nf][0] + bv.x, acc[mf][nf][1] + bv.y);
            *(float2*)(C + (size_t)(row+8)*ldc + col) =
                make_float2(acc[mf][nf][2] + bv.x, acc[mf][nf][3] + bv.y);
        }
    }
}

// ===================== softmax (short/medium): f32 scores -> bf16 probs =====
// Loads/writes start at the band-allowed window minus PV's k-tile slack (144),
// writing zeros in the slack so PV's k-skip never reads stale probs.
__global__ __launch_bounds__(256) void softmax_sm(
        const float* __restrict__ scores, bf16* __restrict__ probs, int band)
{
    __shared__ float srow[SS];
    __shared__ float redA[8];
    __shared__ float redB[8];
    const int rid = blockIdx.x;
    const int i = rid % SS;
    const float* row = scores + (size_t)rid * SS;
    u32* prow = (u32*)(probs + (size_t)rid * SS);
    const int jstart = max(0, i - band);
    const int g0 = max(0, jstart - 144) >> 2;
    const int t = threadIdx.x;
    float lmax = -1e30f;
    for (int g = g0 + t; g < SS/4; g += 256) {
        float4 v = ((const float4*)row)[g];
        int j = g*4;
        float v0 = (j+0 >= jstart) ? v.x : -1e30f;
        float v1 = (j+1 >= jstart) ? v.y : -1e30f;
        float v2 = (j+2 >= jstart) ? v.z : -1e30f;
        float v3 = (j+3 >= jstart) ? v.w : -1e30f;
        ((float4*)srow)[g] = make_float4(v0, v1, v2, v3);
        lmax = fmaxf(fmaxf(fmaxf(v0, v1), v2), fmaxf(v3, lmax));
    }
#pragma unroll
    for (int o = 16; o; o >>= 1) lmax = fmaxf(lmax, __shfl_xor_sync(0xffffffffu, lmax, o));
    if ((t & 31) == 0) redA[t >> 5] = lmax;
    __syncthreads();
    float m = redA[0];
#pragma unroll
    for (int ww = 1; ww < 8; ww++) m = fmaxf(m, redA[ww]);
    float lsum = 0.f;
    for (int g = g0 + t; g < SS/4; g += 256) {
        float4 v = ((const float4*)srow)[g];
        float e0 = (v.x > -1e29f) ? __expf(v.x - m) : 0.f;
        float e1 = (v.y > -1e29f) ? __expf(v.y - m) : 0.f;
        float e2 = (v.z > -1e29f) ? __expf(v.z - m) : 0.f;
        float e3 = (v.w > -1e29f) ? __expf(v.w - m) : 0.f;
        ((float4*)srow)[g] = make_float4(e0, e1, e2, e3);
        lsum += e0 + e1 + e2 + e3;
    }
#pragma unroll
    for (int o = 16; o; o >>= 1) lsum += __shfl_xor_sync(0xffffffffu, lsum, o);
    if ((t & 31) == 0) redB[t >> 5] = lsum;
    __syncthreads();
    float ssum = 0.f;
#pragma unroll
    for (int ww = 0; ww < 8; ww++) ssum += redB[ww];
    const float inv = 1.f / ssum;
    for (int g = g0 + t; g < SS/4; g += 256) {
        float4 v = ((const float4*)srow)[g];
        *(uint2*)(prow + g*2) = make_uint2(pk(v.x*inv, v.y*inv), pk(v.z*inv, v.w*inv));
    }
}

// ===================== softmax (long) + head mean fused =====================
// One block per (b, i): softmax 16 head-rows (f32 in, bf16 out) and write the
// f32 head-mean row directly to the attn_weights output.
__global__ __launch_bounds__(256) void softmax_long(
        const float* __restrict__ scores, bf16* __restrict__ probs,
        float* __restrict__ mean_out)
{
    __shared__ float srow[SS];
    __shared__ float smean[SS];
    __shared__ float redA[8];
    __shared__ float redB[8];
    const int b = blockIdx.x / SS, i = blockIdx.x % SS;
    const int t = threadIdx.x;
    for (int g = t; g < SS/4; g += 256)
        ((float4*)smean)[g] = make_float4(0.f, 0.f, 0.f, 0.f);
    __syncthreads();
    for (int h = 0; h < 16; h++) {
        const float* row = scores + ((size_t)(b*16 + h)*SS + i)*SS;
        u32* prow = (u32*)(probs + ((size_t)(b*16 + h)*SS + i)*SS);
        float lmax = -1e30f;
        for (int g = t; g < SS/4; g += 256) {
            float4 v = ((const float4*)row)[g];
            ((float4*)srow)[g] = v;
            lmax = fmaxf(fmaxf(fmaxf(v.x, v.y), v.z), fmaxf(v.w, lmax));
        }
#pragma unroll
        for (int o = 16; o; o >>= 1) lmax = fmaxf(lmax, __shfl_xor_sync(0xffffffffu, lmax, o));
        if ((t & 31) == 0) redA[t >> 5] = lmax;
        __syncthreads();
        float m = redA[0];
#pragma unroll
        for (int ww = 1; ww < 8; ww++) m = fmaxf(m, redA[ww]);
        float lsum = 0.f;
        for (int g = t; g < SS/4; g += 256) {
            float4 v = ((const float4*)srow)[g];
            float4 e = make_float4(__expf(v.x - m), __expf(v.y - m),
                                   __expf(v.z - m), __expf(v.w - m));
            ((float4*)srow)[g] = e;
            lsum += e.x + e.y + e.z + e.w;
        }
#pragma unroll
        for (int o = 16; o; o >>= 1) lsum += __shfl_xor_sync(0xffffffffu, lsum, o);
        if ((t & 31) == 0) redB[t >> 5] = lsum;
        __syncthreads();
        float ssum = 0.f;
#pragma unroll
        for (int ww = 0; ww < 8; ww++) ssum += redB[ww];
        const float inv = 1.f / ssum;
        for (int g = t; g < SS/4; g += 256) {
            float4 v = ((const float4*)srow)[g];
            float4 p = make_float4(v.x*inv, v.y*inv, v.z*inv, v.w*inv);
            float4 mm = ((float4*)smean)[g];
            ((float4*)smean)[g] = make_float4(mm.x+p.x, mm.y+p.y, mm.z+p.z, mm.w+p.w);
            *(uint2*)(prow + g*2) = make_uint2(pk(p.x, p.y), pk(p.z, p.w));
        }
        __syncthreads();
    }
    if (mean_out) {
        float* mrow = mean_out + (size_t)blockIdx.x * SS;
        for (int g = t; g < SS/4; g += 256) {
            float4 mm = ((float4*)smean)[g];
            ((float4*)mrow)[g] = make_float4(mm.x*(1.f/16.f), mm.y*(1.f/16.f),
                                             mm.z*(1.f/16.f), mm.w*(1.f/16.f));
        }
    }
}

// ===================== fused bias: b_comb + w_comb @ [bo_s;bo_m;bo_l] =======
__global__ void bias_comb(const float* __restrict__ w_comb,
                          const float* __restrict__ b_comb,
                          const float* __restrict__ bo_s,
                          const float* __restrict__ bo_m,
                          const float* __restrict__ bo_l,
                          float* __restrict__ bias_total) {
    const int p = blockIdx.x;
    __shared__ float red[256];
    float s = 0.f;
    for (int q = threadIdx.x; q < D3; q += 256) {
        float bo = (q < DD) ? bo_s[q] : (q < 2*DD) ? bo_m[q - DD] : bo_l[q - 2*DD];
        s += w_comb[(size_t)p*D3 + q] * bo;
    }
    red[threadIdx.x] = s; __syncthreads();
    for (int k = 128; k > 0; k >>= 1) {
        if (threadIdx.x < k) red[threadIdx.x] += red[threadIdx.x + k];
        __syncthreads();
    }
    if (threadIdx.x == 0) bias_total[p] = red[0] + b_comb[p];
}

// ===================== residual + layernorm (vectorized) ====================
__global__ __launch_bounds__(256) void ln_kernel(
        const float* __restrict__ y, const float* __restrict__ x,
        const float* __restrict__ gamma, const float* __restrict__ beta,
        float* __restrict__ out) {
    const int row = blockIdx.x;
    __shared__ float redA[8];
    __shared__ float redB[8];
    const int t = threadIdx.x;
    const float4* yr = (const float4*)(y + (size_t)row*DD);
    const float4* xr = (const float4*)(x + (size_t)row*DD);
    float4 yv = yr[t], xv = xr[t];
    float4 v = make_float4(yv.x+xv.x, yv.y+xv.y, yv.z+xv.z, yv.w+xv.w);
    float s  = v.x + v.y + v.z + v.w;
    float s2 = v.x*v.x + v.y*v.y + v.z*v.z + v.w*v.w;
#pragma unroll
    for (int o = 16; o; o >>= 1) {
        s  += __shfl_xor_sync(0xffffffffu, s,  o);
        s2 += __shfl_xor_sync(0xffffffffu, s2, o);
    }
    if ((t & 31) == 0) { redA[t >> 5] = s; redB[t >> 5] = s2; }
    __syncthreads();
    float ts = 0.f, ts2 = 0.f;
#pragma unroll
    for (int ww = 0; ww < 8; ww++) { ts += redA[ww]; ts2 += redB[ww]; }
    const float mu  = ts * (1.f/DD);
    const float var = ts2 * (1.f/DD) - mu*mu;
    const float rs  = rsqrtf(var + 1e-5f);
    const float4 g4 = ((const float4*)gamma)[t];
    const float4 b4 = ((const float4*)beta)[t];
    ((float4*)(out + (size_t)row*DD))[t] = make_float4(
        (v.x - mu)*rs*g4.x + b4.x, (v.y - mu)*rs*g4.y + b4.y,
        (v.z - mu)*rs*g4.z + b4.z, (v.w - mu)*rs*g4.w + b4.w);
}

// ===================== orchestration ========================================
extern "C" void kernel_launch(void* const* d_in, const int* in_sizes, int n_in,
                              void* d_out, int out_size) {
    const float* x      = (const float*)d_in[0];
    const float* w_in_s = (const float*)d_in[1];
    const float* b_in_s = (const float*)d_in[2];
    const float* wo_s   = (const float*)d_in[3];
    const float* bo_s   = (const float*)d_in[4];
    const float* w_in_m = (const float*)d_in[5];
    const float* b_in_m = (const float*)d_in[6];
    const float* wo_m   = (const float*)d_in[7];
    const float* bo_m   = (const float*)d_in[8];
    const float* w_in_l = (const float*)d_in[9];
    const float* b_in_l = (const float*)d_in[10];
    const float* wo_l   = (const float*)d_in[11];
    const float* bo_l   = (const float*)d_in[12];
    const float* w_comb = (const float*)d_in[13];
    const float* b_comb = (const float*)d_in[14];
    const float* gamma  = (const float*)d_in[15];
    const float* beta   = (const float*)d_in[16];
    float* out = (float*)d_out;

    bf16 *qkv_s, *qkv_m, *qkv_l, *probs, *ctx, *Mall;
    float *scores, *biasT, *comb_out;
    cudaGetSymbolAddress((void**)&qkv_s,    g_qkv_s);
    cudaGetSymbolAddress((void**)&qkv_m,    g_qkv_m);
    cudaGetSymbolAddress((void**)&qkv_l,    g_qkv_l);
    cudaGetSymbolAddress((void**)&scores,   g_scores);
    cudaGetSymbolAddress((void**)&probs,    g_probs);
    cudaGetSymbolAddress((void**)&ctx,      g_ctx);
    cudaGetSymbolAddress((void**)&Mall,     g_Mall);
    cudaGetSymbolAddress((void**)&biasT,    g_bias);
    cudaGetSymbolAddress((void**)&comb_out, g_comb_out);

    // ---- fused weights: Mall_b = w_comb[:, bD:(b+1)D] @ wo_b (bf16 out) ----
    {
        dim3 g(DD/128, DD/128);
        k_nn_w<<<g, 256>>>(w_comb + 0*DD, D3, wo_s, DD, Mall + 0*DD, D3, DD);
        k_nn_w<<<g, 256>>>(w_comb + 1*DD, D3, wo_m, DD, Mall + 1*DD, D3, DD);
        k_nn_w<<<g, 256>>>(w_comb + 2*DD, D3, wo_l, DD, Mall + 2*DD, D3, DD);
        bias_comb<<<DD, 256>>>(w_comb, b_comb, bo_s, bo_m, bo_l, biasT);
    }

    // ---- QKV projections (bf16 out) ----
    dim3 gqkv(D3/128, BS/128);
    k_proj<<<gqkv, 256>>>(x, DD, w_in_s, DD, b_in_s, qkv_s, D3, DD);
    k_proj<<<gqkv, 256>>>(x, DD, w_in_m, DD, b_in_m, qkv_m, D3, DD);
    k_proj<<<gqkv, 256>>>(x, DD, w_in_l, DD, b_in_l, qkv_l, D3, DD);

    const float sc128 = 1.f / sqrtf(128.f);
    const float sc64  = 1.f / sqrtf(64.f);

    // ---- short branch: H=8, dk=128, band=10 ----
    {
        dim3 gqk(SS/128, SS/128, BB*8);
        k_qk<<<gqk, 256>>>(qkv_s, scores, 8, 128, 10, sc128);
        softmax_sm<<<BB*8*SS, 256>>>(scores, probs, 10);
        dim3 gpv(1, SS/128, BB*8);
        k_pv<<<gpv, 256>>>(probs, qkv_s, ctx, 8, 10, 0);
    }
    // ---- medium branch: H=8, dk=128, band=30 ----
    {
        dim3 gqk(SS/128, SS/128, BB*8);
        k_qk<<<gqk, 256>>>(qkv_m, scores, 8, 128, 30, sc128);
        softmax_sm<<<BB*8*SS, 256>>>(scores, probs, 30);
        dim3 gpv(1, SS/128, BB*8);
        k_pv<<<gpv, 256>>>(probs, qkv_m, ctx, 8, 30, DD);
    }
    // ---- long branch: H=16, dk=64, no band; fused softmax+mean ----
    {
        dim3 gqk(SS/128, SS/128, BB*16);
        k_qk<<<gqk, 256>>>(qkv_l, scores, 16, 64, -1, sc64);
        float* mean_out = ((size_t)out_size >= BSD + BSS) ? (out + BSD) : nullptr;
        softmax_long<<<BB*SS, 256>>>(scores, probs, mean_out);
        dim3 gpv(1, SS/128, BB*16);
        k_pv64<<<gpv, 256>>>(probs, qkv_l, ctx, 2*DD);
    }

    // ---- fused output: comb_out = ctx_all(bf16) @ Mall(bf16)^T + biasT ----
    dim3 gc(DD/128, BS/128);
    k_comb<<<gc, 256>>>(ctx, D3, Mall, D3, biasT, comb_out, DD, D3);

    // ---- residual + LN ----
    ln_kernel<<<BS, 256>>>(comb_out, x, gamma, beta, out);
}

// round 9
// speedup vs baseline: 5.0245x; 1.0177x over previous
#include <cuda_runtime.h>
#include <cuda_bf16.h>
#include <math.h>

// Problem constants
#define BB 2
#define SS 2048
#define DD 1024
#define D3 (3*DD)
#define BS (BB*SS)             // 4096
#define BSD ((size_t)BS*DD)    // 4,194,304
#define BSS ((size_t)BB*SS*SS) // 8,388,608

typedef unsigned u32;
typedef __nv_bfloat16 bf16;

// ----------------- scratch buffers (static device globals; no allocs) ------
__device__ bf16  g_xb   [(size_t)BS*DD];          // x in bf16
__device__ bf16  g_win_s[(size_t)D3*DD];          // w_in_* in bf16
__device__ bf16  g_win_m[(size_t)D3*DD];
__device__ bf16  g_win_l[(size_t)D3*DD];
__device__ bf16  g_qkv_s[(size_t)BS*D3];
__device__ bf16  g_qkv_m[(size_t)BS*D3];
__device__ bf16  g_qkv_l[(size_t)BS*D3];
__device__ float g_scores[(size_t)BB*16*SS*SS];   // f32 scores (long-branch sized)
__device__ bf16  g_probs [(size_t)BB*16*SS*SS];   // bf16 probs
__device__ bf16  g_ctx[(size_t)BS*D3];            // concatenated ctx (s|m|l), bf16
__device__ bf16  g_Mall[(size_t)DD*D3];           // fused wo∘w_comb weights, bf16
__device__ float g_bias[DD];
__device__ float g_comb_out[(size_t)BS*DD];

// ===================== helpers ==============================================
__device__ __forceinline__ u32 pk(float lo, float hi) {
    __nv_bfloat162 h = __floats2bfloat162_rn(lo, hi);
    return *reinterpret_cast<u32*>(&h);
}
__device__ __forceinline__ void mma16(float c[4], const u32 a[4], const u32 b[2]) {
    asm volatile(
        "mma.sync.aligned.m16n8k16.row.col.f32.bf16.bf16.f32 "
        "{%0,%1,%2,%3}, {%4,%5,%6,%7}, {%8,%9}, {%0,%1,%2,%3};"
        : "+f"(c[0]), "+f"(c[1]), "+f"(c[2]), "+f"(c[3])
        : "r"(a[0]), "r"(a[1]), "r"(a[2]), "r"(a[3]), "r"(b[0]), "r"(b[1]));
}
__device__ __forceinline__ u32 smem_addr(const void* p) {
    return (u32)__cvta_generic_to_shared(p);
}
__device__ __forceinline__ void cpa16(u32 dst, const void* src) {
    asm volatile("cp.async.ca.shared.global [%0], [%1], 16;" :: "r"(dst), "l"(src));
}

// ---- fragment compute, old layouts (kept for PV / f32-weight kernels) ------
// As: u32[128][12] ([row][kpair]); Bs: u32[8][136] ([kpair][n]).
__device__ __forceinline__ void comp128(
        const u32 (*As)[12], const u32 (*Bs)[136],
        int wm, int wn, int g, int tg, float (&acc)[4][4][4]) {
    u32 a[4][4], b[4][2];
#pragma unroll
    for (int mf = 0; mf < 4; mf++) {
        int m = wm*64 + mf*16 + g;
        a[mf][0] = As[m    ][tg];     a[mf][1] = As[m + 8][tg];
        a[mf][2] = As[m    ][tg + 4]; a[mf][3] = As[m + 8][tg + 4];
    }
#pragma unroll
    for (int nf = 0; nf < 4; nf++) {
        int n = wn*32 + nf*8 + g;
        b[nf][0] = Bs[tg][n]; b[nf][1] = Bs[tg + 4][n];
    }
#pragma unroll
    for (int mf = 0; mf < 4; mf++)
#pragma unroll
        for (int nf = 0; nf < 4; nf++)
            mma16(acc[mf][nf], a[mf], b[nf]);
}
__device__ __forceinline__ void comp64(
        const u32 (*As)[12], const u32 (*Bs)[72],
        int wm, int wn, int g, int tg, float (&acc)[2][4][4]) {
    u32 a[2][4], b[4][2];
#pragma unroll
    for (int mf = 0; mf < 2; mf++) {
        int m = wm*32 + mf*16 + g;
        a[mf][0] = As[m    ][tg];     a[mf][1] = As[m + 8][tg];
        a[mf][2] = As[m    ][tg + 4]; a[mf][3] = As[m + 8][tg + 4];
    }
#pragma unroll
    for (int nf = 0; nf < 4; nf++) {
        int n = wn*32 + nf*8 + g;
        b[nf][0] = Bs[tg][n]; b[nf][1] = Bs[tg + 4][n];
    }
#pragma unroll
    for (int mf = 0; mf < 2; mf++)
#pragma unroll
        for (int nf = 0; nf < 4; nf++)
            mma16(acc[mf][nf], a[mf], b[nf]);
}

// ---- fragment compute, NT pipeline layout: BOTH As and Bs are [row][kpair] -
__device__ __forceinline__ void comp128b(
        const u32 (*As)[12], const u32 (*Bs)[12],
        int wm, int wn, int g, int tg, float (&acc)[4][4][4]) {
    u32 a[4][4], b[4][2];
#pragma unroll
    for (int mf = 0; mf < 4; mf++) {
        int m = wm*64 + mf*16 + g;
        a[mf][0] = As[m    ][tg];     a[mf][1] = As[m + 8][tg];
        a[mf][2] = As[m    ][tg + 4]; a[mf][3] = As[m + 8][tg + 4];
    }
#pragma unroll
    for (int nf = 0; nf < 4; nf++) {
        int n = wn*32 + nf*8 + g;
        b[nf][0] = Bs[n][tg]; b[nf][1] = Bs[n][tg + 4];
    }
#pragma unroll
    for (int mf = 0; mf < 4; mf++)
#pragma unroll
        for (int nf = 0; nf < 4; nf++)
            mma16(acc[mf][nf], a[mf], b[nf]);
}

// ===================== NT core: 3-stage cp.async pipeline ===================
// A: bf16 [.,K] k-contig, block rows m0 pre-applied; B: bf16 [.,K] k-contig,
// block rows n0 pre-applied. K multiple of 16, K >= 64.
#define NT_CORE(A_, lda_, B_, ldb_, K_, acc_)                                   \
    __shared__ u32 As[3][128][12];                                              \
    __shared__ u32 Bs[3][128][12];                                              \
    const int tid = threadIdx.x, lane = tid & 31, w = tid >> 5;                 \
    const int wm = w & 1, wn = w >> 1, g = lane >> 2, tg = lane & 3;            \
    {                                                                           \
        const int r = tid >> 1, hf = tid & 1;                                   \
        const bf16* pA = (A_) + (size_t)r*(lda_) + hf*8;                        \
        const bf16* pB = (B_) + (size_t)r*(ldb_) + hf*8;                        \
        const u32 dA = smem_addr(&As[0][r][hf*4]);                              \
        const u32 dB = smem_addr(&Bs[0][r][hf*4]);                              \
        const int nIter = (K_) >> 4;                                            \
        cpa16(dA, pA);            cpa16(dB, pB);                                \
        asm volatile("cp.async.commit_group;");                                 \
        cpa16(dA + 6144, pA + 16); cpa16(dB + 6144, pB + 16);                   \
        asm volatile("cp.async.commit_group;");                                 \
        int s = 0;                                                              \
        for (int it = 0; it < nIter; ++it) {                                    \
            asm volatile("cp.async.wait_group 1;");                             \
            __syncthreads();                                                    \
            if (it + 2 < nIter) {                                               \
                int sp = s + 2; if (sp >= 3) sp -= 3;                           \
                cpa16(dA + sp*6144, pA + (size_t)(it+2)*16);                    \
                cpa16(dB + sp*6144, pB + (size_t)(it+2)*16);                    \
            }                                                                   \
            asm volatile("cp.async.commit_group;");                             \
            comp128b(As[s], Bs[s], wm, wn, g, tg, acc_);                        \
            s = (s == 2) ? 0 : s + 1;                                           \
        }                                                                       \
    }

// ===================== k_proj: C(bf16) = A(bf16) @ W(bf16)^T + bias =========
__global__ __launch_bounds__(256) void k_proj(
        const bf16* __restrict__ A, int lda,
        const bf16* __restrict__ W, int ldb,
        const float* __restrict__ bias,
        bf16* __restrict__ C, int ldc, int K)
{
    const int m0 = blockIdx.y * 128, n0 = blockIdx.x * 128;
    float acc[4][4][4] = {};
    NT_CORE(A + (size_t)m0*lda, lda, W + (size_t)n0*ldb, ldb, K, acc)
#pragma unroll
    for (int mf = 0; mf < 4; mf++) {
        int row = m0 + wm*64 + mf*16 + g;
#pragma unroll
        for (int nf = 0; nf < 4; nf++) {
            int col = n0 + wn*32 + nf*8 + tg*2;
            float2 bv = *(const float2*)(bias + col);
            *(u32*)(C + (size_t)row*ldc + col) =
                pk(acc[mf][nf][0] + bv.x, acc[mf][nf][1] + bv.y);
            *(u32*)(C + (size_t)(row+8)*ldc + col) =
                pk(acc[mf][nf][2] + bv.x, acc[mf][nf][3] + bv.y);
        }
    }
}

// ===================== k_qk: scores(f32) = scale * Q @ K^T (band skip) ======
__global__ __launch_bounds__(256) void k_qk(
        const bf16* __restrict__ qkv, float* __restrict__ scores,
        int H, int dk, int band, float scale)
{
    const int z = blockIdx.z;
    const int b = z / H, h = z % H;
    const int m0 = blockIdx.y * 128, n0 = blockIdx.x * 128;
    if (band >= 0 && (n0 + 127) < m0 - band) return;
    const bf16* Aq = qkv + (size_t)b*SS*D3 + h*dk + (size_t)m0*D3;
    const bf16* Bk = qkv + (size_t)b*SS*D3 + DD + h*dk + (size_t)n0*D3;
    float* C = scores + (size_t)z*SS*SS;
    float acc[4][4][4] = {};
    NT_CORE(Aq, D3, Bk, D3, dk, acc)
#pragma unroll
    for (int mf = 0; mf < 4; mf++) {
        int row = m0 + wm*64 + mf*16 + g;
#pragma unroll
        for (int nf = 0; nf < 4; nf++) {
            int col = n0 + wn*32 + nf*8 + tg*2;
            *(float2*)(C + (size_t)row*SS + col) =
                make_float2(acc[mf][nf][0]*scale, acc[mf][nf][1]*scale);
            *(float2*)(C + (size_t)(row+8)*SS + col) =
                make_float2(acc[mf][nf][2]*scale, acc[mf][nf][3]*scale);
        }
    }
}

// ===================== k_comb: C(f32) = ctx(bf16) @ Mall(bf16)^T + bias =====
__global__ __launch_bounds__(256) void k_comb(
        const bf16* __restrict__ A, int lda,
        const bf16* __restrict__ W, int ldb,
        const float* __restrict__ bias,
        float* __restrict__ C, int ldc, int K)
{
    const int m0 = blockIdx.y * 128, n0 = blockIdx.x * 128;
    float acc[4][4][4] = {};
    NT_CORE(A + (size_t)m0*lda, lda, W + (size_t)n0*ldb, ldb, K, acc)
#pragma unroll
    for (int mf = 0; mf < 4; mf++) {
        int row = m0 + wm*64 + mf*16 + g;
#pragma unroll
        for (int nf = 0; nf < 4; nf++) {
            int col = n0 + wn*32 + nf*8 + tg*2;
            float2 bv = *(const float2*)(bias + col);
            *(float2*)(C + (size_t)row*ldc + col) =
                make_float2(acc[mf][nf][0] + bv.x, acc[mf][nf][1] + bv.y);
            *(float2*)(C + (size_t)(row+8)*ldc + col) =
                make_float2(acc[mf][nf][2] + bv.x, acc[mf][nf][3] + bv.y);
        }
    }
}

// ===================== k_nn_w: Mall(bf16) = A(f32)[M,K] @ B(f32)[K,N] =======
// (one-time weight fusion, f32 inputs; unchanged from R8)
__global__ __launch_bounds__(256) void k_nn_w(
        const float* __restrict__ A, int lda,
        const float* __restrict__ B, int ldb,
        bf16* __restrict__ C, int ldc, int K)
{
    __shared__ u32 As[2][128][12];
    __shared__ u32 Bs[2][8][136];
    const int tid = threadIdx.x, lane = tid & 31, w = tid >> 5;
    const int wm = w & 1, wn = w >> 1, g = lane >> 2, tg = lane & 3;
    const int m0 = blockIdx.y * 128, n0 = blockIdx.x * 128;
    const int r  = tid >> 2, kq = (tid & 3) * 4, kp0 = (tid & 3) * 2;
    const int kb = tid >> 5, nq = (tid & 31) * 4;
    const float* A0 = A + (size_t)(m0 + r     )*lda + kq;
    const float* A1 = A + (size_t)(m0 + r + 64)*lda + kq;
    const float* Bp = B + n0 + nq;
    float acc[4][4][4] = {};
    float4 pa0, pa1, pb0, pb1;
    pa0 = *(const float4*)A0; pa1 = *(const float4*)A1;
    pb0 = *(const float4*)(Bp + (size_t)(2*kb    )*ldb);
    pb1 = *(const float4*)(Bp + (size_t)(2*kb + 1)*ldb);
    int s = 0;
    {
        *(uint2*)&As[0][r     ][kp0] = make_uint2(pk(pa0.x,pa0.y), pk(pa0.z,pa0.w));
        *(uint2*)&As[0][r + 64][kp0] = make_uint2(pk(pa1.x,pa1.y), pk(pa1.z,pa1.w));
        *(uint4*)&Bs[0][kb][nq] = make_uint4(pk(pb0.x,pb1.x), pk(pb0.y,pb1.y),
                                             pk(pb0.z,pb1.z), pk(pb0.w,pb1.w));
    }
    __syncthreads();
    for (int k0 = 0;;) {
        const int kn = k0 + 16;
        const bool more = kn < K;
        if (more) {
            pa0 = *(const float4*)(A0 + kn); pa1 = *(const float4*)(A1 + kn);
            pb0 = *(const float4*)(Bp + (size_t)(kn + 2*kb    )*ldb);
            pb1 = *(const float4*)(Bp + (size_t)(kn + 2*kb + 1)*ldb);
        }
        comp128(As[s], Bs[s], wm, wn, g, tg, acc);
        if (!more) break;
        const int t = s ^ 1;
        *(uint2*)&As[t][r     ][kp0] = make_uint2(pk(pa0.x,pa0.y), pk(pa0.z,pa0.w));
        *(uint2*)&As[t][r + 64][kp0] = make_uint2(pk(pa1.x,pa1.y), pk(pa1.z,pa1.w));
        *(uint4*)&Bs[t][kb][nq] = make_uint4(pk(pb0.x,pb1.x), pk(pb0.y,pb1.y),
                                             pk(pb0.z,pb1.z), pk(pb0.w,pb1.w));
        __syncthreads();
        s = t; k0 = kn;
    }
#pragma unroll
    for (int mf = 0; mf < 4; mf++) {
        int row = m0 + wm*64 + mf*16 + g;
#pragma unroll
        for (int nf = 0; nf < 4; nf++) {
            int col = n0 + wn*32 + nf*8 + tg*2;
            *(u32*)(C + (size_t)row*ldc + col)     = pk(acc[mf][nf][0], acc[mf][nf][1]);
            *(u32*)(C + (size_t)(row+8)*ldc + col) = pk(acc[mf][nf][2], acc[mf][nf][3]);
        }
    }
}

// ===================== k_pv: ctx(bf16) = P(bf16) @ V(bf16), dk=128 ==========
__global__ __launch_bounds__(256) void k_pv(
        const bf16* __restrict__ probs, const bf16* __restrict__ qkv,
        bf16* __restrict__ ctx_all, int H, int band, int colbase)
{
    const int z = blockIdx.z;
    const int b = z / H, h = z % H;
    const int m0 = blockIdx.y * 128;
    const bf16* A  = probs + (size_t)z*SS*SS + (size_t)m0*SS;
    const bf16* Bv = qkv + (size_t)b*SS*D3 + 2*DD + h*128;
    bf16* C = ctx_all + (size_t)b*SS*D3 + colbase + h*128;
    const int k0start = (band >= 0) ? ((max(0, m0 - band) >> 4) << 4) : 0;
    __shared__ u32 As[2][128][12];
    __shared__ u32 Bs[2][8][136];
    const int tid = threadIdx.x, lane = tid & 31, w = tid >> 5;
    const int wm = w & 1, wn = w >> 1, g = lane >> 2, tg = lane & 3;
    const int r2 = tid >> 1, hf = tid & 1;
    const int kb = tid >> 5, nq = (tid & 31) * 4;
    const bf16* pA = A + (size_t)r2*SS + hf*8;
    float acc[4][4][4] = {};
    uint4 va; uint2 ra, rb;
    va = *(const uint4*)(pA + k0start);
    ra = *(const uint2*)(Bv + (size_t)(k0start + 2*kb    )*D3 + nq);
    rb = *(const uint2*)(Bv + (size_t)(k0start + 2*kb + 1)*D3 + nq);
    int s = 0;
    {
        *(uint4*)&As[0][r2][hf*4] = va;
        *(uint4*)&Bs[0][kb][nq] = make_uint4(
            __byte_perm(ra.x, rb.x, 0x5410), __byte_perm(ra.x, rb.x, 0x7632),
            __byte_perm(ra.y, rb.y, 0x5410), __byte_perm(ra.y, rb.y, 0x7632));
    }
    __syncthreads();
    for (int k0 = k0start;;) {
        const int kn = k0 + 16;
        const bool more = kn < SS;
        if (more) {
            va = *(const uint4*)(pA + kn);
            ra = *(const uint2*)(Bv + (size_t)(kn + 2*kb    )*D3 + nq);
            rb = *(const uint2*)(Bv + (size_t)(kn + 2*kb + 1)*D3 + nq);
        }
        comp128(As[s], Bs[s], wm, wn, g, tg, acc);
        if (!more) break;
        const int t = s ^ 1;
        *(uint4*)&As[t][r2][hf*4] = va;
        *(uint4*)&Bs[t][kb][nq] = make_uint4(
            __byte_perm(ra.x, rb.x, 0x5410), __byte_perm(ra.x, rb.x, 0x7632),
            __byte_perm(ra.y, rb.y, 0x5410), __byte_perm(ra.y, rb.y, 0x7632));
        __syncthreads();
        s = t; k0 = kn;
    }
#pragma unroll
    for (int mf = 0; mf < 4; mf++) {
        int row = m0 + wm*64 + mf*16 + g;
#pragma unroll
        for (int nf = 0; nf < 4; nf++) {
            int col = wn*32 + nf*8 + tg*2;
            *(u32*)(C + (size_t)row*D3 + col)     = pk(acc[mf][nf][0], acc[mf][nf][1]);
            *(u32*)(C + (size_t)(row+8)*D3 + col) = pk(acc[mf][nf][2], acc[mf][nf][3]);
        }
    }
}

// ===================== k_pv64: ctx(bf16) = P @ V, dk=64 (long branch) =======
__global__ __launch_bounds__(256) void k_pv64(
        const bf16* __restrict__ probs, const bf16* __restrict__ qkv,
        bf16* __restrict__ ctx_all, int colbase)
{
    const int z = blockIdx.z;            // BB*16
    const int b = z >> 4, h = z & 15;
    const int m0 = blockIdx.y * 128;
    const bf16* A  = probs + (size_t)z*SS*SS + (size_t)m0*SS;
    const bf16* Bv = qkv + (size_t)b*SS*D3 + 2*DD + h*64;
    bf16* C = ctx_all + (size_t)b*SS*D3 + colbase + h*64;
    __shared__ u32 As[2][128][12];
    __shared__ u32 Bs[2][8][72];
    const int tid = threadIdx.x, lane = tid & 31, w = tid >> 5;
    const int wm = w & 3, wn = w >> 2, g = lane >> 2, tg = lane & 3;
    const int r2 = tid >> 1, hf = tid & 1;
    const int kb = tid >> 5, nq = (tid & 31) * 2;
    const bf16* pA = A + (size_t)r2*SS + hf*8;
    float acc[2][4][4] = {};
    uint4 va; u32 ra, rb;
    va = *(const uint4*)pA;
    ra = *(const u32*)(Bv + (size_t)(2*kb    )*D3 + nq);
    rb = *(const u32*)(Bv + (size_t)(2*kb + 1)*D3 + nq);
    int s = 0;
    {
        *(uint4*)&As[0][r2][hf*4] = va;
        *(uint2*)&Bs[0][kb][nq] = make_uint2(__byte_perm(ra, rb, 0x5410),
                                             __byte_perm(ra, rb, 0x7632));
    }
    __syncthreads();
    for (int k0 = 0;;) {
        const int kn = k0 + 16;
        const bool more = kn < SS;
        if (more) {
            va = *(const uint4*)(pA + kn);
            ra = *(const u32*)(Bv + (size_t)(kn + 2*kb    )*D3 + nq);
            rb = *(const u32*)(Bv + (size_t)(kn + 2*kb + 1)*D3 + nq);
        }
        comp64(As[s], Bs[s], wm, wn, g, tg, acc);
        if (!more) break;
        const int t = s ^ 1;
        *(uint4*)&As[t][r2][hf*4] = va;
        *(uint2*)&Bs[t][kb][nq] = make_uint2(__byte_perm(ra, rb, 0x5410),
                                             __byte_perm(ra, rb, 0x7632));
        __syncthreads();
        s = t; k0 = kn;
    }
#pragma unroll
    for (int mf = 0; mf < 2; mf++) {
        int row = m0 + wm*32 + mf*16 + g;
#pragma unroll
        for (int nf = 0; nf < 4; nf++) {
            int col = wn*32 + nf*8 + tg*2;
            *(u32*)(C + (size_t)row*D3 + col)     = pk(acc[mf][nf][0], acc[mf][nf][1]);
            *(u32*)(C + (size_t)(row+8)*D3 + col) = pk(acc[mf][nf][2], acc[mf][nf][3]);
        }
    }
}

// ===================== f32 -> bf16 conversion (vectorized) ==================
__global__ __launch_bounds__(256) void cvt_f2b(
        const float* __restrict__ in, bf16* __restrict__ out, int n4)
{
    int i = blockIdx.x * 256 + threadIdx.x;
    if (i < n4) {
        float4 v = ((const float4*)in)[i];
        ((uint2*)out)[i] = make_uint2(pk(v.x, v.y), pk(v.z, v.w));
    }
}

// ===================== softmax (short/medium): f32 scores -> bf16 probs =====
__global__ __launch_bounds__(256) void softmax_sm(
        const float* __restrict__ scores, bf16* __restrict__ probs, int band)
{
    __shared__ float srow[SS];
    __shared__ float redA[8];
    __shared__ float redB[8];
    const int rid = blockIdx.x;
    const int i = rid % SS;
    const float* row = scores + (size_t)rid * SS;
    u32* prow = (u32*)(probs + (size_t)rid * SS);
    const int jstart = max(0, i - band);
    const int g0 = max(0, jstart - 144) >> 2;
    const int t = threadIdx.x;
    float lmax = -1e30f;
    for (int g = g0 + t; g < SS/4; g += 256) {
        float4 v = ((const float4*)row)[g];
        int j = g*4;
        float v0 = (j+0 >= jstart) ? v.x : -1e30f;
        float v1 = (j+1 >= jstart) ? v.y : -1e30f;
        float v2 = (j+2 >= jstart) ? v.z : -1e30f;
        float v3 = (j+3 >= jstart) ? v.w : -1e30f;
        ((float4*)srow)[g] = make_float4(v0, v1, v2, v3);
        lmax = fmaxf(fmaxf(fmaxf(v0, v1), v2), fmaxf(v3, lmax));
    }
#pragma unroll
    for (int o = 16; o; o >>= 1) lmax = fmaxf(lmax, __shfl_xor_sync(0xffffffffu, lmax, o));
    if ((t & 31) == 0) redA[t >> 5] = lmax;
    __syncthreads();
    float m = redA[0];
#pragma unroll
    for (int ww = 1; ww < 8; ww++) m = fmaxf(m, redA[ww]);
    float lsum = 0.f;
    for (int g = g0 + t; g < SS/4; g += 256) {
        float4 v = ((const float4*)srow)[g];
        float e0 = (v.x > -1e29f) ? __expf(v.x - m) : 0.f;
        float e1 = (v.y > -1e29f) ? __expf(v.y - m) : 0.f;
        float e2 = (v.z > -1e29f) ? __expf(v.z - m) : 0.f;
        float e3 = (v.w > -1e29f) ? __expf(v.w - m) : 0.f;
        ((float4*)srow)[g] = make_float4(e0, e1, e2, e3);
        lsum += e0 + e1 + e2 + e3;
    }
#pragma unroll
    for (int o = 16; o; o >>= 1) lsum += __shfl_xor_sync(0xffffffffu, lsum, o);
    if ((t & 31) == 0) redB[t >> 5] = lsum;
    __syncthreads();
    float ssum = 0.f;
#pragma unroll
    for (int ww = 0; ww < 8; ww++) ssum += redB[ww];
    const float inv = 1.f / ssum;
    for (int g = g0 + t; g < SS/4; g += 256) {
        float4 v = ((const float4*)srow)[g];
        *(uint2*)(prow + g*2) = make_uint2(pk(v.x*inv, v.y*inv), pk(v.z*inv, v.w*inv));
    }
}

// ===================== softmax (long) + head mean fused =====================
__global__ __launch_bounds__(256) void softmax_long(
        const float* __restrict__ scores, bf16* __restrict__ probs,
        float* __restrict__ mean_out)
{
    __shared__ float srow[SS];
    __shared__ float smean[SS];
    __shared__ float redA[8];
    __shared__ float redB[8];
    const int b = blockIdx.x / SS, i = blockIdx.x % SS;
    const int t = threadIdx.x;
    for (int g = t; g < SS/4; g += 256)
        ((float4*)smean)[g] = make_float4(0.f, 0.f, 0.f, 0.f);
    __syncthreads();
    for (int h = 0; h < 16; h++) {
        const float* row = scores + ((size_t)(b*16 + h)*SS + i)*SS;
        u32* prow = (u32*)(probs + ((size_t)(b*16 + h)*SS + i)*SS);
        float lmax = -1e30f;
        for (int g = t; g < SS/4; g += 256) {
            float4 v = ((const float4*)row)[g];
            ((float4*)srow)[g] = v;
            lmax = fmaxf(fmaxf(fmaxf(v.x, v.y), v.z), fmaxf(v.w, lmax));
        }
#pragma unroll
        for (int o = 16; o; o >>= 1) lmax = fmaxf(lmax, __shfl_xor_sync(0xffffffffu, lmax, o));
        if ((t & 31) == 0) redA[t >> 5] = lmax;
        __syncthreads();
        float m = redA[0];
#pragma unroll
        for (int ww = 1; ww < 8; ww++) m = fmaxf(m, redA[ww]);
        float lsum = 0.f;
        for (int g = t; g < SS/4; g += 256) {
            float4 v = ((const float4*)srow)[g];
            float4 e = make_float4(__expf(v.x - m), __expf(v.y - m),
                                   __expf(v.z - m), __expf(v.w - m));
            ((float4*)srow)[g] = e;
            lsum += e.x + e.y + e.z + e.w;
        }
#pragma unroll
        for (int o = 16; o; o >>= 1) lsum += __shfl_xor_sync(0xffffffffu, lsum, o);
        if ((t & 31) == 0) redB[t >> 5] = lsum;
        __syncthreads();
        float ssum = 0.f;
#pragma unroll
        for (int ww = 0; ww < 8; ww++) ssum += redB[ww];
        const float inv = 1.f / ssum;
        for (int g = t; g < SS/4; g += 256) {
            float4 v = ((const float4*)srow)[g];
            float4 p = make_float4(v.x*inv, v.y*inv, v.z*inv, v.w*inv);
            float4 mm = ((float4*)smean)[g];
            ((float4*)smean)[g] = make_float4(mm.x+p.x, mm.y+p.y, mm.z+p.z, mm.w+p.w);
            *(uint2*)(prow + g*2) = make_uint2(pk(p.x, p.y), pk(p.z, p.w));
        }
        __syncthreads();
    }
    if (mean_out) {
        float* mrow = mean_out + (size_t)blockIdx.x * SS;
        for (int g = t; g < SS/4; g += 256) {
            float4 mm = ((float4*)smean)[g];
            ((float4*)mrow)[g] = make_float4(mm.x*(1.f/16.f), mm.y*(1.f/16.f),
                                             mm.z*(1.f/16.f), mm.w*(1.f/16.f));
        }
    }
}

// ===================== fused bias: b_comb + w_comb @ [bo_s;bo_m;bo_l] =======
__global__ void bias_comb(const float* __restrict__ w_comb,
                          const float* __restrict__ b_comb,
                          const float* __restrict__ bo_s,
                          const float* __restrict__ bo_m,
                          const float* __restrict__ bo_l,
                          float* __restrict__ bias_total) {
    const int p = blockIdx.x;
    __shared__ float red[256];
    float s = 0.f;
    for (int q = threadIdx.x; q < D3; q += 256) {
        float bo = (q < DD) ? bo_s[q] : (q < 2*DD) ? bo_m[q - DD] : bo_l[q - 2*DD];
        s += w_comb[(size_t)p*D3 + q] * bo;
    }
    red[threadIdx.x] = s; __syncthreads();
    for (int k = 128; k > 0; k >>= 1) {
        if (threadIdx.x < k) red[threadIdx.x] += red[threadIdx.x + k];
        __syncthreads();
    }
    if (threadIdx.x == 0) bias_total[p] = red[0] + b_comb[p];
}

// ===================== residual + layernorm (vectorized) ====================
__global__ __launch_bounds__(256) void ln_kernel(
        const float* __restrict__ y, const float* __restrict__ x,
        const float* __restrict__ gamma, const float* __restrict__ beta,
        float* __restrict__ out) {
    const int row = blockIdx.x;
    __shared__ float redA[8];
    __shared__ float redB[8];
    const int t = threadIdx.x;
    const float4* yr = (const float4*)(y + (size_t)row*DD);
    const float4* xr = (const float4*)(x + (size_t)row*DD);
    float4 yv = yr[t], xv = xr[t];
    float4 v = make_float4(yv.x+xv.x, yv.y+xv.y, yv.z+xv.z, yv.w+xv.w);
    float s  = v.x + v.y + v.z + v.w;
    float s2 = v.x*v.x + v.y*v.y + v.z*v.z + v.w*v.w;
#pragma unroll
    for (int o = 16; o; o >>= 1) {
        s  += __shfl_xor_sync(0xffffffffu, s,  o);
        s2 += __shfl_xor_sync(0xffffffffu, s2, o);
    }
    if ((t & 31) == 0) { redA[t >> 5] = s; redB[t >> 5] = s2; }
    __syncthreads();
    float ts = 0.f, ts2 = 0.f;
#pragma unroll
    for (int ww = 0; ww < 8; ww++) { ts += redA[ww]; ts2 += redB[ww]; }
    const float mu  = ts * (1.f/DD);
    const float var = ts2 * (1.f/DD) - mu*mu;
    const float rs  = rsqrtf(var + 1e-5f);
    const float4 g4 = ((const float4*)gamma)[t];
    const float4 b4 = ((const float4*)beta)[t];
    ((float4*)(out + (size_t)row*DD))[t] = make_float4(
        (v.x - mu)*rs*g4.x + b4.x, (v.y - mu)*rs*g4.y + b4.y,
        (v.z - mu)*rs*g4.z + b4.z, (v.w - mu)*rs*g4.w + b4.w);
}

// ===================== orchestration ========================================
extern "C" void kernel_launch(void* const* d_in, const int* in_sizes, int n_in,
                              void* d_out, int out_size) {
    const float* x      = (const float*)d_in[0];
    const float* w_in_s = (const float*)d_in[1];
    const float* b_in_s = (const float*)d_in[2];
    const float* wo_s   = (const float*)d_in[3];
    const float* bo_s   = (const float*)d_in[4];
    const float* w_in_m = (const float*)d_in[5];
    const float* b_in_m = (const float*)d_in[6];
    const float* wo_m   = (const float*)d_in[7];
    const float* bo_m   = (const float*)d_in[8];
    const float* w_in_l = (const float*)d_in[9];
    const float* b_in_l = (const float*)d_in[10];
    const float* wo_l   = (const float*)d_in[11];
    const float* bo_l   = (const float*)d_in[12];
    const float* w_comb = (const float*)d_in[13];
    const float* b_comb = (const float*)d_in[14];
    const float* gamma  = (const float*)d_in[15];
    const float* beta   = (const float*)d_in[16];
    float* out = (float*)d_out;

    bf16 *xb, *win_s, *win_m, *win_l, *qkv_s, *qkv_m, *qkv_l, *probs, *ctx, *Mall;
    float *scores, *biasT, *comb_out;
    cudaGetSymbolAddress((void**)&xb,       g_xb);
    cudaGetSymbolAddress((void**)&win_s,    g_win_s);
    cudaGetSymbolAddress((void**)&win_m,    g_win_m);
    cudaGetSymbolAddress((void**)&win_l,    g_win_l);
    cudaGetSymbolAddress((void**)&qkv_s,    g_qkv_s);
    cudaGetSymbolAddress((void**)&qkv_m,    g_qkv_m);
    cudaGetSymbolAddress((void**)&qkv_l,    g_qkv_l);
    cudaGetSymbolAddress((void**)&scores,   g_scores);
    cudaGetSymbolAddress((void**)&probs,    g_probs);
    cudaGetSymbolAddress((void**)&ctx,      g_ctx);
    cudaGetSymbolAddress((void**)&Mall,     g_Mall);
    cudaGetSymbolAddress((void**)&biasT,    g_bias);
    cudaGetSymbolAddress((void**)&comb_out, g_comb_out);

    // ---- bf16 conversions of x and w_in_* ----
    {
        int nx = (int)(BSD/4);
        cvt_f2b<<<(nx+255)/256, 256>>>(x, xb, nx);
        int nw = (int)((size_t)D3*DD/4);
        cvt_f2b<<<(nw+255)/256, 256>>>(w_in_s, win_s, nw);
        cvt_f2b<<<(nw+255)/256, 256>>>(w_in_m, win_m, nw);
        cvt_f2b<<<(nw+255)/256, 256>>>(w_in_l, win_l, nw);
    }

    // ---- fused weights: Mall_b = w_comb[:, bD:(b+1)D] @ wo_b (bf16 out) ----
    {
        dim3 g(DD/128, DD/128);
        k_nn_w<<<g, 256>>>(w_comb + 0*DD, D3, wo_s, DD, Mall + 0*DD, D3, DD);
        k_nn_w<<<g, 256>>>(w_comb + 1*DD, D3, wo_m, DD, Mall + 1*DD, D3, DD);
        k_nn_w<<<g, 256>>>(w_comb + 2*DD, D3, wo_l, DD, Mall + 2*DD, D3, DD);
        bias_comb<<<DD, 256>>>(w_comb, b_comb, bo_s, bo_m, bo_l, biasT);
    }

    // ---- QKV projections (bf16 in/out, cp.async pipeline) ----
    dim3 gqkv(D3/128, BS/128);
    k_proj<<<gqkv, 256>>>(xb, DD, win_s, DD, b_in_s, qkv_s, D3, DD);
    k_proj<<<gqkv, 256>>>(xb, DD, win_m, DD, b_in_m, qkv_m, D3, DD);
    k_proj<<<gqkv, 256>>>(xb, DD, win_l, DD, b_in_l, qkv_l, D3, DD);

    const float sc128 = 1.f / sqrtf(128.f);
    const float sc64  = 1.f / sqrtf(64.f);

    // ---- short branch: H=8, dk=128, band=10 ----
    {
        dim3 gqk(SS/128, SS/128, BB*8);
        k_qk<<<gqk, 256>>>(qkv_s, scores, 8, 128, 10, sc128);
        softmax_sm<<<BB*8*SS, 256>>>(scores, probs, 10);
        dim3 gpv(1, SS/128, BB*8);
        k_pv<<<gpv, 256>>>(probs, qkv_s, ctx, 8, 10, 0);
    }
    // ---- medium branch: H=8, dk=128, band=30 ----
    {
        dim3 gqk(SS/128, SS/128, BB*8);
        k_qk<<<gqk, 256>>>(qkv_m, scores, 8, 128, 30, sc128);
        softmax_sm<<<BB*8*SS, 256>>>(scores, probs, 30);
        dim3 gpv(1, SS/128, BB*8);
        k_pv<<<gpv, 256>>>(probs, qkv_m, ctx, 8, 30, DD);
    }
    // ---- long branch: H=16, dk=64, no band; fused softmax+mean ----
    {
        dim3 gqk(SS/128, SS/128, BB*16);
        k_qk<<<gqk, 256>>>(qkv_l, scores, 16, 64, -1, sc64);
        float* mean_out = ((size_t)out_size >= BSD + BSS) ? (out + BSD) : nullptr;
        softmax_long<<<BB*SS, 256>>>(scores, probs, mean_out);
        dim3 gpv(1, SS/128, BB*16);
        k_pv64<<<gpv, 256>>>(probs, qkv_l, ctx, 2*DD);
    }

    // ---- fused output: comb_out = ctx_all(bf16) @ Mall(bf16)^T + biasT ----
    dim3 gc(DD/128, BS/128);
    k_comb<<<gc, 256>>>(ctx, D3, Mall, D3, biasT, comb_out, DD, D3);

    // ---- residual + LN ----
    ln_kernel<<<BS, 256>>>(comb_out, x, gamma, beta, out);
}

// round 10
// speedup vs baseline: 6.2937x; 1.2526x over previous
#include <cuda_runtime.h>
#include <cuda_bf16.h>
#include <math.h>

// Problem constants
#define BB 2
#define SS 2048
#define DD 1024
#define D3 (3*DD)
#define BS (BB*SS)             // 4096
#define BSD ((size_t)BS*DD)    // 4,194,304
#define BSS ((size_t)BB*SS*SS) // 8,388,608

typedef unsigned u32;
typedef __nv_bfloat16 bf16;

// ----------------- scratch buffers (static device globals; no allocs) ------
__device__ bf16   g_xb   [(size_t)BS*DD];         // x in bf16
__device__ bf16   g_win_s[(size_t)D3*DD];         // w_in_* in bf16
__device__ bf16   g_win_m[(size_t)D3*DD];
__device__ bf16   g_win_l[(size_t)D3*DD];
__device__ bf16   g_qkv_s[(size_t)BS*D3];
__device__ bf16   g_qkv_m[(size_t)BS*D3];
__device__ bf16   g_qkv_l[(size_t)BS*D3];
__device__ bf16   g_ctx[(size_t)BS*D3];           // concatenated ctx (s|m|l)
__device__ bf16   g_Mall[(size_t)DD*D3];          // fused wo∘w_comb weights
__device__ float  g_bias[DD];
__device__ float  g_comb_out[(size_t)BS*DD];
__device__ float2 g_ml[(size_t)BB*16*SS];         // long branch (m, 1/l) per row

// ===================== helpers ==============================================
__device__ __forceinline__ u32 pk(float lo, float hi) {
    __nv_bfloat162 h = __floats2bfloat162_rn(lo, hi);
    return *reinterpret_cast<u32*>(&h);
}
__device__ __forceinline__ void mma16(float c[4], const u32 a[4], const u32 b[2]) {
    asm volatile(
        "mma.sync.aligned.m16n8k16.row.col.f32.bf16.bf16.f32 "
        "{%0,%1,%2,%3}, {%4,%5,%6,%7}, {%8,%9}, {%0,%1,%2,%3};"
        : "+f"(c[0]), "+f"(c[1]), "+f"(c[2]), "+f"(c[3])
        : "r"(a[0]), "r"(a[1]), "r"(a[2]), "r"(a[3]), "r"(b[0]), "r"(b[1]));
}
__device__ __forceinline__ u32 smem_addr(const void* p) {
    return (u32)__cvta_generic_to_shared(p);
}
__device__ __forceinline__ void cpa16(u32 dst, const void* src) {
    asm volatile("cp.async.ca.shared.global [%0], [%1], 16;" :: "r"(dst), "l"(src));
}

// ---- fragment compute for k_nn_w (As [row][kpair], Bs [kpair][n]) ----------
__device__ __forceinline__ void comp128(
        const u32 (*As)[12], const u32 (*Bs)[136],
        int wm, int wn, int g, int tg, float (&acc)[4][4][4]) {
    u32 a[4][4], b[4][2];
#pragma unroll
    for (int mf = 0; mf < 4; mf++) {
        int m = wm*64 + mf*16 + g;
        a[mf][0] = As[m    ][tg];     a[mf][1] = As[m + 8][tg];
        a[mf][2] = As[m    ][tg + 4]; a[mf][3] = As[m + 8][tg + 4];
    }
#pragma unroll
    for (int nf = 0; nf < 4; nf++) {
        int n = wn*32 + nf*8 + g;
        b[nf][0] = Bs[tg][n]; b[nf][1] = Bs[tg + 4][n];
    }
#pragma unroll
    for (int mf = 0; mf < 4; mf++)
#pragma unroll
        for (int nf = 0; nf < 4; nf++)
            mma16(acc[mf][nf], a[mf], b[nf]);
}

// ---- fragment compute, NT pipeline layout: BOTH As and Bs [row][kpair] -----
__device__ __forceinline__ void comp128b(
        const u32 (*As)[12], const u32 (*Bs)[12],
        int wm, int wn, int g, int tg, float (&acc)[4][4][4]) {
    u32 a[4][4], b[4][2];
#pragma unroll
    for (int mf = 0; mf < 4; mf++) {
        int m = wm*64 + mf*16 + g;
        a[mf][0] = As[m    ][tg];     a[mf][1] = As[m + 8][tg];
        a[mf][2] = As[m    ][tg + 4]; a[mf][3] = As[m + 8][tg + 4];
    }
#pragma unroll
    for (int nf = 0; nf < 4; nf++) {
        int n = wn*32 + nf*8 + g;
        b[nf][0] = Bs[n][tg]; b[nf][1] = Bs[n][tg + 4];
    }
#pragma unroll
    for (int mf = 0; mf < 4; mf++)
#pragma unroll
        for (int nf = 0; nf < 4; nf++)
            mma16(acc[mf][nf], a[mf], b[nf]);
}

// ===================== NT core: 3-stage cp.async pipeline ===================
#define NT_CORE(A_, lda_, B_, ldb_, K_, acc_)                                   \
    __shared__ u32 As[3][128][12];                                              \
    __shared__ u32 Bs[3][128][12];                                              \
    const int tid = threadIdx.x, lane = tid & 31, w = tid >> 5;                 \
    const int wm = w & 1, wn = w >> 1, g = lane >> 2, tg = lane & 3;            \
    {                                                                           \
        const int r = tid >> 1, hf = tid & 1;                                   \
        const bf16* pA = (A_) + (size_t)r*(lda_) + hf*8;                        \
        const bf16* pB = (B_) + (size_t)r*(ldb_) + hf*8;                        \
        const u32 dA = smem_addr(&As[0][r][hf*4]);                              \
        const u32 dB = smem_addr(&Bs[0][r][hf*4]);                              \
        const int nIter = (K_) >> 4;                                            \
        cpa16(dA, pA);            cpa16(dB, pB);                                \
        asm volatile("cp.async.commit_group;");                                 \
        cpa16(dA + 6144, pA + 16); cpa16(dB + 6144, pB + 16);                   \
        asm volatile("cp.async.commit_group;");                                 \
        int s = 0;                                                              \
        for (int it = 0; it < nIter; ++it) {                                    \
            asm volatile("cp.async.wait_group 1;");                             \
            __syncthreads();                                                    \
            if (it + 2 < nIter) {                                               \
                int sp = s + 2; if (sp >= 3) sp -= 3;                           \
                cpa16(dA + sp*6144, pA + (size_t)(it+2)*16);                    \
                cpa16(dB + sp*6144, pB + (size_t)(it+2)*16);                    \
            }                                                                   \
            asm volatile("cp.async.commit_group;");                             \
            comp128b(As[s], Bs[s], wm, wn, g, tg, acc_);                        \
            s = (s == 2) ? 0 : s + 1;                                           \
        }                                                                       \
    }

// ===================== k_proj: C(bf16) = A(bf16) @ W(bf16)^T + bias =========
__global__ __launch_bounds__(256) void k_proj(
        const bf16* __restrict__ A, int lda,
        const bf16* __restrict__ W, int ldb,
        const float* __restrict__ bias,
        bf16* __restrict__ C, int ldc, int K)
{
    const int m0 = blockIdx.y * 128, n0 = blockIdx.x * 128;
    float acc[4][4][4] = {};
    NT_CORE(A + (size_t)m0*lda, lda, W + (size_t)n0*ldb, ldb, K, acc)
#pragma unroll
    for (int mf = 0; mf < 4; mf++) {
        int row = m0 + wm*64 + mf*16 + g;
#pragma unroll
        for (int nf = 0; nf < 4; nf++) {
            int col = n0 + wn*32 + nf*8 + tg*2;
            float2 bv = *(const float2*)(bias + col);
            *(u32*)(C + (size_t)row*ldc + col) =
                pk(acc[mf][nf][0] + bv.x, acc[mf][nf][1] + bv.y);
            *(u32*)(C + (size_t)(row+8)*ldc + col) =
                pk(acc[mf][nf][2] + bv.x, acc[mf][nf][3] + bv.y);
        }
    }
}

// ===================== k_comb: C(f32) = ctx(bf16) @ Mall(bf16)^T + bias =====
__global__ __launch_bounds__(256) void k_comb(
        const bf16* __restrict__ A, int lda,
        const bf16* __restrict__ W, int ldb,
        const float* __restrict__ bias,
        float* __restrict__ C, int ldc, int K)
{
    const int m0 = blockIdx.y * 128, n0 = blockIdx.x * 128;
    float acc[4][4][4] = {};
    NT_CORE(A + (size_t)m0*lda, lda, W + (size_t)n0*ldb, ldb, K, acc)
#pragma unroll
    for (int mf = 0; mf < 4; mf++) {
        int row = m0 + wm*64 + mf*16 + g;
#pragma unroll
        for (int nf = 0; nf < 4; nf++) {
            int col = n0 + wn*32 + nf*8 + tg*2;
            float2 bv = *(const float2*)(bias + col);
            *(float2*)(C + (size_t)row*ldc + col) =
                make_float2(acc[mf][nf][0] + bv.x, acc[mf][nf][1] + bv.y);
            *(float2*)(C + (size_t)(row+8)*ldc + col) =
                make_float2(acc[mf][nf][2] + bv.x, acc[mf][nf][3] + bv.y);
        }
    }
}

// ===================== k_nn_w: Mall(bf16) = A(f32)[M,K] @ B(f32)[K,N] =======
__global__ __launch_bounds__(256) void k_nn_w(
        const float* __restrict__ A, int lda,
        const float* __restrict__ B, int ldb,
        bf16* __restrict__ C, int ldc, int K)
{
    __shared__ u32 As[2][128][12];
    __shared__ u32 Bs[2][8][136];
    const int tid = threadIdx.x, lane = tid & 31, w = tid >> 5;
    const int wm = w & 1, wn = w >> 1, g = lane >> 2, tg = lane & 3;
    const int m0 = blockIdx.y * 128, n0 = blockIdx.x * 128;
    const int r  = tid >> 2, kq = (tid & 3) * 4, kp0 = (tid & 3) * 2;
    const int kb = tid >> 5, nq = (tid & 31) * 4;
    const float* A0 = A + (size_t)(m0 + r     )*lda + kq;
    const float* A1 = A + (size_t)(m0 + r + 64)*lda + kq;
    const float* Bp = B + n0 + nq;
    float acc[4][4][4] = {};
    float4 pa0, pa1, pb0, pb1;
    pa0 = *(const float4*)A0; pa1 = *(const float4*)A1;
    pb0 = *(const float4*)(Bp + (size_t)(2*kb    )*ldb);
    pb1 = *(const float4*)(Bp + (size_t)(2*kb + 1)*ldb);
    int s = 0;
    {
        *(uint2*)&As[0][r     ][kp0] = make_uint2(pk(pa0.x,pa0.y), pk(pa0.z,pa0.w));
        *(uint2*)&As[0][r + 64][kp0] = make_uint2(pk(pa1.x,pa1.y), pk(pa1.z,pa1.w));
        *(uint4*)&Bs[0][kb][nq] = make_uint4(pk(pb0.x,pb1.x), pk(pb0.y,pb1.y),
                                             pk(pb0.z,pb1.z), pk(pb0.w,pb1.w));
    }
    __syncthreads();
    for (int k0 = 0;;) {
        const int kn = k0 + 16;
        const bool more = kn < K;
        if (more) {
            pa0 = *(const float4*)(A0 + kn); pa1 = *(const float4*)(A1 + kn);
            pb0 = *(const float4*)(Bp + (size_t)(kn + 2*kb    )*ldb);
            pb1 = *(const float4*)(Bp + (size_t)(kn + 2*kb + 1)*ldb);
        }
        comp128(As[s], Bs[s], wm, wn, g, tg, acc);
        if (!more) break;
        const int t = s ^ 1;
        *(uint2*)&As[t][r     ][kp0] = make_uint2(pk(pa0.x,pa0.y), pk(pa0.z,pa0.w));
        *(uint2*)&As[t][r + 64][kp0] = make_uint2(pk(pa1.x,pa1.y), pk(pa1.z,pa1.w));
        *(uint4*)&Bs[t][kb][nq] = make_uint4(pk(pb0.x,pb1.x), pk(pb0.y,pb1.y),
                                             pk(pb0.z,pb1.z), pk(pb0.w,pb1.w));
        __syncthreads();
        s = t; k0 = kn;
    }
#pragma unroll
    for (int mf = 0; mf < 4; mf++) {
        int row = m0 + wm*64 + mf*16 + g;
#pragma unroll
        for (int nf = 0; nf < 4; nf++) {
            int col = n0 + wn*32 + nf*8 + tg*2;
            *(u32*)(C + (size_t)row*ldc + col)     = pk(acc[mf][nf][0], acc[mf][nf][1]);
            *(u32*)(C + (size_t)(row+8)*ldc + col) = pk(acc[mf][nf][2], acc[mf][nf][3]);
        }
    }
}

// ===================== k_flash: fused QK + online softmax + PV ==============
// One CTA = 128 Q rows of one (b,h). 8 warps x 16 rows. K/V tiles of 128.
// P stays in registers (S-accumulator == next A-fragment layout).
// ml_out != nullptr (long branch): store per-row (m, 1/l) for the mean kernel.
template<int DK>
__global__ __launch_bounds__(256) void k_flash(
        const bf16* __restrict__ qkv, bf16* __restrict__ ctx_all,
        int H, int band, int colbase, float scale,
        float2* __restrict__ ml_out)
{
    constexpr int KSTR = DK/2 + 4;     // Ks stride (u32 kpairs + pad)
    constexpr int VSTR = DK + 8;       // Vs stride
    extern __shared__ u32 dsm[];
    u32 (*Ks)[KSTR] = (u32(*)[KSTR])dsm;
    u32 (*Vs)[VSTR] = (u32(*)[VSTR])(dsm + 128*KSTR);

    const int z = blockIdx.z;
    const int b = z / H, h = z % H;
    const int m0 = blockIdx.y * 128;
    const bf16* Qb = qkv + (size_t)b*SS*D3 + h*DK;
    const bf16* Kb = qkv + (size_t)b*SS*D3 + DD + h*DK;
    const bf16* Vb = qkv + (size_t)b*SS*D3 + 2*DD + h*DK;
    bf16* C = ctx_all + (size_t)b*SS*D3 + colbase + h*DK;

    const int tid = threadIdx.x, lane = tid & 31, w = tid >> 5;
    const int g = lane >> 2, tg = lane & 3;
    const int i1 = m0 + w*16 + g, i2 = i1 + 8;

    // Q fragments for this warp's 16 rows (read once, L2-resident)
    u32 aq[DK/16][4];
#pragma unroll
    for (int kf = 0; kf < DK/16; kf++) {
        aq[kf][0] = *(const u32*)(Qb + (size_t)i1*D3 + kf*16 + tg*2);
        aq[kf][1] = *(const u32*)(Qb + (size_t)i2*D3 + kf*16 + tg*2);
        aq[kf][2] = *(const u32*)(Qb + (size_t)i1*D3 + kf*16 + 8 + tg*2);
        aq[kf][3] = *(const u32*)(Qb + (size_t)i2*D3 + kf*16 + 8 + tg*2);
    }

    float oacc[DK/8][4];
#pragma unroll
    for (int nv = 0; nv < DK/8; nv++) {
        oacc[nv][0] = 0.f; oacc[nv][1] = 0.f; oacc[nv][2] = 0.f; oacc[nv][3] = 0.f;
    }
    float m1 = -1e30f, m2 = -1e30f, l1 = 0.f, l2 = 0.f;

    int t0 = 0;
    if (band >= 0) { int lo = m0 - band - 127; if (lo > 0) t0 = (lo + 127) >> 7; }

    for (int t = t0; t < SS/128; t++) {
        const int n0 = t * 128;
        __syncthreads();
        // stage K tile [128 rows][DK] as [row][kpair]
#pragma unroll
        for (int it = 0; it < DK/16; it++) {
            int idx = tid + it*256;
            int r = idx / (DK/8), c = idx % (DK/8);
            *(uint4*)&Ks[r][c*4] = *(const uint4*)(Kb + (size_t)(n0 + r)*D3 + c*8);
        }
        // stage V tile [128 seq][DK] as interleaved [kpair][n]
#pragma unroll
        for (int it = 0; it < DK/16; it++) {
            int idx = tid + it*256;
            int kb = idx / (DK/4), nq = (idx % (DK/4))*4;
            uint2 ra = *(const uint2*)(Vb + (size_t)(n0 + 2*kb    )*D3 + nq);
            uint2 rb = *(const uint2*)(Vb + (size_t)(n0 + 2*kb + 1)*D3 + nq);
            Vs[kb][nq+0] = __byte_perm(ra.x, rb.x, 0x5410);
            Vs[kb][nq+1] = __byte_perm(ra.x, rb.x, 0x7632);
            Vs[kb][nq+2] = __byte_perm(ra.y, rb.y, 0x5410);
            Vs[kb][nq+3] = __byte_perm(ra.y, rb.y, 0x7632);
        }
        __syncthreads();

        // S = scale * Q @ K^T  (warp: 16 rows x 128 cols)
        float s[16][4];
#pragma unroll
        for (int nf = 0; nf < 16; nf++) {
            s[nf][0] = 0.f; s[nf][1] = 0.f; s[nf][2] = 0.f; s[nf][3] = 0.f;
        }
#pragma unroll
        for (int kf = 0; kf < DK/16; kf++) {
#pragma unroll
            for (int nf = 0; nf < 16; nf++) {
                u32 b2[2] = { Ks[nf*8+g][kf*8+tg], Ks[nf*8+g][kf*8+tg+4] };
                mma16(s[nf], aq[kf], b2);
            }
        }
        const bool needMask = (band >= 0) && (n0 < m0 + 127 - band);
#pragma unroll
        for (int nf = 0; nf < 16; nf++) {
            s[nf][0] *= scale; s[nf][1] *= scale;
            s[nf][2] *= scale; s[nf][3] *= scale;
        }
        if (needMask) {
#pragma unroll
            for (int nf = 0; nf < 16; nf++) {
                int j = n0 + nf*8 + tg*2;
                if (j     < i1 - band) s[nf][0] = -1e30f;
                if (j + 1 < i1 - band) s[nf][1] = -1e30f;
                if (j     < i2 - band) s[nf][2] = -1e30f;
                if (j + 1 < i2 - band) s[nf][3] = -1e30f;
            }
        }
        // online softmax (rows i1, i2; row spread over the tg-quad)
        float mx1 = -1e30f, mx2 = -1e30f;
#pragma unroll
        for (int nf = 0; nf < 16; nf++) {
            mx1 = fmaxf(mx1, fmaxf(s[nf][0], s[nf][1]));
            mx2 = fmaxf(mx2, fmaxf(s[nf][2], s[nf][3]));
        }
        mx1 = fmaxf(mx1, __shfl_xor_sync(0xffffffffu, mx1, 1));
        mx1 = fmaxf(mx1, __shfl_xor_sync(0xffffffffu, mx1, 2));
        mx2 = fmaxf(mx2, __shfl_xor_sync(0xffffffffu, mx2, 1));
        mx2 = fmaxf(mx2, __shfl_xor_sync(0xffffffffu, mx2, 2));
        const float mn1 = fmaxf(m1, mx1), mn2 = fmaxf(m2, mx2);
        const float c1 = __expf(m1 - mn1), c2 = __expf(m2 - mn2);
        float ls1 = 0.f, ls2 = 0.f;
#pragma unroll
        for (int nf = 0; nf < 16; nf++) {
            float p0 = __expf(s[nf][0] - mn1);
            float p1 = __expf(s[nf][1] - mn1);
            float p2 = __expf(s[nf][2] - mn2);
            float p3 = __expf(s[nf][3] - mn2);
            if (needMask) {   // exp(-1e30 - (-1e30)) == 1 trap: zero explicitly
                int j = n0 + nf*8 + tg*2;
                if (j     < i1 - band) p0 = 0.f;
                if (j + 1 < i1 - band) p1 = 0.f;
                if (j     < i2 - band) p2 = 0.f;
                if (j + 1 < i2 - band) p3 = 0.f;
            }
            ls1 += p0 + p1; ls2 += p2 + p3;
            s[nf][0] = p0; s[nf][1] = p1; s[nf][2] = p2; s[nf][3] = p3;
        }
        ls1 += __shfl_xor_sync(0xffffffffu, ls1, 1);
        ls1 += __shfl_xor_sync(0xffffffffu, ls1, 2);
        ls2 += __shfl_xor_sync(0xffffffffu, ls2, 1);
        ls2 += __shfl_xor_sync(0xffffffffu, ls2, 2);
        l1 = l1*c1 + ls1; l2 = l2*c2 + ls2;
        m1 = mn1; m2 = mn2;
#pragma unroll
        for (int nv = 0; nv < DK/8; nv++) {
            oacc[nv][0] *= c1; oacc[nv][1] *= c1;
            oacc[nv][2] *= c2; oacc[nv][3] *= c2;
        }
        // O += P @ V  (P accumulator tiles re-pack directly into A fragments)
#pragma unroll
        for (int kp2 = 0; kp2 < 8; kp2++) {
            u32 ap[4] = { pk(s[2*kp2  ][0], s[2*kp2  ][1]),
                          pk(s[2*kp2  ][2], s[2*kp2  ][3]),
                          pk(s[2*kp2+1][0], s[2*kp2+1][1]),
                          pk(s[2*kp2+1][2], s[2*kp2+1][3]) };
#pragma unroll
            for (int nv = 0; nv < DK/8; nv++) {
                u32 b2[2] = { Vs[kp2*8+tg][nv*8+g], Vs[kp2*8+tg+4][nv*8+g] };
                mma16(oacc[nv], ap, b2);
            }
        }
    }
    const float inv1 = 1.f / l1, inv2 = 1.f / l2;
#pragma unroll
    for (int nv = 0; nv < DK/8; nv++) {
        *(u32*)(C + (size_t)i1*D3 + nv*8 + tg*2) = pk(oacc[nv][0]*inv1, oacc[nv][1]*inv1);
        *(u32*)(C + (size_t)i2*D3 + nv*8 + tg*2) = pk(oacc[nv][2]*inv2, oacc[nv][3]*inv2);
    }
    if (ml_out != nullptr && tg == 0) {
        ml_out[(size_t)z*SS + i1] = make_float2(m1, inv1);
        ml_out[(size_t)z*SS + i2] = make_float2(m2, inv2);
    }
}

// ===================== k_mean: recompute head-mean of long-branch probs =====
// CTA = 128x128 tile of out[b]; loops 16 heads: S = QK^T, p = exp(s-m)/l, sum.
__global__ __launch_bounds__(256) void k_mean(
        const bf16* __restrict__ qkv_l, const float2* __restrict__ ml,
        float* __restrict__ outm)
{
    __shared__ u32 Ks[128][36];
    const int b  = blockIdx.z;
    const int i0 = blockIdx.y * 128, j0 = blockIdx.x * 128;
    const int tid = threadIdx.x, lane = tid & 31, w = tid >> 5;
    const int g = lane >> 2, tg = lane & 3;
    const int i1 = i0 + w*16 + g, i2 = i1 + 8;
    const float sc = 0.125f;  // 1/sqrt(64)
    float macc[16][4];
#pragma unroll
    for (int nf = 0; nf < 16; nf++) {
        macc[nf][0] = 0.f; macc[nf][1] = 0.f; macc[nf][2] = 0.f; macc[nf][3] = 0.f;
    }
    for (int h = 0; h < 16; h++) {
        const bf16* Qb = qkv_l + (size_t)b*SS*D3 + h*64;
        const bf16* Kb = qkv_l + (size_t)b*SS*D3 + DD + h*64;
        __syncthreads();
#pragma unroll
        for (int it = 0; it < 4; it++) {
            int idx = tid + it*256;
            int r = idx >> 3, c = idx & 7;
            *(uint4*)&Ks[r][c*4] = *(const uint4*)(Kb + (size_t)(j0 + r)*D3 + c*8);
        }
        __syncthreads();
        u32 aq[4][4];
#pragma unroll
        for (int kf = 0; kf < 4; kf++) {
            aq[kf][0] = *(const u32*)(Qb + (size_t)i1*D3 + kf*16 + tg*2);
            aq[kf][1] = *(const u32*)(Qb + (size_t)i2*D3 + kf*16 + tg*2);
            aq[kf][2] = *(const u32*)(Qb + (size_t)i1*D3 + kf*16 + 8 + tg*2);
            aq[kf][3] = *(const u32*)(Qb + (size_t)i2*D3 + kf*16 + 8 + tg*2);
        }
        float s[16][4];
#pragma unroll
        for (int nf = 0; nf < 16; nf++) {
            s[nf][0] = 0.f; s[nf][1] = 0.f; s[nf][2] = 0.f; s[nf][3] = 0.f;
        }
#pragma unroll
        for (int kf = 0; kf < 4; kf++) {
#pragma unroll
            for (int nf = 0; nf < 16; nf++) {
                u32 b2[2] = { Ks[nf*8+g][kf*8+tg], Ks[nf*8+g][kf*8+tg+4] };
                mma16(s[nf], aq[kf], b2);
            }
        }
        const float2 a1 = ml[(size_t)(b*16 + h)*SS + i1];
        const float2 a2 = ml[(size_t)(b*16 + h)*SS + i2];
#pragma unroll
        for (int nf = 0; nf < 16; nf++) {
            macc[nf][0] += __expf(s[nf][0]*sc - a1.x) * a1.y;
            macc[nf][1] += __expf(s[nf][1]*sc - a1.x) * a1.y;
            macc[nf][2] += __expf(s[nf][2]*sc - a2.x) * a2.y;
            macc[nf][3] += __expf(s[nf][3]*sc - a2.x) * a2.y;
        }
    }
    const float q = 1.f / 16.f;
#pragma unroll
    for (int nf = 0; nf < 16; nf++) {
        int j = j0 + nf*8 + tg*2;
        *(float2*)(outm + (size_t)(b*SS + i1)*SS + j) =
            make_float2(macc[nf][0]*q, macc[nf][1]*q);
        *(float2*)(outm + (size_t)(b*SS + i2)*SS + j) =
            make_float2(macc[nf][2]*q, macc[nf][3]*q);
    }
}

// ===================== f32 -> bf16 conversion (vectorized) ==================
__global__ __launch_bounds__(256) void cvt_f2b(
        const float* __restrict__ in, bf16* __restrict__ out, int n4)
{
    int i = blockIdx.x * 256 + threadIdx.x;
    if (i < n4) {
        float4 v = ((const float4*)in)[i];
        ((uint2*)out)[i] = make_uint2(pk(v.x, v.y), pk(v.z, v.w));
    }
}

// ===================== fused bias: b_comb + w_comb @ [bo_s;bo_m;bo_l] =======
__global__ void bias_comb(const float* __restrict__ w_comb,
                          const float* __restrict__ b_comb,
                          const float* __restrict__ bo_s,
                          const float* __restrict__ bo_m,
                          const float* __restrict__ bo_l,
                          float* __restrict__ bias_total) {
    const int p = blockIdx.x;
    __shared__ float red[256];
    float s = 0.f;
    for (int q = threadIdx.x; q < D3; q += 256) {
        float bo = (q < DD) ? bo_s[q] : (q < 2*DD) ? bo_m[q - DD] : bo_l[q - 2*DD];
        s += w_comb[(size_t)p*D3 + q] * bo;
    }
    red[threadIdx.x] = s; __syncthreads();
    for (int k = 128; k > 0; k >>= 1) {
        if (threadIdx.x < k) red[threadIdx.x] += red[threadIdx.x + k];
        __syncthreads();
    }
    if (threadIdx.x == 0) bias_total[p] = red[0] + b_comb[p];
}

// ===================== residual + layernorm (vectorized) ====================
__global__ __launch_bounds__(256) void ln_kernel(
        const float* __restrict__ y, const float* __restrict__ x,
        const float* __restrict__ gamma, const float* __restrict__ beta,
        float* __restrict__ out) {
    const int row = blockIdx.x;
    __shared__ float redA[8];
    __shared__ float redB[8];
    const int t = threadIdx.x;
    const float4* yr = (const float4*)(y + (size_t)row*DD);
    const float4* xr = (const float4*)(x + (size_t)row*DD);
    float4 yv = yr[t], xv = xr[t];
    float4 v = make_float4(yv.x+xv.x, yv.y+xv.y, yv.z+xv.z, yv.w+xv.w);
    float s  = v.x + v.y + v.z + v.w;
    float s2 = v.x*v.x + v.y*v.y + v.z*v.z + v.w*v.w;
#pragma unroll
    for (int o = 16; o; o >>= 1) {
        s  += __shfl_xor_sync(0xffffffffu, s,  o);
        s2 += __shfl_xor_sync(0xffffffffu, s2, o);
    }
    if ((t & 31) == 0) { redA[t >> 5] = s; redB[t >> 5] = s2; }
    __syncthreads();
    float ts = 0.f, ts2 = 0.f;
#pragma unroll
    for (int ww = 0; ww < 8; ww++) { ts += redA[ww]; ts2 += redB[ww]; }
    const float mu  = ts * (1.f/DD);
    const float var = ts2 * (1.f/DD) - mu*mu;
    const float rs  = rsqrtf(var + 1e-5f);
    const float4 g4 = ((const float4*)gamma)[t];
    const float4 b4 = ((const float4*)beta)[t];
    ((float4*)(out + (size_t)row*DD))[t] = make_float4(
        (v.x - mu)*rs*g4.x + b4.x, (v.y - mu)*rs*g4.y + b4.y,
        (v.z - mu)*rs*g4.z + b4.z, (v.w - mu)*rs*g4.w + b4.w);
}

// ===================== orchestration ========================================
extern "C" void kernel_launch(void* const* d_in, const int* in_sizes, int n_in,
                              void* d_out, int out_size) {
    const float* x      = (const float*)d_in[0];
    const float* w_in_s = (const float*)d_in[1];
    const float* b_in_s = (const float*)d_in[2];
    const float* wo_s   = (const float*)d_in[3];
    const float* bo_s   = (const float*)d_in[4];
    const float* w_in_m = (const float*)d_in[5];
    const float* b_in_m = (const float*)d_in[6];
    const float* wo_m   = (const float*)d_in[7];
    const float* bo_m   = (const float*)d_in[8];
    const float* w_in_l = (const float*)d_in[9];
    const float* b_in_l = (const float*)d_in[10];
    const float* wo_l   = (const float*)d_in[11];
    const float* bo_l   = (const float*)d_in[12];
    const float* w_comb = (const float*)d_in[13];
    const float* b_comb = (const float*)d_in[14];
    const float* gamma  = (const float*)d_in[15];
    const float* beta   = (const float*)d_in[16];
    float* out = (float*)d_out;

    bf16 *xb, *win_s, *win_m, *win_l, *qkv_s, *qkv_m, *qkv_l, *ctx, *Mall;
    float *biasT, *comb_out;
    float2 *ml;
    cudaGetSymbolAddress((void**)&xb,       g_xb);
    cudaGetSymbolAddress((void**)&win_s,    g_win_s);
    cudaGetSymbolAddress((void**)&win_m,    g_win_m);
    cudaGetSymbolAddress((void**)&win_l,    g_win_l);
    cudaGetSymbolAddress((void**)&qkv_s,    g_qkv_s);
    cudaGetSymbolAddress((void**)&qkv_m,    g_qkv_m);
    cudaGetSymbolAddress((void**)&qkv_l,    g_qkv_l);
    cudaGetSymbolAddress((void**)&ctx,      g_ctx);
    cudaGetSymbolAddress((void**)&Mall,     g_Mall);
    cudaGetSymbolAddress((void**)&biasT,    g_bias);
    cudaGetSymbolAddress((void**)&comb_out, g_comb_out);
    cudaGetSymbolAddress((void**)&ml,       g_ml);

    // opt-in dynamic smem for the flash kernels (k_flash<128> needs 68 KB)
    cudaFuncSetAttribute(k_flash<128>, cudaFuncAttributeMaxDynamicSharedMemorySize, 69632);
    cudaFuncSetAttribute(k_flash<64>,  cudaFuncAttributeMaxDynamicSharedMemorySize, 36864);

    // ---- bf16 conversions of x and w_in_* ----
    {
        int nx = (int)(BSD/4);
        cvt_f2b<<<(nx+255)/256, 256>>>(x, xb, nx);
        int nw = (int)((size_t)D3*DD/4);
        cvt_f2b<<<(nw+255)/256, 256>>>(w_in_s, win_s, nw);
        cvt_f2b<<<(nw+255)/256, 256>>>(w_in_m, win_m, nw);
        cvt_f2b<<<(nw+255)/256, 256>>>(w_in_l, win_l, nw);
    }

    // ---- fused weights: Mall_b = w_comb[:, bD:(b+1)D] @ wo_b (bf16 out) ----
    {
        dim3 g(DD/128, DD/128);
        k_nn_w<<<g, 256>>>(w_comb + 0*DD, D3, wo_s, DD, Mall + 0*DD, D3, DD);
        k_nn_w<<<g, 256>>>(w_comb + 1*DD, D3, wo_m, DD, Mall + 1*DD, D3, DD);
        k_nn_w<<<g, 256>>>(w_comb + 2*DD, D3, wo_l, DD, Mall + 2*DD, D3, DD);
        bias_comb<<<DD, 256>>>(w_comb, b_comb, bo_s, bo_m, bo_l, biasT);
    }

    // ---- QKV projections (bf16 in/out, cp.async pipeline) ----
    dim3 gqkv(D3/128, BS/128);
    k_proj<<<gqkv, 256>>>(xb, DD, win_s, DD, b_in_s, qkv_s, D3, DD);
    k_proj<<<gqkv, 256>>>(xb, DD, win_m, DD, b_in_m, qkv_m, D3, DD);
    k_proj<<<gqkv, 256>>>(xb, DD, win_l, DD, b_in_l, qkv_l, D3, DD);

    const float sc128 = 1.f / sqrtf(128.f);
    const float sc64  = 0.125f;

    // ---- fused flash attention per branch ----
    k_flash<128><<<dim3(1, SS/128, BB*8),  256, 69632>>>(qkv_s, ctx,  8, 10, 0,    sc128, nullptr);
    k_flash<128><<<dim3(1, SS/128, BB*8),  256, 69632>>>(qkv_m, ctx,  8, 30, DD,   sc128, nullptr);
    k_flash<64> <<<dim3(1, SS/128, BB*16), 256, 36864>>>(qkv_l, ctx, 16, -1, 2*DD, sc64,  ml);

    // ---- attn_weights: head-mean recompute from (m, 1/l) ----
    if ((size_t)out_size >= BSD + BSS)
        k_mean<<<dim3(SS/128, SS/128, BB), 256>>>(qkv_l, ml, out + BSD);

    // ---- fused output: comb_out = ctx_all(bf16) @ Mall(bf16)^T + biasT ----
    dim3 gc(DD/128, BS/128);
    k_comb<<<gc, 256>>>(ctx, D3, Mall, D3, biasT, comb_out, DD, D3);

    // ---- residual + LN ----
    ln_kernel<<<BS, 256>>>(comb_out, x, gamma, beta, out);
}

// round 17
// speedup vs baseline: 7.2599x; 1.1535x over previous
#include <cuda_runtime.h>
#include <cuda_bf16.h>
#include <math.h>

// Problem constants
#define BB 2
#define SS 2048
#define DD 1024
#define D3 (3*DD)
#define BS (BB*SS)             // 4096
#define BSD ((size_t)BS*DD)    // 4,194,304
#define BSS ((size_t)BB*SS*SS) // 8,388,608

typedef unsigned u32;
typedef __nv_bfloat16 bf16;

// ----------------- scratch buffers (static device globals; no allocs) ------
__device__ bf16   g_xb   [(size_t)BS*DD];         // x in bf16
__device__ bf16   g_win_s[(size_t)D3*DD];         // w_in_* in bf16
__device__ bf16   g_win_m[(size_t)D3*DD];
__device__ bf16   g_win_l[(size_t)D3*DD];
__device__ bf16   g_qkv_s[(size_t)BS*D3];
__device__ bf16   g_qkv_m[(size_t)BS*D3];
__device__ bf16   g_qkv_l[(size_t)BS*D3];
__device__ bf16   g_ctx[(size_t)BS*D3];           // concatenated ctx (s|m|l)
__device__ bf16   g_Mall[(size_t)DD*D3];          // fused wo∘w_comb weights
__device__ float  g_bias[DD];
__device__ float  g_comb_out[(size_t)BS*DD];
__device__ float2 g_ml[(size_t)BB*16*SS];         // long branch (m, 1/l) per row

// ===================== helpers ==============================================
__device__ __forceinline__ u32 pk(float lo, float hi) {
    __nv_bfloat162 h = __floats2bfloat162_rn(lo, hi);
    return *reinterpret_cast<u32*>(&h);
}
__device__ __forceinline__ void mma16(float c[4], const u32 a[4], const u32 b[2]) {
    asm volatile(
        "mma.sync.aligned.m16n8k16.row.col.f32.bf16.bf16.f32 "
        "{%0,%1,%2,%3}, {%4,%5,%6,%7}, {%8,%9}, {%0,%1,%2,%3};"
        : "+f"(c[0]), "+f"(c[1]), "+f"(c[2]), "+f"(c[3])
        : "r"(a[0]), "r"(a[1]), "r"(a[2]), "r"(a[3]), "r"(b[0]), "r"(b[1]));
}
__device__ __forceinline__ u32 smem_addr(const void* p) {
    return (u32)__cvta_generic_to_shared(p);
}
__device__ __forceinline__ void cpa16(u32 dst, const void* src) {
    asm volatile("cp.async.ca.shared.global [%0], [%1], 16;" :: "r"(dst), "l"(src));
}
// ldmatrix x4: lanes 0-7 address matrix0 rows, 8-15 m1, 16-23 m2, 24-31 m3.
// result per matrix: lane l -> (row l/4, kpair l%4)
__device__ __forceinline__ void ldsm4(u32* d, u32 addr) {
    asm volatile("ldmatrix.sync.aligned.m8n8.x4.shared.b16 {%0,%1,%2,%3}, [%4];"
        : "=r"(d[0]), "=r"(d[1]), "=r"(d[2]), "=r"(d[3]) : "r"(addr));
}

// ---- fragment compute for k_nn_w (As [row][kpair], Bs [kpair][n]) ----------
__device__ __forceinline__ void comp128(
        const u32 (*As)[12], const u32 (*Bs)[136],
        int wm, int wn, int g, int tg, float (&acc)[4][4][4]) {
    u32 a[4][4], b[4][2];
#pragma unroll
    for (int mf = 0; mf < 4; mf++) {
        int m = wm*64 + mf*16 + g;
        a[mf][0] = As[m    ][tg];     a[mf][1] = As[m + 8][tg];
        a[mf][2] = As[m    ][tg + 4]; a[mf][3] = As[m + 8][tg + 4];
    }
#pragma unroll
    for (int nf = 0; nf < 4; nf++) {
        int n = wn*32 + nf*8 + g;
        b[nf][0] = Bs[tg][n]; b[nf][1] = Bs[tg + 4][n];
    }
#pragma unroll
    for (int mf = 0; mf < 4; mf++)
#pragma unroll
        for (int nf = 0; nf < 4; nf++)
            mma16(acc[mf][nf], a[mf], b[nf]);
}

// ---- fragment compute, NT pipeline layout: BOTH As and Bs [row][kpair] -----
// ldmatrix version: A 4x ldsm4, B 2x ldsm4 (was 24 scalar LDS.32).
// Row stride 48B = 12 banks mod 32 -> conflict-free 8-row phases.
__device__ __forceinline__ void comp128b(
        const u32 (*As)[12], const u32 (*Bs)[12],
        int wm, int wn, int g, int tg, float (&acc)[4][4][4]) {
    const int lane = (g << 2) | tg;
    const int q = lane >> 3, r = lane & 7;
    u32 a[4][4], b[4][2];
    const u32 abase = smem_addr(As)
        + (u32)((wm*64 + (q & 1)*8 + r) * 48 + (q >> 1)*16);
#pragma unroll
    for (int mf = 0; mf < 4; mf++)
        ldsm4(a[mf], abase + (u32)(mf*16*48));
    const u32 bbase = smem_addr(Bs)
        + (u32)((wn*32 + (q >> 1)*8 + r) * 48 + (q & 1)*16);
    {
        u32 t[4];
        ldsm4(t, bbase);                      // nf 0,1
        b[0][0]=t[0]; b[0][1]=t[1]; b[1][0]=t[2]; b[1][1]=t[3];
        ldsm4(t, bbase + 16*48);              // nf 2,3
        b[2][0]=t[0]; b[2][1]=t[1]; b[3][0]=t[2]; b[3][1]=t[3];
    }
#pragma unroll
    for (int mf = 0; mf < 4; mf++)
#pragma unroll
        for (int nf = 0; nf < 4; nf++)
            mma16(acc[mf][nf], a[mf], b[nf]);
}

// ===================== NT core: 3-stage cp.async pipeline ===================
#define NT_CORE(A_, lda_, B_, ldb_, K_, acc_)                                   \
    __shared__ u32 As[3][128][12];                                              \
    __shared__ u32 Bs[3][128][12];                                              \
    const int tid = threadIdx.x, lane = tid & 31, w = tid >> 5;                 \
    const int wm = w & 1, wn = w >> 1, g = lane >> 2, tg = lane & 3;            \
    {                                                                           \
        const int r = tid >> 1, hf = tid & 1;                                   \
        const bf16* pA = (A_) + (size_t)r*(lda_) + hf*8;                        \
        const bf16* pB = (B_) + (size_t)r*(ldb_) + hf*8;                        \
        const u32 dA = smem_addr(&As[0][r][hf*4]);                              \
        const u32 dB = smem_addr(&Bs[0][r][hf*4]);                              \
        const int nIter = (K_) >> 4;                                            \
        cpa16(dA, pA);            cpa16(dB, pB);                                \
        asm volatile("cp.async.commit_group;");                                 \
        cpa16(dA + 6144, pA + 16); cpa16(dB + 6144, pB + 16);                   \
        asm volatile("cp.async.commit_group;");                                 \
        int s = 0;                                                              \
        for (int it = 0; it < nIter; ++it) {                                    \
            asm volatile("cp.async.wait_group 1;");                             \
            __syncthreads();                                                    \
            if (it + 2 < nIter) {                                               \
                int sp = s + 2; if (sp >= 3) sp -= 3;                           \
                cpa16(dA + sp*6144, pA + (size_t)(it+2)*16);                    \
                cpa16(dB + sp*6144, pB + (size_t)(it+2)*16);                    \
            }                                                                   \
            asm volatile("cp.async.commit_group;");                             \
            comp128b(As[s], Bs[s], wm, wn, g, tg, acc_);                        \
            s = (s == 2) ? 0 : s + 1;                                           \
        }                                                                       \
    }

// ===================== k_proj: C(bf16) = A(bf16) @ W(bf16)^T + bias =========
__global__ __launch_bounds__(256) void k_proj(
        const bf16* __restrict__ A, int lda,
        const bf16* __restrict__ W, int ldb,
        const float* __restrict__ bias,
        bf16* __restrict__ C, int ldc, int K)
{
    const int m0 = blockIdx.y * 128, n0 = blockIdx.x * 128;
    float acc[4][4][4] = {};
    NT_CORE(A + (size_t)m0*lda, lda, W + (size_t)n0*ldb, ldb, K, acc)
#pragma unroll
    for (int mf = 0; mf < 4; mf++) {
        int row = m0 + wm*64 + mf*16 + g;
#pragma unroll
        for (int nf = 0; nf < 4; nf++) {
            int col = n0 + wn*32 + nf*8 + tg*2;
            float2 bv = *(const float2*)(bias + col);
            *(u32*)(C + (size_t)row*ldc + col) =
                pk(acc[mf][nf][0] + bv.x, acc[mf][nf][1] + bv.y);
            *(u32*)(C + (size_t)(row+8)*ldc + col) =
                pk(acc[mf][nf][2] + bv.x, acc[mf][nf][3] + bv.y);
        }
    }
}

// ===================== k_comb: C(f32) = ctx(bf16) @ Mall(bf16)^T + bias =====
__global__ __launch_bounds__(256) void k_comb(
        const bf16* __restrict__ A, int lda,
        const bf16* __restrict__ W, int ldb,
        const float* __restrict__ bias,
        float* __restrict__ C, int ldc, int K)
{
    const int m0 = blockIdx.y * 128, n0 = blockIdx.x * 128;
    float acc[4][4][4] = {};
    NT_CORE(A + (size_t)m0*lda, lda, W + (size_t)n0*ldb, ldb, K, acc)
#pragma unroll
    for (int mf = 0; mf < 4; mf++) {
        int row = m0 + wm*64 + mf*16 + g;
#pragma unroll
        for (int nf = 0; nf < 4; nf++) {
            int col = n0 + wn*32 + nf*8 + tg*2;
            float2 bv = *(const float2*)(bias + col);
            *(float2*)(C + (size_t)row*ldc + col) =
                make_float2(acc[mf][nf][0] + bv.x, acc[mf][nf][1] + bv.y);
            *(float2*)(C + (size_t)(row+8)*ldc + col) =
                make_float2(acc[mf][nf][2] + bv.x, acc[mf][nf][3] + bv.y);
        }
    }
}

// ===================== k_nn_w: Mall(bf16) = A(f32)[M,K] @ B(f32)[K,N] =======
__global__ __launch_bounds__(256) void k_nn_w(
        const float* __restrict__ A, int lda,
        const float* __restrict__ B, int ldb,
        bf16* __restrict__ C, int ldc, int K)
{
    __shared__ u32 As[2][128][12];
    __shared__ u32 Bs[2][8][136];
    const int tid = threadIdx.x, lane = tid & 31, w = tid >> 5;
    const int wm = w & 1, wn = w >> 1, g = lane >> 2, tg = lane & 3;
    const int m0 = blockIdx.y * 128, n0 = blockIdx.x * 128;
    const int r  = tid >> 2, kq = (tid & 3) * 4, kp0 = (tid & 3) * 2;
    const int kb = tid >> 5, nq = (tid & 31) * 4;
    const float* A0 = A + (size_t)(m0 + r     )*lda + kq;
    const float* A1 = A + (size_t)(m0 + r + 64)*lda + kq;
    const float* Bp = B + n0 + nq;
    float acc[4][4][4] = {};
    float4 pa0, pa1, pb0, pb1;
    pa0 = *(const float4*)A0; pa1 = *(const float4*)A1;
    pb0 = *(const float4*)(Bp + (size_t)(2*kb    )*ldb);
    pb1 = *(const float4*)(Bp + (size_t)(2*kb + 1)*ldb);
    int s = 0;
    {
        *(uint2*)&As[0][r     ][kp0] = make_uint2(pk(pa0.x,pa0.y), pk(pa0.z,pa0.w));
        *(uint2*)&As[0][r + 64][kp0] = make_uint2(pk(pa1.x,pa1.y), pk(pa1.z,pa1.w));
        *(uint4*)&Bs[0][kb][nq] = make_uint4(pk(pb0.x,pb1.x), pk(pb0.y,pb1.y),
                                             pk(pb0.z,pb1.z), pk(pb0.w,pb1.w));
    }
    __syncthreads();
    for (int k0 = 0;;) {
        const int kn = k0 + 16;
        const bool more = kn < K;
        if (more) {
            pa0 = *(const float4*)(A0 + kn); pa1 = *(const float4*)(A1 + kn);
            pb0 = *(const float4*)(Bp + (size_t)(kn + 2*kb    )*ldb);
            pb1 = *(const float4*)(Bp + (size_t)(kn + 2*kb + 1)*ldb);
        }
        comp128(As[s], Bs[s], wm, wn, g, tg, acc);
        if (!more) break;
        const int t = s ^ 1;
        *(uint2*)&As[t][r     ][kp0] = make_uint2(pk(pa0.x,pa0.y), pk(pa0.z,pa0.w));
        *(uint2*)&As[t][r + 64][kp0] = make_uint2(pk(pa1.x,pa1.y), pk(pa1.z,pa1.w));
        *(uint4*)&Bs[t][kb][nq] = make_uint4(pk(pb0.x,pb1.x), pk(pb0.y,pb1.y),
                                             pk(pb0.z,pb1.z), pk(pb0.w,pb1.w));
        __syncthreads();
        s = t; k0 = kn;
    }
#pragma unroll
    for (int mf = 0; mf < 4; mf++) {
        int row = m0 + wm*64 + mf*16 + g;
#pragma unroll
        for (int nf = 0; nf < 4; nf++) {
            int col = n0 + wn*32 + nf*8 + tg*2;
            *(u32*)(C + (size_t)row*ldc + col)     = pk(acc[mf][nf][0], acc[mf][nf][1]);
            *(u32*)(C + (size_t)(row+8)*ldc + col) = pk(acc[mf][nf][2], acc[mf][nf][3]);
        }
    }
}

// ===================== k_flash: fused QK + online softmax + PV ==============
template<int DK>
__global__ __launch_bounds__(256) void k_flash(
        const bf16* __restrict__ qkv, bf16* __restrict__ ctx_all,
        int H, int band, int colbase, float scale,
        float2* __restrict__ ml_out)
{
    constexpr int KSTR = DK/2 + 4;     // u32 stride; *4 bytes = 4 banks mod 32
    constexpr int VSTR = DK + 8;
    extern __shared__ u32 dsm[];
    u32 (*Ks)[KSTR] = (u32(*)[KSTR])dsm;
    u32 (*Vs)[VSTR] = (u32(*)[VSTR])(dsm + 128*KSTR);

    const int z = blockIdx.z;
    const int b = z / H, h = z % H;
    const int m0 = blockIdx.y * 128;
    const bf16* Qb = qkv + (size_t)b*SS*D3 + h*DK;
    const bf16* Kb = qkv + (size_t)b*SS*D3 + DD + h*DK;
    const bf16* Vb = qkv + (size_t)b*SS*D3 + 2*DD + h*DK;
    bf16* C = ctx_all + (size_t)b*SS*D3 + colbase + h*DK;

    const int tid = threadIdx.x, lane = tid & 31, w = tid >> 5;
    const int g = lane >> 2, tg = lane & 3;
    const int q2 = lane >> 3, r8 = lane & 7;
    const int i1 = m0 + w*16 + g, i2 = i1 + 8;

    u32 aq[DK/16][4];
#pragma unroll
    for (int kf = 0; kf < DK/16; kf++) {
        aq[kf][0] = *(const u32*)(Qb + (size_t)i1*D3 + kf*16 + tg*2);
        aq[kf][1] = *(const u32*)(Qb + (size_t)i2*D3 + kf*16 + tg*2);
        aq[kf][2] = *(const u32*)(Qb + (size_t)i1*D3 + kf*16 + 8 + tg*2);
        aq[kf][3] = *(const u32*)(Qb + (size_t)i2*D3 + kf*16 + 8 + tg*2);
    }

    float oacc[DK/8][4];
#pragma unroll
    for (int nv = 0; nv < DK/8; nv++) {
        oacc[nv][0] = 0.f; oacc[nv][1] = 0.f; oacc[nv][2] = 0.f; oacc[nv][3] = 0.f;
    }
    float m1 = -1e30f, m2 = -1e30f, l1 = 0.f, l2 = 0.f;

    int t0 = 0;
    if (band >= 0) { int lo = m0 - band - 127; if (lo > 0) t0 = (lo + 127) >> 7; }

    // per-lane base for Ks ldmatrix: covers nf-pair matrices
    const u32 ksbase = smem_addr(Ks) + (u32)(((q2 >> 1)*8 + r8) * (KSTR*4));

    for (int t = t0; t < SS/128; t++) {
        const int n0 = t * 128;
        __syncthreads();
#pragma unroll
        for (int it = 0; it < DK/16; it++) {
            int idx = tid + it*256;
            int r = idx / (DK/8), c = idx % (DK/8);
            *(uint4*)&Ks[r][c*4] = *(const uint4*)(Kb + (size_t)(n0 + r)*D3 + c*8);
        }
#pragma unroll
        for (int it = 0; it < DK/16; it++) {
            int idx = tid + it*256;
            int kb = idx / (DK/4), nq = (idx % (DK/4))*4;
            uint2 ra = *(const uint2*)(Vb + (size_t)(n0 + 2*kb    )*D3 + nq);
            uint2 rb = *(const uint2*)(Vb + (size_t)(n0 + 2*kb + 1)*D3 + nq);
            Vs[kb][nq+0] = __byte_perm(ra.x, rb.x, 0x5410);
            Vs[kb][nq+1] = __byte_perm(ra.x, rb.x, 0x7632);
            Vs[kb][nq+2] = __byte_perm(ra.y, rb.y, 0x5410);
            Vs[kb][nq+3] = __byte_perm(ra.y, rb.y, 0x7632);
        }
        __syncthreads();

        // S = scale * Q @ K^T — Ks fragments via ldmatrix (8 ldsm4 per kf)
        float s[16][4];
#pragma unroll
        for (int nf = 0; nf < 16; nf++) {
            s[nf][0] = 0.f; s[nf][1] = 0.f; s[nf][2] = 0.f; s[nf][3] = 0.f;
        }
#pragma unroll
        for (int kf = 0; kf < DK/16; kf++) {
            const u32 kaddr = ksbase + (u32)(kf*32 + (q2 & 1)*16);
#pragma unroll
            for (int p = 0; p < 8; p++) {
                u32 bt[4];
                ldsm4(bt, kaddr + (u32)(p*16*(KSTR*4)));
                mma16(s[2*p],     aq[kf], bt);
                mma16(s[2*p + 1], aq[kf], bt + 2);
            }
        }
        const bool needMask = (band >= 0) && (n0 < m0 + 127 - band);
#pragma unroll
        for (int nf = 0; nf < 16; nf++) {
            s[nf][0] *= scale; s[nf][1] *= scale;
            s[nf][2] *= scale; s[nf][3] *= scale;
        }
        if (needMask) {
#pragma unroll
            for (int nf = 0; nf < 16; nf++) {
                int j = n0 + nf*8 + tg*2;
                if (j     < i1 - band) s[nf][0] = -1e30f;
                if (j + 1 < i1 - band) s[nf][1] = -1e30f;
                if (j     < i2 - band) s[nf][2] = -1e30f;
                if (j + 1 < i2 - band) s[nf][3] = -1e30f;
            }
        }
        float mx1 = -1e30f, mx2 = -1e30f;
#pragma unroll
        for (int nf = 0; nf < 16; nf++) {
            mx1 = fmaxf(mx1, fmaxf(s[nf][0], s[nf][1]));
            mx2 = fmaxf(mx2, fmaxf(s[nf][2], s[nf][3]));
        }
        mx1 = fmaxf(mx1, __shfl_xor_sync(0xffffffffu, mx1, 1));
        mx1 = fmaxf(mx1, __shfl_xor_sync(0xffffffffu, mx1, 2));
        mx2 = fmaxf(mx2, __shfl_xor_sync(0xffffffffu, mx2, 1));
        mx2 = fmaxf(mx2, __shfl_xor_sync(0xffffffffu, mx2, 2));
        const float mn1 = fmaxf(m1, mx1), mn2 = fmaxf(m2, mx2);
        const float c1 = __expf(m1 - mn1), c2 = __expf(m2 - mn2);
        float ls1 = 0.f, ls2 = 0.f;
#pragma unroll
        for (int nf = 0; nf < 16; nf++) {
            float p0 = __expf(s[nf][0] - mn1);
            float p1 = __expf(s[nf][1] - mn1);
            float p2 = __expf(s[nf][2] - mn2);
            float p3 = __expf(s[nf][3] - mn2);
            if (needMask) {   // exp(-1e30 - (-1e30)) == 1 trap: zero explicitly
                int j = n0 + nf*8 + tg*2;
                if (j     < i1 - band) p0 = 0.f;
                if (j + 1 < i1 - band) p1 = 0.f;
                if (j     < i2 - band) p2 = 0.f;
                if (j + 1 < i2 - band) p3 = 0.f;
            }
            ls1 += p0 + p1; ls2 += p2 + p3;
            s[nf][0] = p0; s[nf][1] = p1; s[nf][2] = p2; s[nf][3] = p3;
        }
        ls1 += __shfl_xor_sync(0xffffffffu, ls1, 1);
        ls1 += __shfl_xor_sync(0xffffffffu, ls1, 2);
        ls2 += __shfl_xor_sync(0xffffffffu, ls2, 1);
        ls2 += __shfl_xor_sync(0xffffffffu, ls2, 2);
        l1 = l1*c1 + ls1; l2 = l2*c2 + ls2;
        m1 = mn1; m2 = mn2;
#pragma unroll
        for (int nv = 0; nv < DK/8; nv++) {
            oacc[nv][0] *= c1; oacc[nv][1] *= c1;
            oacc[nv][2] *= c2; oacc[nv][3] *= c2;
        }
        // O += P @ V  (P accumulator tiles re-pack directly into A fragments)
#pragma unroll
        for (int kp2 = 0; kp2 < 8; kp2++) {
            u32 ap[4] = { pk(s[2*kp2  ][0], s[2*kp2  ][1]),
                          pk(s[2*kp2  ][2], s[2*kp2  ][3]),
                          pk(s[2*kp2+1][0], s[2*kp2+1][1]),
                          pk(s[2*kp2+1][2], s[2*kp2+1][3]) };
#pragma unroll
            for (int nv = 0; nv < DK/8; nv++) {
                u32 b2[2] = { Vs[kp2*8+tg][nv*8+g], Vs[kp2*8+tg+4][nv*8+g] };
                mma16(oacc[nv], ap, b2);
            }
        }
    }
    const float inv1 = 1.f / l1, inv2 = 1.f / l2;
#pragma unroll
    for (int nv = 0; nv < DK/8; nv++) {
        *(u32*)(C + (size_t)i1*D3 + nv*8 + tg*2) = pk(oacc[nv][0]*inv1, oacc[nv][1]*inv1);
        *(u32*)(C + (size_t)i2*D3 + nv*8 + tg*2) = pk(oacc[nv][2]*inv2, oacc[nv][3]*inv2);
    }
    if (ml_out != nullptr && tg == 0) {
        ml_out[(size_t)z*SS + i1] = make_float2(m1, inv1);
        ml_out[(size_t)z*SS + i2] = make_float2(m2, inv2);
    }
}

// ===================== k_mean: recompute head-mean of long-branch probs =====
__global__ __launch_bounds__(256) void k_mean(
        const bf16* __restrict__ qkv_l, const float2* __restrict__ ml,
        float* __restrict__ outm)
{
    __shared__ u32 Ks[128][36];
    const int b  = blockIdx.z;
    const int i0 = blockIdx.y * 128, j0 = blockIdx.x * 128;
    const int tid = threadIdx.x, lane = tid & 31, w = tid >> 5;
    const int g = lane >> 2, tg = lane & 3;
    const int q2 = lane >> 3, r8 = lane & 7;
    const int i1 = i0 + w*16 + g, i2 = i1 + 8;
    const float sc = 0.125f;  // 1/sqrt(64)
    const u32 ksbase = smem_addr(Ks) + (u32)(((q2 >> 1)*8 + r8) * 144);
    float macc[16][4];
#pragma unroll
    for (int nf = 0; nf < 16; nf++) {
        macc[nf][0] = 0.f; macc[nf][1] = 0.f; macc[nf][2] = 0.f; macc[nf][3] = 0.f;
    }
    for (int h = 0; h < 16; h++) {
        const bf16* Qb = qkv_l + (size_t)b*SS*D3 + h*64;
        const bf16* Kb = qkv_l + (size_t)b*SS*D3 + DD + h*64;
        __syncthreads();
#pragma unroll
        for (int it = 0; it < 4; it++) {
            int idx = tid + it*256;
            int r = idx >> 3, c = idx & 7;
            *(uint4*)&Ks[r][c*4] = *(const uint4*)(Kb + (size_t)(j0 + r)*D3 + c*8);
        }
        __syncthreads();
        u32 aq[4][4];
#pragma unroll
        for (int kf = 0; kf < 4; kf++) {
            aq[kf][0] = *(const u32*)(Qb + (size_t)i1*D3 + kf*16 + tg*2);
            aq[kf][1] = *(const u32*)(Qb + (size_t)i2*D3 + kf*16 + tg*2);
            aq[kf][2] = *(const u32*)(Qb + (size_t)i1*D3 + kf*16 + 8 + tg*2);
            aq[kf][3] = *(const u32*)(Qb + (size_t)i2*D3 + kf*16 + 8 + tg*2);
        }
        float s[16][4];
#pragma unroll
        for (int nf = 0; nf < 16; nf++) {
            s[nf][0] = 0.f; s[nf][1] = 0.f; s[nf][2] = 0.f; s[nf][3] = 0.f;
        }
#pragma unroll
        for (int kf = 0; kf < 4; kf++) {
            const u32 kaddr = ksbase + (u32)(kf*32 + (q2 & 1)*16);
#pragma unroll
            for (int p = 0; p < 8; p++) {
                u32 bt[4];
                ldsm4(bt, kaddr + (u32)(p*16*144));
                mma16(s[2*p],     aq[kf], bt);
                mma16(s[2*p + 1], aq[kf], bt + 2);
            }
        }
        const float2 a1 = ml[(size_t)(b*16 + h)*SS + i1];
        const float2 a2 = ml[(size_t)(b*16 + h)*SS + i2];
#pragma unroll
        for (int nf = 0; nf < 16; nf++) {
            macc[nf][0] += __expf(s[nf][0]*sc - a1.x) * a1.y;
            macc[nf][1] += __expf(s[nf][1]*sc - a1.x) * a1.y;
            macc[nf][2] += __expf(s[nf][2]*sc - a2.x) * a2.y;
            macc[nf][3] += __expf(s[nf][3]*sc - a2.x) * a2.y;
        }
    }
    const float q = 1.f / 16.f;
#pragma unroll
    for (int nf = 0; nf < 16; nf++) {
        int j = j0 + nf*8 + tg*2;
        *(float2*)(outm + (size_t)(b*SS + i1)*SS + j) =
            make_float2(macc[nf][0]*q, macc[nf][1]*q);
        *(float2*)(outm + (size_t)(b*SS + i2)*SS + j) =
            make_float2(macc[nf][2]*q, macc[nf][3]*q);
    }
}

// ===================== f32 -> bf16 conversion (vectorized) ==================
__global__ __launch_bounds__(256) void cvt_f2b(
        const float* __restrict__ in, bf16* __restrict__ out, int n4)
{
    int i = blockIdx.x * 256 + threadIdx.x;
    if (i < n4) {
        float4 v = ((const float4*)in)[i];
        ((uint2*)out)[i] = make_uint2(pk(v.x, v.y), pk(v.z, v.w));
    }
}

// ===================== fused bias: b_comb + w_comb @ [bo_s;bo_m;bo_l] =======
__global__ void bias_comb(const float* __restrict__ w_comb,
                          const float* __restrict__ b_comb,
                          const float* __restrict__ bo_s,
                          const float* __restrict__ bo_m,
                          const float* __restrict__ bo_l,
                          float* __restrict__ bias_total) {
    const int p = blockIdx.x;
    __shared__ float red[256];
    float s = 0.f;
    for (int q = threadIdx.x; q < D3; q += 256) {
        float bo = (q < DD) ? bo_s[q] : (q < 2*DD) ? bo_m[q - DD] : bo_l[q - 2*DD];
        s += w_comb[(size_t)p*D3 + q] * bo;
    }
    red[threadIdx.x] = s; __syncthreads();
    for (int k = 128; k > 0; k >>= 1) {
        if (threadIdx.x < k) red[threadIdx.x] += red[threadIdx.x + k];
        __syncthreads();
    }
    if (threadIdx.x == 0) bias_total[p] = red[0] + b_comb[p];
}

// ===================== residual + layernorm (vectorized) ====================
__global__ __launch_bounds__(256) void ln_kernel(
        const float* __restrict__ y, const float* __restrict__ x,
        const float* __restrict__ gamma, const float* __restrict__ beta,
        float* __restrict__ out) {
    const int row = blockIdx.x;
    __shared__ float redA[8];
    __shared__ float redB[8];
    const int t = threadIdx.x;
    const float4* yr = (const float4*)(y + (size_t)row*DD);
    const float4* xr = (const float4*)(x + (size_t)row*DD);
    float4 yv = yr[t], xv = xr[t];
    float4 v = make_float4(yv.x+xv.x, yv.y+xv.y, yv.z+xv.z, yv.w+xv.w);
    float s  = v.x + v.y + v.z + v.w;
    float s2 = v.x*v.x + v.y*v.y + v.z*v.z + v.w*v.w;
#pragma unroll
    for (int o = 16; o; o >>= 1) {
        s  += __shfl_xor_sync(0xffffffffu, s,  o);
        s2 += __shfl_xor_sync(0xffffffffu, s2, o);
    }
    if ((t & 31) == 0) { redA[t >> 5] = s; redB[t >> 5] = s2; }
    __syncthreads();
    float ts = 0.f, ts2 = 0.f;
#pragma unroll
    for (int ww = 0; ww < 8; ww++) { ts += redA[ww]; ts2 += redB[ww]; }
    const float mu  = ts * (1.f/DD);
    const float var = ts2 * (1.f/DD) - mu*mu;
    const float rs  = rsqrtf(var + 1e-5f);
    const float4 g4 = ((const float4*)gamma)[t];
    const float4 b4 = ((const float4*)beta)[t];
    ((float4*)(out + (size_t)row*DD))[t] = make_float4(
        (v.x - mu)*rs*g4.x + b4.x, (v.y - mu)*rs*g4.y + b4.y,
        (v.z - mu)*rs*g4.z + b4.z, (v.w - mu)*rs*g4.w + b4.w);
}

// ===================== orchestration ========================================
extern "C" void kernel_launch(void* const* d_in, const int* in_sizes, int n_in,
                              void* d_out, int out_size) {
    const float* x      = (const float*)d_in[0];
    const float* w_in_s = (const float*)d_in[1];
    const float* b_in_s = (const float*)d_in[2];
    const float* wo_s   = (const float*)d_in[3];
    const float* bo_s   = (const float*)d_in[4];
    const float* w_in_m = (const float*)d_in[5];
    const float* b_in_m = (const float*)d_in[6];
    const float* wo_m   = (const float*)d_in[7];
    const float* bo_m   = (const float*)d_in[8];
    const float* w_in_l = (const float*)d_in[9];
    const float* b_in_l = (const float*)d_in[10];
    const float* wo_l   = (const float*)d_in[11];
    const float* bo_l   = (const float*)d_in[12];
    const float* w_comb = (const float*)d_in[13];
    const float* b_comb = (const float*)d_in[14];
    const float* gamma  = (const float*)d_in[15];
    const float* beta   = (const float*)d_in[16];
    float* out = (float*)d_out;

    bf16 *xb, *win_s, *win_m, *win_l, *qkv_s, *qkv_m, *qkv_l, *ctx, *Mall;
    float *biasT, *comb_out;
    float2 *ml;
    cudaGetSymbolAddress((void**)&xb,       g_xb);
    cudaGetSymbolAddress((void**)&win_s,    g_win_s);
    cudaGetSymbolAddress((void**)&win_m,    g_win_m);
    cudaGetSymbolAddress((void**)&win_l,    g_win_l);
    cudaGetSymbolAddress((void**)&qkv_s,    g_qkv_s);
    cudaGetSymbolAddress((void**)&qkv_m,    g_qkv_m);
    cudaGetSymbolAddress((void**)&qkv_l,    g_qkv_l);
    cudaGetSymbolAddress((void**)&ctx,      g_ctx);
    cudaGetSymbolAddress((void**)&Mall,     g_Mall);
    cudaGetSymbolAddress((void**)&biasT,    g_bias);
    cudaGetSymbolAddress((void**)&comb_out, g_comb_out);
    cudaGetSymbolAddress((void**)&ml,       g_ml);

    // opt-in dynamic smem for the flash kernels (k_flash<128> needs 68 KB)
    cudaFuncSetAttribute(k_flash<128>, cudaFuncAttributeMaxDynamicSharedMemorySize, 69632);
    cudaFuncSetAttribute(k_flash<64>,  cudaFuncAttributeMaxDynamicSharedMemorySize, 36864);

    // ---- bf16 conversions of x and w_in_* ----
    {
        int nx = (int)(BSD/4);
        cvt_f2b<<<(nx+255)/256, 256>>>(x, xb, nx);
        int nw = (int)((size_t)D3*DD/4);
        cvt_f2b<<<(nw+255)/256, 256>>>(w_in_s, win_s, nw);
        cvt_f2b<<<(nw+255)/256, 256>>>(w_in_m, win_m, nw);
        cvt_f2b<<<(nw+255)/256, 256>>>(w_in_l, win_l, nw);
    }

    // ---- fused weights: Mall_b = w_comb[:, bD:(b+1)D] @ wo_b (bf16 out) ----
    {
        dim3 g(DD/128, DD/128);
        k_nn_w<<<g, 256>>>(w_comb + 0*DD, D3, wo_s, DD, Mall + 0*DD, D3, DD);
        k_nn_w<<<g, 256>>>(w_comb + 1*DD, D3, wo_m, DD, Mall + 1*DD, D3, DD);
        k_nn_w<<<g, 256>>>(w_comb + 2*DD, D3, wo_l, DD, Mall + 2*DD, D3, DD);
        bias_comb<<<DD, 256>>>(w_comb, b_comb, bo_s, bo_m, bo_l, biasT);
    }

    // ---- QKV projections (bf16 in/out, cp.async pipeline + ldmatrix) ----
    dim3 gqkv(D3/128, BS/128);
    k_proj<<<gqkv, 256>>>(xb, DD, win_s, DD, b_in_s, qkv_s, D3, DD);
    k_proj<<<gqkv, 256>>>(xb, DD, win_m, DD, b_in_m, qkv_m, D3, DD);
    k_proj<<<gqkv, 256>>>(xb, DD, win_l, DD, b_in_l, qkv_l, D3, DD);

    const float sc128 = 1.f / sqrtf(128.f);
    const float sc64  = 0.125f;

    // ---- fused flash attention per branch ----
    k_flash<128><<<dim3(1, SS/128, BB*8),  256, 69632>>>(qkv_s, ctx,  8, 10, 0,    sc128, nullptr);
    k_flash<128><<<dim3(1, SS/128, BB*8),  256, 69632>>>(qkv_m, ctx,  8, 30, DD,   sc128, nullptr);
    k_flash<64> <<<dim3(1, SS/128, BB*16), 256, 36864>>>(qkv_l, ctx, 16, -1, 2*DD, sc64,  ml);

    // ---- attn_weights: head-mean recompute from (m, 1/l) ----
    if ((size_t)out_size >= BSD + BSS)
        k_mean<<<dim3(SS/128, SS/128, BB), 256>>>(qkv_l, ml, out + BSD);

    // ---- fused output: comb_out = ctx_all(bf16) @ Mall(bf16)^T + biasT ----
    dim3 gc(DD/128, BS/128);
    k_comb<<<gc, 256>>>(ctx, D3, Mall, D3, biasT, comb_out, DD, D3);

    // ---- residual + LN ----
    ln_kernel<<<BS, 256>>>(comb_out, x, gamma, beta, out);
}